// round 8
// baseline (speedup 1.0000x reference)
#include <cuda_runtime.h>
#include <cuda_bf16.h>
#include <math.h>
#include <stdint.h>

// ---------------- dims ----------------
#define BATCH 8
#define SEQ   1024
#define DMODEL 1024
#define NHEADS 16
#define DQKV  64
#define DFF   4096
#define NLAYERS 6
#define BL    (BATCH*SEQ)          // 8192
#define D3    (3*DMODEL)           // 3072

typedef __nv_bfloat16 bf16;

// ---------------- scratch ----------------
__device__ float g_h  [BL*DMODEL];
__device__ float g_tmp[BL*DMODEL];
__device__ float g_qkv[BL*D3];
__device__ float g_pe [SEQ*DMODEL];
__device__ unsigned long long g_mb[BL*(SEQ/64)];

// split activations
__device__ bf16 g_hh [BL*DMODEL];
__device__ bf16 g_hl [BL*DMODEL];
__device__ bf16 g_cxh[BL*DMODEL];
__device__ bf16 g_cxl[BL*DMODEL];
__device__ bf16 g_ffh[BL*DFF];
__device__ bf16 g_ffl[BL*DFF];

// transposed + split weights (bf16 hi/lo), layout [N][K] K-major
#define WT_TOTAL (72u*1048576u)
__device__ bf16 g_wt_hi[WT_TOTAL];
__device__ bf16 g_wt_lo[WT_TOTAL];

// ================= PTX helpers =================
__device__ __forceinline__ uint32_t smem_u32(const void* p) {
    uint32_t a;
    asm("{ .reg .u64 t; cvta.to.shared.u64 t, %1; cvt.u32.u64 %0, t; }" : "=r"(a) : "l"(p));
    return a;
}
__device__ __forceinline__ void cp16(uint32_t s, const void* g) {
    asm volatile("cp.async.cg.shared.global [%0], [%1], 16;" :: "r"(s), "l"(g));
}
__device__ __forceinline__ void cp_commit() { asm volatile("cp.async.commit_group;"); }
template <int N> __device__ __forceinline__ void cp_wait() {
    asm volatile("cp.async.wait_group %0;" :: "n"(N));
}
__device__ __forceinline__ void ldm4(uint32_t& r0, uint32_t& r1, uint32_t& r2, uint32_t& r3, uint32_t a) {
    asm volatile("ldmatrix.sync.aligned.m8n8.x4.shared.b16 {%0,%1,%2,%3}, [%4];"
        : "=r"(r0), "=r"(r1), "=r"(r2), "=r"(r3) : "r"(a));
}
__device__ __forceinline__ void mma16816(float* c, uint32_t a0, uint32_t a1, uint32_t a2, uint32_t a3,
                                         uint32_t b0, uint32_t b1) {
    asm volatile("mma.sync.aligned.m16n8k16.row.col.f32.bf16.bf16.f32 "
        "{%0,%1,%2,%3}, {%4,%5,%6,%7}, {%8,%9}, {%0,%1,%2,%3};"
        : "+f"(c[0]), "+f"(c[1]), "+f"(c[2]), "+f"(c[3])
        : "r"(a0), "r"(a1), "r"(a2), "r"(a3), "r"(b0), "r"(b1));
}
__device__ __forceinline__ uint32_t pack_split2(float v0, float v1, uint32_t& lo_out) {
    bf16 h0 = __float2bfloat16(v0);
    bf16 h1 = __float2bfloat16(v1);
    bf16 l0 = __float2bfloat16(v0 - __bfloat162float(h0));
    bf16 l1 = __float2bfloat16(v1 - __bfloat162float(h1));
    uint32_t hi = ((uint32_t)*(uint16_t*)&h1 << 16) | *(uint16_t*)&h0;
    lo_out = ((uint32_t)*(uint16_t*)&l1 << 16) | *(uint16_t*)&l0;
    return hi;
}

// ---------------- setup: positional encoding + mask bitwords (fused) ----------------
__global__ void setup_kernel(const int* __restrict__ mask, unsigned long long* __restrict__ mb,
                             float* __restrict__ pe) {
    int bid = blockIdx.x;
    if (bid < 4096) {
        int idx = bid * 256 + threadIdx.x;      // 0 .. SEQ*DMODEL-1
        int l = idx >> 10;
        int c = idx & 1023;
        double p = (double)(c & ~1) / (double)DMODEL;
        double divisor = pow(10000.0, p);
        double ang = (double)(l + 1) / divisor;
        pe[idx] = (float)((c & 1) ? cos(ang) : sin(ang));
    } else {
        int warp = (((bid - 4096) * 256) + threadIdx.x) >> 5;
        int lane = threadIdx.x & 31;
        const int nwarps = 512 * 256 / 32;      // 4096
        for (int w = warp; w < BL * (SEQ / 64); w += nwarps) {
            int row = w >> 4;
            int kt  = w & 15;
            size_t base = (size_t)row * SEQ + kt * 64;
            int m0 = mask[base + lane];
            int m1 = mask[base + 32 + lane];
            unsigned lo = __ballot_sync(0xffffffffu, m0 != 0);
            unsigned hi = __ballot_sync(0xffffffffu, m1 != 0);
            if (lane == 0) mb[w] = (unsigned long long)lo | ((unsigned long long)hi << 32);
        }
    }
}

// ---------------- embedding + PE (+ split) ----------------
__global__ void embed_kernel(const int* __restrict__ x, const float* __restrict__ embed,
                             const float* __restrict__ pe, float* __restrict__ h,
                             bf16* __restrict__ Hh, bf16* __restrict__ Hl) {
    int r = blockIdx.x;
    int t = threadIdx.x;
    int l = r & 1023;
    int tok = x[r];
    float4 e  = *(const float4*)(embed + (size_t)tok * DMODEL + t * 4);
    float4 pp = *(const float4*)(pe + (size_t)l * DMODEL + t * 4);
    float4 o;
    o.x = e.x * 32.0f + pp.x;
    o.y = e.y * 32.0f + pp.y;
    o.z = e.z * 32.0f + pp.z;
    o.w = e.w * 32.0f + pp.w;
    *(float4*)(h + (size_t)r * DMODEL + t * 4) = o;
    uint32_t hi0, hi1, lo0, lo1;
    hi0 = pack_split2(o.x, o.y, lo0);
    hi1 = pack_split2(o.z, o.w, lo1);
    uint2 hv = {hi0, hi1}, lv = {lo0, lo1};
    *(uint2*)(Hh + (size_t)r * DMODEL + t * 4) = hv;
    *(uint2*)(Hl + (size_t)r * DMODEL + t * 4) = lv;
}

// ---------------- weight transpose + bf16 split ----------------
__device__ __forceinline__ void tsplit_body(const float* W, bf16* Oh, bf16* Ol,
                                            int K, int N, int mode) {
    __shared__ float tile[32][33];
    int n0 = blockIdx.x * 32, k0 = blockIdx.y * 32;
    int tx = threadIdx.x, ty = threadIdx.y;    // 32 x 8
#pragma unroll
    for (int i = 0; i < 32; i += 8) {
        int k = k0 + ty + i, n = n0 + tx;
        float v;
        if (mode == 0) v = W[(size_t)k * N + n];
        else v = W[(size_t)(n >> 6) * (K * 64) + (size_t)k * 64 + (n & 63)];
        tile[ty + i][tx] = v;
    }
    __syncthreads();
#pragma unroll
    for (int i = 0; i < 32; i += 8) {
        int n = n0 + ty + i, k = k0 + tx;
        float v = tile[tx][ty + i];
        bf16 hi = __float2bfloat16(v);
        bf16 lo = __float2bfloat16(v - __bfloat162float(hi));
        Oh[(size_t)n * K + k] = hi;
        Ol[(size_t)n * K + k] = lo;
    }
}

__global__ void tsplit_kernel(const float* __restrict__ W, bf16* __restrict__ Oh, bf16* __restrict__ Ol,
                              int K, int N, int mode) {
    tsplit_body(W, Oh, Ol, K, N, mode);
}

#define M1 1048576u
__global__ void tsplit_qkv_kernel(const float* __restrict__ Wq, const float* __restrict__ Wk,
                                  const float* __restrict__ Wv, bf16* __restrict__ Oh,
                                  bf16* __restrict__ Ol) {
    int z = blockIdx.z;
    const float* W = (z == 0) ? Wq : (z == 1) ? Wk : Wv;
    tsplit_body(W, Oh + (size_t)z * M1, Ol + (size_t)z * M1, DMODEL, DMODEL, 1);
}

// ---------------- HMMA GEMM, 2-stage cp.async, 2 CTAs/SM ----------------
#define BMT 128
#define BNT 128
#define BKC 32
#define TSTRIDE 40
#define TILEB (BMT * TSTRIDE * 2)
#define STAGEB (4 * TILEB)
#define GSMEM (2 * STAGEB)

__global__ void __launch_bounds__(256, 2)
gemm_mma(const bf16* __restrict__ Ah, const bf16* __restrict__ Al,
         const bf16* __restrict__ Bh, const bf16* __restrict__ Bl,
         float* __restrict__ C, bf16* __restrict__ Oh, bf16* __restrict__ Ol,
         int N, int K,
         const float* __restrict__ bias, const float* __restrict__ res, int relu) {
    extern __shared__ char smem[];
    const uint32_t sbase = smem_u32(smem);
    const int t = threadIdx.x;
    const int wid = t >> 5, lane = t & 31;
    const int wm = wid >> 2, wn = wid & 3;
    const int row0 = blockIdx.y * BMT, col0 = blockIdx.x * BNT;

    const bf16* srcs[4];
    srcs[0] = Ah + (size_t)row0 * K;
    srcs[1] = Al + (size_t)row0 * K;
    srcs[2] = Bh + (size_t)col0 * K;
    srcs[3] = Bl + (size_t)col0 * K;

    const int nst = K / BKC;
    const int lrow0 = t >> 2, lchunk = t & 3;

    auto load_stage = [&](int kc, int buf) {
        uint32_t sb = sbase + buf * STAGEB;
#pragma unroll
        for (int m = 0; m < 4; ++m) {
            const bf16* g = srcs[m] + (size_t)kc * BKC;
            uint32_t tb = sb + m * TILEB;
#pragma unroll
            for (int hlf = 0; hlf < 2; ++hlf) {
                int row = lrow0 + hlf * 64;
                cp16(tb + (row * TSTRIDE + lchunk * 8) * 2,
                     g + (size_t)row * K + lchunk * 8);
            }
        }
        cp_commit();
    };

    float acc[4][4][4];
#pragma unroll
    for (int i = 0; i < 4; ++i)
#pragma unroll
        for (int j = 0; j < 4; ++j)
#pragma unroll
            for (int r = 0; r < 4; ++r) acc[i][j][r] = 0.f;

    const int lrow = lane & 15;
    const int lcol = (lane >> 4) << 3;

    load_stage(0, 0);

    for (int kc = 0; kc < nst; ++kc) {
        int buf = kc & 1;
        if (kc + 1 < nst) {
            load_stage(kc + 1, buf ^ 1);
            cp_wait<1>();
        } else {
            cp_wait<0>();
        }
        __syncthreads();

        uint32_t sb = sbase + buf * STAGEB;
        uint32_t sAh = sb;
        uint32_t sAl = sb + TILEB;
        uint32_t sBh = sb + 2 * TILEB;
        uint32_t sBl = sb + 3 * TILEB;

#pragma unroll
        for (int ks = 0; ks < 2; ++ks) {
            int kof = ks * 16 + lcol;
            uint32_t ah[4][4], al[4][4];
#pragma unroll
            for (int mi = 0; mi < 4; ++mi) {
                int row = wm * 64 + mi * 16 + lrow;
                uint32_t off = (row * TSTRIDE + kof) * 2;
                ldm4(ah[mi][0], ah[mi][1], ah[mi][2], ah[mi][3], sAh + off);
                ldm4(al[mi][0], al[mi][1], al[mi][2], al[mi][3], sAl + off);
            }
            uint32_t bh[2][4], bl[2][4];
#pragma unroll
            for (int nh = 0; nh < 2; ++nh) {
                int row = wn * 32 + nh * 16 + lrow;
                uint32_t off = (row * TSTRIDE + kof) * 2;
                ldm4(bh[nh][0], bh[nh][1], bh[nh][2], bh[nh][3], sBh + off);
                ldm4(bl[nh][0], bl[nh][1], bl[nh][2], bl[nh][3], sBl + off);
            }
#pragma unroll
            for (int mi = 0; mi < 4; ++mi) {
#pragma unroll
                for (int ni = 0; ni < 4; ++ni) {
                    int nh = ni >> 1, np = ni & 1;
                    uint32_t b0h = bh[nh][np], b1h = bh[nh][np + 2];
                    uint32_t b0l = bl[nh][np], b1l = bl[nh][np + 2];
                    mma16816(acc[mi][ni], ah[mi][0], ah[mi][1], ah[mi][2], ah[mi][3], b0h, b1h);
                    mma16816(acc[mi][ni], ah[mi][0], ah[mi][1], ah[mi][2], ah[mi][3], b0l, b1l);
                    mma16816(acc[mi][ni], al[mi][0], al[mi][1], al[mi][2], al[mi][3], b0h, b1h);
                }
            }
        }
        __syncthreads();
    }

    // epilogue
    const int erow = lane >> 2, ecol = (lane & 3) * 2;
#pragma unroll
    for (int mi = 0; mi < 4; ++mi) {
#pragma unroll
        for (int p = 0; p < 2; ++p) {
            int r = row0 + wm * 64 + mi * 16 + p * 8 + erow;
            const float* rrow = res ? res + (size_t)r * N : (const float*)0;
#pragma unroll
            for (int ni = 0; ni < 4; ++ni) {
                int c = col0 + wn * 32 + ni * 8 + ecol;
                float v0 = acc[mi][ni][p * 2 + 0];
                float v1 = acc[mi][ni][p * 2 + 1];
                if (bias) { v0 += bias[c]; v1 += bias[c + 1]; }
                if (rrow) {
                    float2 rv = *(const float2*)(rrow + c);
                    v0 += rv.x; v1 += rv.y;
                }
                if (relu) { v0 = fmaxf(v0, 0.f); v1 = fmaxf(v1, 0.f); }
                if (C) {
                    float2 o = {v0, v1};
                    *(float2*)(C + (size_t)r * N + c) = o;
                }
                if (Oh) {
                    uint32_t lo, hi = pack_split2(v0, v1, lo);
                    *(uint32_t*)(Oh + (size_t)r * N + c) = hi;
                    *(uint32_t*)(Ol + (size_t)r * N + c) = lo;
                }
            }
        }
    }
}

// ---------------- flash attention (fp32, __expf softmax, split ctx out) ----------------
#define QSW(d, r) (((d) << 6) + (((((r) >> 2) ^ ((d) & 15))) << 2) + ((r) & 3))

__global__ void __launch_bounds__(256)
flash_kernel(const float* __restrict__ qkv, const unsigned long long* __restrict__ mb,
             bf16* __restrict__ cxh, bf16* __restrict__ cxl) {
    extern __shared__ float sm[];
    float* Qs = sm;
    float* Ks = Qs + 4096;
    float* Vs = Ks + 4096;
    float* Ss = Vs + 4096;
    float* rowM = Ss + 64 * 65;
    float* rowL = rowM + 64;
    float* rowA = rowL + 64;

    int b = blockIdx.z, hh = blockIdx.y, qt = blockIdx.x;
    int t = threadIdx.x, tx = t & 15, ty = t >> 4;
    int rowbase = b * SEQ + qt * 64;
    const float* qbase = qkv + (size_t)rowbase * D3 + hh * 64;

#pragma unroll
    for (int it = 0; it < 4; ++it) {
        int f = t + it * 256;
        int r = f >> 4;
        int d4 = (f & 15) << 2;
        float4 val = *(const float4*)(qbase + (size_t)r * D3 + d4);
        Qs[QSW(d4 + 0, r)] = val.x;
        Qs[QSW(d4 + 1, r)] = val.y;
        Qs[QSW(d4 + 2, r)] = val.z;
        Qs[QSW(d4 + 3, r)] = val.w;
    }
    if (t < 64) { rowM[t] = -INFINITY; rowL[t] = 0.f; }

    float o[4][4];
#pragma unroll
    for (int i = 0; i < 4; ++i)
#pragma unroll
        for (int j = 0; j < 4; ++j) o[i][j] = 0.f;

    const unsigned long long* mrow = mb + (size_t)rowbase * (SEQ / 64);

    for (int kt = 0; kt < SEQ / 64; ++kt) {
        __syncthreads();
        const float* kbase = qkv + (size_t)(b * SEQ + kt * 64) * D3 + DMODEL + hh * 64;
        const float* vbase = qkv + (size_t)(b * SEQ + kt * 64) * D3 + 2 * DMODEL + hh * 64;
#pragma unroll
        for (int it = 0; it < 4; ++it) {
            int f = t + it * 256;
            int r = f >> 4;
            int d4 = (f & 15) << 2;
            float4 kv4 = *(const float4*)(kbase + (size_t)r * D3 + d4);
            Ks[QSW(d4 + 0, r)] = kv4.x;
            Ks[QSW(d4 + 1, r)] = kv4.y;
            Ks[QSW(d4 + 2, r)] = kv4.z;
            Ks[QSW(d4 + 3, r)] = kv4.w;
            float4 vv = *(const float4*)(vbase + (size_t)r * D3 + d4);
            *(float4*)(Vs + r * 64 + d4) = vv;
        }
        __syncthreads();

        float s[4][4];
#pragma unroll
        for (int i = 0; i < 4; ++i)
#pragma unroll
            for (int j = 0; j < 4; ++j) s[i][j] = 0.f;
#pragma unroll 8
        for (int d = 0; d < 64; ++d) {
            float4 a4 = *(const float4*)(Qs + (d << 6) + ((ty ^ (d & 15)) << 2));
            float4 b4 = *(const float4*)(Ks + (d << 6) + ((tx ^ (d & 15)) << 2));
            float a[4] = {a4.x, a4.y, a4.z, a4.w};
            float bb[4] = {b4.x, b4.y, b4.z, b4.w};
#pragma unroll
            for (int i = 0; i < 4; ++i)
#pragma unroll
                for (int j = 0; j < 4; ++j) s[i][j] = fmaf(a[i], bb[j], s[i][j]);
        }
#pragma unroll
        for (int i = 0; i < 4; ++i) {
            int ri = ty * 4 + i;
            unsigned long long wbits = mrow[ri * (SEQ / 64) + kt];
#pragma unroll
            for (int j = 0; j < 4; ++j) {
                int cj = tx * 4 + j;
                float vv = s[i][j] * 0.125f;
                if (!((wbits >> cj) & 1ULL)) vv = -1e9f;
                Ss[ri * 65 + cj] = vv;
            }
        }
        __syncthreads();

        // online softmax: 4 threads per row, fast exp
        {
            int r = t >> 2, sub = t & 3;
            float* srow = Ss + r * 65 + sub * 16;
            float mold = rowM[r];
            float mx = mold;
#pragma unroll
            for (int j = 0; j < 16; ++j) mx = fmaxf(mx, srow[j]);
            mx = fmaxf(mx, __shfl_xor_sync(0xffffffffu, mx, 1));
            mx = fmaxf(mx, __shfl_xor_sync(0xffffffffu, mx, 2));
            float sum = 0.f;
#pragma unroll
            for (int j = 0; j < 16; ++j) {
                float p = __expf(srow[j] - mx);
                srow[j] = p;
                sum += p;
            }
            sum += __shfl_xor_sync(0xffffffffu, sum, 1);
            sum += __shfl_xor_sync(0xffffffffu, sum, 2);
            if (sub == 0) {
                float alpha = __expf(mold - mx);
                rowL[r] = rowL[r] * alpha + sum;
                rowM[r] = mx;
                rowA[r] = alpha;
            }
        }
        __syncthreads();

        float al[4];
#pragma unroll
        for (int i = 0; i < 4; ++i) al[i] = rowA[ty * 4 + i];
#pragma unroll
        for (int i = 0; i < 4; ++i)
#pragma unroll
            for (int j = 0; j < 4; ++j) o[i][j] *= al[i];
#pragma unroll 8
        for (int j = 0; j < 64; ++j) {
            float p0 = Ss[(ty * 4 + 0) * 65 + j];
            float p1 = Ss[(ty * 4 + 1) * 65 + j];
            float p2 = Ss[(ty * 4 + 2) * 65 + j];
            float p3 = Ss[(ty * 4 + 3) * 65 + j];
            float4 vv = *(const float4*)(Vs + j * 64 + tx * 4);
            o[0][0] = fmaf(p0, vv.x, o[0][0]); o[0][1] = fmaf(p0, vv.y, o[0][1]);
            o[0][2] = fmaf(p0, vv.z, o[0][2]); o[0][3] = fmaf(p0, vv.w, o[0][3]);
            o[1][0] = fmaf(p1, vv.x, o[1][0]); o[1][1] = fmaf(p1, vv.y, o[1][1]);
            o[1][2] = fmaf(p1, vv.z, o[1][2]); o[1][3] = fmaf(p1, vv.w, o[1][3]);
            o[2][0] = fmaf(p2, vv.x, o[2][0]); o[2][1] = fmaf(p2, vv.y, o[2][1]);
            o[2][2] = fmaf(p2, vv.z, o[2][2]); o[2][3] = fmaf(p2, vv.w, o[2][3]);
            o[3][0] = fmaf(p3, vv.x, o[3][0]); o[3][1] = fmaf(p3, vv.y, o[3][1]);
            o[3][2] = fmaf(p3, vv.z, o[3][2]); o[3][3] = fmaf(p3, vv.w, o[3][3]);
        }
    }
    __syncthreads();
#pragma unroll
    for (int i = 0; i < 4; ++i) {
        float inv = 1.f / rowL[ty * 4 + i];
        int grow = rowbase + ty * 4 + i;
        float v0 = o[i][0] * inv, v1 = o[i][1] * inv, v2 = o[i][2] * inv, v3 = o[i][3] * inv;
        uint32_t lo0, lo1;
        uint32_t hi0 = pack_split2(v0, v1, lo0);
        uint32_t hi1 = pack_split2(v2, v3, lo1);
        uint2 hv = {hi0, hi1}, lv = {lo0, lo1};
        size_t off = (size_t)grow * DMODEL + hh * 64 + tx * 4;
        *(uint2*)(cxh + off) = hv;
        *(uint2*)(cxl + off) = lv;
    }
}

// ---------------- layernorm (+ split out) ----------------
__global__ void layernorm_kernel(const float* __restrict__ X, const float* __restrict__ s,
                                 const float* __restrict__ bvec, float* __restrict__ Y,
                                 bf16* __restrict__ Yh, bf16* __restrict__ Yl) {
    __shared__ float red[256];
    int r = blockIdx.x;
    int t = threadIdx.x;
    float4 v = *(const float4*)(X + (size_t)r * DMODEL + t * 4);
    float ssum = v.x + v.y + v.z + v.w;
    red[t] = ssum;
    __syncthreads();
    for (int off = 128; off > 0; off >>= 1) {
        if (t < off) red[t] += red[t + off];
        __syncthreads();
    }
    float mu = red[0] * (1.f / DMODEL);
    __syncthreads();
    float d0 = v.x - mu, d1 = v.y - mu, d2 = v.z - mu, d3 = v.w - mu;
    red[t] = d0 * d0 + d1 * d1 + d2 * d2 + d3 * d3;
    __syncthreads();
    for (int off = 128; off > 0; off >>= 1) {
        if (t < off) red[t] += red[t + off];
        __syncthreads();
    }
    float var = red[0] * (1.f / DMODEL);
    float rs = rsqrtf(var + 1e-5f);
    float4 sc = *(const float4*)(s + t * 4);
    float4 be = *(const float4*)(bvec + t * 4);
    float4 out;
    out.x = d0 * rs * sc.x + be.x;
    out.y = d1 * rs * sc.y + be.y;
    out.z = d2 * rs * sc.z + be.z;
    out.w = d3 * rs * sc.w + be.w;
    *(float4*)(Y + (size_t)r * DMODEL + t * 4) = out;
    uint32_t lo0, lo1;
    uint32_t hi0 = pack_split2(out.x, out.y, lo0);
    uint32_t hi1 = pack_split2(out.z, out.w, lo1);
    uint2 hv = {hi0, hi1}, lv = {lo0, lo1};
    *(uint2*)(Yh + (size_t)r * DMODEL + t * 4) = hv;
    *(uint2*)(Yl + (size_t)r * DMODEL + t * 4) = lv;
}

// ---------------- output head ----------------
__global__ void head_kernel(const float* __restrict__ h, const float* __restrict__ ow,
                            const float* __restrict__ ob, float* __restrict__ out) {
    int t = threadIdx.x;
    int b = t >> 4, a = t & 15;
    const float* hrow = h + (size_t)(b * SEQ + (SEQ - 1)) * DMODEL;
    float acc = 0.f;
    for (int m = 0; m < DMODEL; ++m) acc = fmaf(hrow[m], ow[m * 16 + a], acc);
    acc += ob[a];
    float mx = acc;
    for (int off = 8; off > 0; off >>= 1)
        mx = fmaxf(mx, __shfl_xor_sync(0xffffffffu, mx, off));
    float e = expf(acc - mx);
    float sum = e;
    for (int off = 8; off > 0; off >>= 1)
        sum += __shfl_xor_sync(0xffffffffu, sum, off);
    out[b * 16 + a] = acc - mx - logf(sum);
}

// ---------------- launch ----------------
extern "C" void kernel_launch(void* const* d_in, const int* in_sizes, int n_in,
                              void* d_out, int out_size) {
    const int*   x     = (const int*)d_in[0];
    const int*   mask  = (const int*)d_in[1];
    const float* embed = (const float*)d_in[2];
    const float* Wq    = (const float*)d_in[3];
    const float* Wk    = (const float*)d_in[4];
    const float* Wv    = (const float*)d_in[5];
    const float* Wo_w  = (const float*)d_in[6];
    const float* Wo_b  = (const float*)d_in[7];
    const float* ln1_s = (const float*)d_in[8];
    const float* ln1_b = (const float*)d_in[9];
    const float* ff_w1 = (const float*)d_in[10];
    const float* ff_b1 = (const float*)d_in[11];
    const float* ff_w2 = (const float*)d_in[12];
    const float* ff_b2 = (const float*)d_in[13];
    const float* ln2_s = (const float*)d_in[14];
    const float* ln2_b = (const float*)d_in[15];
    const float* out_w = (const float*)d_in[16];
    const float* out_b = (const float*)d_in[17];
    float* out = (float*)d_out;

    float *h, *tmp, *qkv, *pe;
    unsigned long long* mb;
    bf16 *wtH, *wtL, *hH, *hL, *cxH, *cxL, *ffH, *ffL;
    cudaGetSymbolAddress((void**)&h,   g_h);
    cudaGetSymbolAddress((void**)&tmp, g_tmp);
    cudaGetSymbolAddress((void**)&qkv, g_qkv);
    cudaGetSymbolAddress((void**)&pe,  g_pe);
    cudaGetSymbolAddress((void**)&mb,  g_mb);
    cudaGetSymbolAddress((void**)&wtH, g_wt_hi);
    cudaGetSymbolAddress((void**)&wtL, g_wt_lo);
    cudaGetSymbolAddress((void**)&hH,  g_hh);
    cudaGetSymbolAddress((void**)&hL,  g_hl);
    cudaGetSymbolAddress((void**)&cxH, g_cxh);
    cudaGetSymbolAddress((void**)&cxL, g_cxl);
    cudaGetSymbolAddress((void**)&ffH, g_ffh);
    cudaGetSymbolAddress((void**)&ffL, g_ffl);

    const int flash_smem = (4096 * 3 + 64 * 65 + 3 * 64) * 4;
    cudaFuncSetAttribute(flash_kernel, cudaFuncAttributeMaxDynamicSharedMemorySize, flash_smem);
    cudaFuncSetAttribute(gemm_mma, cudaFuncAttributeMaxDynamicSharedMemorySize, GSMEM);

    dim3 tb(32, 8);
    dim3 gQKV(D3 / BNT, BL / BMT);   // (24, 64)
    dim3 gD(DMODEL / BNT, BL / BMT); // (8, 64)
    dim3 gF(DFF / BNT, BL / BMT);    // (32, 64)

    // Launch order: our index 3 is what ncu (-s 5 -c 1, +2 harness launches) profiles.
    setup_kernel<<<4096 + 512, 256>>>(mask, mb, pe);                    // 0
    embed_kernel<<<BL, 256>>>(x, embed, pe, h, hH, hL);                 // 1

    for (int i = 0; i < NLAYERS; ++i) {
        size_t oq = (size_t)i * 3 * M1;
        size_t oo = 18 * (size_t)M1 + (size_t)i * M1;
        size_t o1 = 24 * (size_t)M1 + (size_t)i * 4 * M1;
        size_t o2 = 48 * (size_t)M1 + (size_t)i * 4 * M1;

        tsplit_qkv_kernel<<<dim3(32, 32, 3), tb>>>(
            Wq + (size_t)i * NHEADS * DMODEL * DQKV,
            Wk + (size_t)i * NHEADS * DMODEL * DQKV,
            Wv + (size_t)i * NHEADS * DMODEL * DQKV,
            wtH + oq, wtL + oq);                                        // 2 (layer 0)

        // fused QKV: [BL, 3072]                                        // 3 (layer 0, profiled)
        gemm_mma<<<gQKV, 256, GSMEM>>>(hH, hL, wtH + oq, wtL + oq, qkv, nullptr, nullptr,
                                       D3, DMODEL, nullptr, nullptr, 0);

        tsplit_kernel<<<dim3(32, 32), tb>>>(Wo_w + (size_t)i * DMODEL * DMODEL,
                                            wtH + oo, wtL + oo, DMODEL, DMODEL, 0);
        tsplit_kernel<<<dim3(128, 32), tb>>>(ff_w1 + (size_t)i * DMODEL * DFF,
                                             wtH + o1, wtL + o1, DMODEL, DFF, 0);
        tsplit_kernel<<<dim3(32, 128), tb>>>(ff_w2 + (size_t)i * DFF * DMODEL,
                                             wtH + o2, wtL + o2, DFF, DMODEL, 0);

        flash_kernel<<<dim3(SEQ / 64, NHEADS, BATCH), 256, flash_smem>>>(qkv, mb, cxH, cxL);

        gemm_mma<<<gD, 256, GSMEM>>>(cxH, cxL, wtH + oo, wtL + oo, tmp, nullptr, nullptr,
                                     DMODEL, DMODEL, Wo_b + (size_t)i * DMODEL, h, 0);
        layernorm_kernel<<<BL, 256>>>(tmp, ln1_s + (size_t)i * DMODEL, ln1_b + (size_t)i * DMODEL, h, hH, hL);

        gemm_mma<<<gF, 256, GSMEM>>>(hH, hL, wtH + o1, wtL + o1, nullptr, ffH, ffL,
                                     DFF, DMODEL, ff_b1 + (size_t)i * DFF, nullptr, 1);
        gemm_mma<<<gD, 256, GSMEM>>>(ffH, ffL, wtH + o2, wtL + o2, tmp, nullptr, nullptr,
                                     DMODEL, DFF, ff_b2 + (size_t)i * DMODEL, h, 0);
        layernorm_kernel<<<BL, 256>>>(tmp, ln2_s + (size_t)i * DMODEL, ln2_b + (size_t)i * DMODEL, h, hH, hL);
    }

    head_kernel<<<1, 128>>>(h, out_w, out_b, out);
}

// round 9
// speedup vs baseline: 1.5851x; 1.5851x over previous
#include <cuda_runtime.h>
#include <cuda_bf16.h>
#include <math.h>
#include <stdint.h>

// ---------------- dims ----------------
#define BATCH 8
#define SEQ   1024
#define DMODEL 1024
#define NHEADS 16
#define DQKV  64
#define DFF   4096
#define NLAYERS 6
#define BL    (BATCH*SEQ)          // 8192
#define D3    (3*DMODEL)           // 3072

typedef __nv_bfloat16 bf16;

// ---------------- scratch ----------------
__device__ float g_h  [BL*DMODEL];
__device__ float g_tmp[BL*DMODEL];
__device__ float g_qkv[BL*D3];
__device__ float g_pe [SEQ*DMODEL];
__device__ unsigned long long g_mb[BL*(SEQ/64)];

// split activations
__device__ bf16 g_hh [BL*DMODEL];
__device__ bf16 g_hl [BL*DMODEL];
__device__ bf16 g_cxh[BL*DMODEL];
__device__ bf16 g_cxl[BL*DMODEL];
__device__ bf16 g_ffh[BL*DFF];
__device__ bf16 g_ffl[BL*DFF];

// transposed + split weights (bf16 hi/lo), layout [N][K] K-major
#define WT_TOTAL (72u*1048576u)
__device__ bf16 g_wt_hi[WT_TOTAL];
__device__ bf16 g_wt_lo[WT_TOTAL];

// ================= PTX helpers =================
__device__ __forceinline__ uint32_t smem_u32(const void* p) {
    uint32_t a;
    asm("{ .reg .u64 t; cvta.to.shared.u64 t, %1; cvt.u32.u64 %0, t; }" : "=r"(a) : "l"(p));
    return a;
}
__device__ __forceinline__ void cp16(uint32_t s, const void* g) {
    asm volatile("cp.async.cg.shared.global [%0], [%1], 16;" :: "r"(s), "l"(g));
}
__device__ __forceinline__ void cp_commit() { asm volatile("cp.async.commit_group;"); }
template <int N> __device__ __forceinline__ void cp_wait() {
    asm volatile("cp.async.wait_group %0;" :: "n"(N));
}
__device__ __forceinline__ void ldm4(uint32_t& r0, uint32_t& r1, uint32_t& r2, uint32_t& r3, uint32_t a) {
    asm volatile("ldmatrix.sync.aligned.m8n8.x4.shared.b16 {%0,%1,%2,%3}, [%4];"
        : "=r"(r0), "=r"(r1), "=r"(r2), "=r"(r3) : "r"(a));
}
__device__ __forceinline__ void mma16816(float* c, uint32_t a0, uint32_t a1, uint32_t a2, uint32_t a3,
                                         uint32_t b0, uint32_t b1) {
    asm volatile("mma.sync.aligned.m16n8k16.row.col.f32.bf16.bf16.f32 "
        "{%0,%1,%2,%3}, {%4,%5,%6,%7}, {%8,%9}, {%0,%1,%2,%3};"
        : "+f"(c[0]), "+f"(c[1]), "+f"(c[2]), "+f"(c[3])
        : "r"(a0), "r"(a1), "r"(a2), "r"(a3), "r"(b0), "r"(b1));
}
__device__ __forceinline__ uint32_t pack_split2(float v0, float v1, uint32_t& lo_out) {
    bf16 h0 = __float2bfloat16(v0);
    bf16 h1 = __float2bfloat16(v1);
    bf16 l0 = __float2bfloat16(v0 - __bfloat162float(h0));
    bf16 l1 = __float2bfloat16(v1 - __bfloat162float(h1));
    uint32_t hi = ((uint32_t)*(uint16_t*)&h1 << 16) | *(uint16_t*)&h0;
    lo_out = ((uint32_t)*(uint16_t*)&l1 << 16) | *(uint16_t*)&l0;
    return hi;
}

// ---------------- setup: positional encoding + mask bitwords (fused) ----------------
__global__ void setup_kernel(const int* __restrict__ mask, unsigned long long* __restrict__ mb,
                             float* __restrict__ pe) {
    int bid = blockIdx.x;
    if (bid < 4096) {
        int idx = bid * 256 + threadIdx.x;
        int l = idx >> 10;
        int c = idx & 1023;
        double p = (double)(c & ~1) / (double)DMODEL;
        double divisor = pow(10000.0, p);
        double ang = (double)(l + 1) / divisor;
        pe[idx] = (float)((c & 1) ? cos(ang) : sin(ang));
    } else {
        int warp = (((bid - 4096) * 256) + threadIdx.x) >> 5;
        int lane = threadIdx.x & 31;
        const int nwarps = 512 * 256 / 32;
        for (int w = warp; w < BL * (SEQ / 64); w += nwarps) {
            int row = w >> 4;
            int kt  = w & 15;
            size_t base = (size_t)row * SEQ + kt * 64;
            int m0 = mask[base + lane];
            int m1 = mask[base + 32 + lane];
            unsigned lo = __ballot_sync(0xffffffffu, m0 != 0);
            unsigned hi = __ballot_sync(0xffffffffu, m1 != 0);
            if (lane == 0) mb[w] = (unsigned long long)lo | ((unsigned long long)hi << 32);
        }
    }
}

// ---------------- embedding + PE (+ split) ----------------
__global__ void embed_kernel(const int* __restrict__ x, const float* __restrict__ embed,
                             const float* __restrict__ pe, float* __restrict__ h,
                             bf16* __restrict__ Hh, bf16* __restrict__ Hl) {
    int r = blockIdx.x;
    int t = threadIdx.x;
    int l = r & 1023;
    int tok = x[r];
    float4 e  = *(const float4*)(embed + (size_t)tok * DMODEL + t * 4);
    float4 pp = *(const float4*)(pe + (size_t)l * DMODEL + t * 4);
    float4 o;
    o.x = e.x * 32.0f + pp.x;
    o.y = e.y * 32.0f + pp.y;
    o.z = e.z * 32.0f + pp.z;
    o.w = e.w * 32.0f + pp.w;
    *(float4*)(h + (size_t)r * DMODEL + t * 4) = o;
    uint32_t hi0, hi1, lo0, lo1;
    hi0 = pack_split2(o.x, o.y, lo0);
    hi1 = pack_split2(o.z, o.w, lo1);
    uint2 hv = {hi0, hi1}, lv = {lo0, lo1};
    *(uint2*)(Hh + (size_t)r * DMODEL + t * 4) = hv;
    *(uint2*)(Hl + (size_t)r * DMODEL + t * 4) = lv;
}

// ---------------- weight transpose + bf16 split ----------------
__device__ __forceinline__ void tsplit_body(const float* W, bf16* Oh, bf16* Ol,
                                            int K, int N, int mode) {
    __shared__ float tile[32][33];
    int n0 = blockIdx.x * 32, k0 = blockIdx.y * 32;
    int tx = threadIdx.x, ty = threadIdx.y;
#pragma unroll
    for (int i = 0; i < 32; i += 8) {
        int k = k0 + ty + i, n = n0 + tx;
        float v;
        if (mode == 0) v = W[(size_t)k * N + n];
        else v = W[(size_t)(n >> 6) * (K * 64) + (size_t)k * 64 + (n & 63)];
        tile[ty + i][tx] = v;
    }
    __syncthreads();
#pragma unroll
    for (int i = 0; i < 32; i += 8) {
        int n = n0 + ty + i, k = k0 + tx;
        float v = tile[tx][ty + i];
        bf16 hi = __float2bfloat16(v);
        bf16 lo = __float2bfloat16(v - __bfloat162float(hi));
        Oh[(size_t)n * K + k] = hi;
        Ol[(size_t)n * K + k] = lo;
    }
}

__global__ void tsplit_kernel(const float* __restrict__ W, bf16* __restrict__ Oh, bf16* __restrict__ Ol,
                              int K, int N, int mode) {
    tsplit_body(W, Oh, Ol, K, N, mode);
}

#define M1 1048576u
__global__ void tsplit_qkv_kernel(const float* __restrict__ Wq, const float* __restrict__ Wk,
                                  const float* __restrict__ Wv, bf16* __restrict__ Oh,
                                  bf16* __restrict__ Ol) {
    int z = blockIdx.z;
    const float* W = (z == 0) ? Wq : (z == 1) ? Wk : Wv;
    tsplit_body(W, Oh + (size_t)z * M1, Ol + (size_t)z * M1, DMODEL, DMODEL, 1);
}

// ---------------- HMMA GEMM: BKC=64, 2-stage cp.async, fragment pipeline ----------------
#define BMT 128
#define BNT 128
#define BKC 64
#define TSTRIDE 72                         // 64 + 8 pad (bf16 elems); 144B rows, LDSM conflict-free
#define TILEB (BMT * TSTRIDE * 2)          // 18432 B
#define STAGEB (4 * TILEB)                 // 73728 B
#define GSMEM (2 * STAGEB)                 // 147456 B  (1 CTA/SM)

__global__ void __launch_bounds__(256, 1)
gemm_mma(const bf16* __restrict__ Ah, const bf16* __restrict__ Al,
         const bf16* __restrict__ Bh, const bf16* __restrict__ Bl,
         float* __restrict__ C, bf16* __restrict__ Oh, bf16* __restrict__ Ol,
         int N, int K,
         const float* __restrict__ bias, const float* __restrict__ res, int relu) {
    extern __shared__ char smem[];
    const uint32_t sbase = smem_u32(smem);
    const int t = threadIdx.x;
    const int wid = t >> 5, lane = t & 31;
    const int wm = wid >> 2, wn = wid & 3;       // 2 x 4 warps, warp tile 64x32
    const int row0 = blockIdx.y * BMT, col0 = blockIdx.x * BNT;

    const bf16* srcs[4];
    srcs[0] = Ah + (size_t)row0 * K;
    srcs[1] = Al + (size_t)row0 * K;
    srcs[2] = Bh + (size_t)col0 * K;
    srcs[3] = Bl + (size_t)col0 * K;

    const int nst = K / BKC;
    const int lrow8 = t >> 3, lchunk = t & 7;    // loader: 8 x 16B chunks per row

    auto load_stage = [&](int kc, int buf) {
        uint32_t sb = sbase + buf * STAGEB;
#pragma unroll
        for (int m = 0; m < 4; ++m) {
            const bf16* g = srcs[m] + (size_t)kc * BKC;
            uint32_t tb = sb + m * TILEB;
#pragma unroll
            for (int p = 0; p < 4; ++p) {
                int row = lrow8 + p * 32;
                cp16(tb + (row * TSTRIDE + lchunk * 8) * 2,
                     g + (size_t)row * K + lchunk * 8);
            }
        }
        cp_commit();
    };

    float acc[4][4][4];
#pragma unroll
    for (int i = 0; i < 4; ++i)
#pragma unroll
        for (int j = 0; j < 4; ++j)
#pragma unroll
            for (int r = 0; r < 4; ++r) acc[i][j][r] = 0.f;

    const int lrow = lane & 15;
    const int lcol = (lane >> 4) << 3;

    // fragment double buffer (2 ks-slots)
    uint32_t fah[2][4][4], fal[2][4][4], fbh[2][2][4], fbl[2][2][4];

    load_stage(0, 0);

    for (int kc = 0; kc < nst; ++kc) {
        int buf = kc & 1;
        if (kc + 1 < nst) {
            load_stage(kc + 1, buf ^ 1);
            cp_wait<1>();
        } else {
            cp_wait<0>();
        }
        __syncthreads();

        uint32_t sb = sbase + buf * STAGEB;
        uint32_t sAh = sb;
        uint32_t sAl = sb + TILEB;
        uint32_t sBh = sb + 2 * TILEB;
        uint32_t sBl = sb + 3 * TILEB;

        auto load_frags = [&](int ks, int fb) {
            int kof = ks * 16 + lcol;
#pragma unroll
            for (int mi = 0; mi < 4; ++mi) {
                int row = wm * 64 + mi * 16 + lrow;
                uint32_t off = (row * TSTRIDE + kof) * 2;
                ldm4(fah[fb][mi][0], fah[fb][mi][1], fah[fb][mi][2], fah[fb][mi][3], sAh + off);
                ldm4(fal[fb][mi][0], fal[fb][mi][1], fal[fb][mi][2], fal[fb][mi][3], sAl + off);
            }
#pragma unroll
            for (int nh = 0; nh < 2; ++nh) {
                int row = wn * 32 + nh * 16 + lrow;
                uint32_t off = (row * TSTRIDE + kof) * 2;
                ldm4(fbh[fb][nh][0], fbh[fb][nh][1], fbh[fb][nh][2], fbh[fb][nh][3], sBh + off);
                ldm4(fbl[fb][nh][0], fbl[fb][nh][1], fbl[fb][nh][2], fbl[fb][nh][3], sBl + off);
            }
        };

        auto mma_frags = [&](int fb) {
#pragma unroll
            for (int mi = 0; mi < 4; ++mi) {
#pragma unroll
                for (int ni = 0; ni < 4; ++ni) {
                    int nh = ni >> 1, np = ni & 1;
                    uint32_t b0h = fbh[fb][nh][np], b1h = fbh[fb][nh][np + 2];
                    uint32_t b0l = fbl[fb][nh][np], b1l = fbl[fb][nh][np + 2];
                    mma16816(acc[mi][ni], fah[fb][mi][0], fah[fb][mi][1], fah[fb][mi][2], fah[fb][mi][3], b0h, b1h);
                    mma16816(acc[mi][ni], fah[fb][mi][0], fah[fb][mi][1], fah[fb][mi][2], fah[fb][mi][3], b0l, b1l);
                    mma16816(acc[mi][ni], fal[fb][mi][0], fal[fb][mi][1], fal[fb][mi][2], fal[fb][mi][3], b0h, b1h);
                }
            }
        };

        load_frags(0, 0);
#pragma unroll
        for (int ks = 0; ks < 4; ++ks) {
            if (ks < 3) load_frags(ks + 1, (ks + 1) & 1);
            mma_frags(ks & 1);
        }
        __syncthreads();
    }

    // epilogue
    const int erow = lane >> 2, ecol = (lane & 3) * 2;
#pragma unroll
    for (int mi = 0; mi < 4; ++mi) {
#pragma unroll
        for (int p = 0; p < 2; ++p) {
            int r = row0 + wm * 64 + mi * 16 + p * 8 + erow;
            const float* rrow = res ? res + (size_t)r * N : (const float*)0;
#pragma unroll
            for (int ni = 0; ni < 4; ++ni) {
                int c = col0 + wn * 32 + ni * 8 + ecol;
                float v0 = acc[mi][ni][p * 2 + 0];
                float v1 = acc[mi][ni][p * 2 + 1];
                if (bias) { v0 += bias[c]; v1 += bias[c + 1]; }
                if (rrow) {
                    float2 rv = *(const float2*)(rrow + c);
                    v0 += rv.x; v1 += rv.y;
                }
                if (relu) { v0 = fmaxf(v0, 0.f); v1 = fmaxf(v1, 0.f); }
                if (C) {
                    float2 o = {v0, v1};
                    *(float2*)(C + (size_t)r * N + c) = o;
                }
                if (Oh) {
                    uint32_t lo, hi = pack_split2(v0, v1, lo);
                    *(uint32_t*)(Oh + (size_t)r * N + c) = hi;
                    *(uint32_t*)(Ol + (size_t)r * N + c) = lo;
                }
            }
        }
    }
}

// ---------------- flash attention (fp32, __expf softmax, split ctx out) ----------------
#define QSW(d, r) (((d) << 6) + (((((r) >> 2) ^ ((d) & 15))) << 2) + ((r) & 3))

__global__ void __launch_bounds__(256)
flash_kernel(const float* __restrict__ qkv, const unsigned long long* __restrict__ mb,
             bf16* __restrict__ cxh, bf16* __restrict__ cxl) {
    extern __shared__ float sm[];
    float* Qs = sm;
    float* Ks = Qs + 4096;
    float* Vs = Ks + 4096;
    float* Ss = Vs + 4096;
    float* rowM = Ss + 64 * 65;
    float* rowL = rowM + 64;
    float* rowA = rowL + 64;

    int b = blockIdx.z, hh = blockIdx.y, qt = blockIdx.x;
    int t = threadIdx.x, tx = t & 15, ty = t >> 4;
    int rowbase = b * SEQ + qt * 64;
    const float* qbase = qkv + (size_t)rowbase * D3 + hh * 64;

#pragma unroll
    for (int it = 0; it < 4; ++it) {
        int f = t + it * 256;
        int r = f >> 4;
        int d4 = (f & 15) << 2;
        float4 val = *(const float4*)(qbase + (size_t)r * D3 + d4);
        Qs[QSW(d4 + 0, r)] = val.x;
        Qs[QSW(d4 + 1, r)] = val.y;
        Qs[QSW(d4 + 2, r)] = val.z;
        Qs[QSW(d4 + 3, r)] = val.w;
    }
    if (t < 64) { rowM[t] = -INFINITY; rowL[t] = 0.f; }

    float o[4][4];
#pragma unroll
    for (int i = 0; i < 4; ++i)
#pragma unroll
        for (int j = 0; j < 4; ++j) o[i][j] = 0.f;

    const unsigned long long* mrow = mb + (size_t)rowbase * (SEQ / 64);

    for (int kt = 0; kt < SEQ / 64; ++kt) {
        __syncthreads();
        const float* kbase = qkv + (size_t)(b * SEQ + kt * 64) * D3 + DMODEL + hh * 64;
        const float* vbase = qkv + (size_t)(b * SEQ + kt * 64) * D3 + 2 * DMODEL + hh * 64;
#pragma unroll
        for (int it = 0; it < 4; ++it) {
            int f = t + it * 256;
            int r = f >> 4;
            int d4 = (f & 15) << 2;
            float4 kv4 = *(const float4*)(kbase + (size_t)r * D3 + d4);
            Ks[QSW(d4 + 0, r)] = kv4.x;
            Ks[QSW(d4 + 1, r)] = kv4.y;
            Ks[QSW(d4 + 2, r)] = kv4.z;
            Ks[QSW(d4 + 3, r)] = kv4.w;
            float4 vv = *(const float4*)(vbase + (size_t)r * D3 + d4);
            *(float4*)(Vs + r * 64 + d4) = vv;
        }
        __syncthreads();

        float s[4][4];
#pragma unroll
        for (int i = 0; i < 4; ++i)
#pragma unroll
            for (int j = 0; j < 4; ++j) s[i][j] = 0.f;
#pragma unroll 8
        for (int d = 0; d < 64; ++d) {
            float4 a4 = *(const float4*)(Qs + (d << 6) + ((ty ^ (d & 15)) << 2));
            float4 b4 = *(const float4*)(Ks + (d << 6) + ((tx ^ (d & 15)) << 2));
            float a[4] = {a4.x, a4.y, a4.z, a4.w};
            float bb[4] = {b4.x, b4.y, b4.z, b4.w};
#pragma unroll
            for (int i = 0; i < 4; ++i)
#pragma unroll
                for (int j = 0; j < 4; ++j) s[i][j] = fmaf(a[i], bb[j], s[i][j]);
        }
#pragma unroll
        for (int i = 0; i < 4; ++i) {
            int ri = ty * 4 + i;
            unsigned long long wbits = mrow[ri * (SEQ / 64) + kt];
#pragma unroll
            for (int j = 0; j < 4; ++j) {
                int cj = tx * 4 + j;
                float vv = s[i][j] * 0.125f;
                if (!((wbits >> cj) & 1ULL)) vv = -1e9f;
                Ss[ri * 65 + cj] = vv;
            }
        }
        __syncthreads();

        {
            int r = t >> 2, sub = t & 3;
            float* srow = Ss + r * 65 + sub * 16;
            float mold = rowM[r];
            float mx = mold;
#pragma unroll
            for (int j = 0; j < 16; ++j) mx = fmaxf(mx, srow[j]);
            mx = fmaxf(mx, __shfl_xor_sync(0xffffffffu, mx, 1));
            mx = fmaxf(mx, __shfl_xor_sync(0xffffffffu, mx, 2));
            float sum = 0.f;
#pragma unroll
            for (int j = 0; j < 16; ++j) {
                float p = __expf(srow[j] - mx);
                srow[j] = p;
                sum += p;
            }
            sum += __shfl_xor_sync(0xffffffffu, sum, 1);
            sum += __shfl_xor_sync(0xffffffffu, sum, 2);
            if (sub == 0) {
                float alpha = __expf(mold - mx);
                rowL[r] = rowL[r] * alpha + sum;
                rowM[r] = mx;
                rowA[r] = alpha;
            }
        }
        __syncthreads();

        float al[4];
#pragma unroll
        for (int i = 0; i < 4; ++i) al[i] = rowA[ty * 4 + i];
#pragma unroll
        for (int i = 0; i < 4; ++i)
#pragma unroll
            for (int j = 0; j < 4; ++j) o[i][j] *= al[i];
#pragma unroll 8
        for (int j = 0; j < 64; ++j) {
            float p0 = Ss[(ty * 4 + 0) * 65 + j];
            float p1 = Ss[(ty * 4 + 1) * 65 + j];
            float p2 = Ss[(ty * 4 + 2) * 65 + j];
            float p3 = Ss[(ty * 4 + 3) * 65 + j];
            float4 vv = *(const float4*)(Vs + j * 64 + tx * 4);
            o[0][0] = fmaf(p0, vv.x, o[0][0]); o[0][1] = fmaf(p0, vv.y, o[0][1]);
            o[0][2] = fmaf(p0, vv.z, o[0][2]); o[0][3] = fmaf(p0, vv.w, o[0][3]);
            o[1][0] = fmaf(p1, vv.x, o[1][0]); o[1][1] = fmaf(p1, vv.y, o[1][1]);
            o[1][2] = fmaf(p1, vv.z, o[1][2]); o[1][3] = fmaf(p1, vv.w, o[1][3]);
            o[2][0] = fmaf(p2, vv.x, o[2][0]); o[2][1] = fmaf(p2, vv.y, o[2][1]);
            o[2][2] = fmaf(p2, vv.z, o[2][2]); o[2][3] = fmaf(p2, vv.w, o[2][3]);
            o[3][0] = fmaf(p3, vv.x, o[3][0]); o[3][1] = fmaf(p3, vv.y, o[3][1]);
            o[3][2] = fmaf(p3, vv.z, o[3][2]); o[3][3] = fmaf(p3, vv.w, o[3][3]);
        }
    }
    __syncthreads();
#pragma unroll
    for (int i = 0; i < 4; ++i) {
        float inv = 1.f / rowL[ty * 4 + i];
        int grow = rowbase + ty * 4 + i;
        float v0 = o[i][0] * inv, v1 = o[i][1] * inv, v2 = o[i][2] * inv, v3 = o[i][3] * inv;
        uint32_t lo0, lo1;
        uint32_t hi0 = pack_split2(v0, v1, lo0);
        uint32_t hi1 = pack_split2(v2, v3, lo1);
        uint2 hv = {hi0, hi1}, lv = {lo0, lo1};
        size_t off = (size_t)grow * DMODEL + hh * 64 + tx * 4;
        *(uint2*)(cxh + off) = hv;
        *(uint2*)(cxl + off) = lv;
    }
}

// ---------------- layernorm (+ split out) ----------------
__global__ void layernorm_kernel(const float* __restrict__ X, const float* __restrict__ s,
                                 const float* __restrict__ bvec, float* __restrict__ Y,
                                 bf16* __restrict__ Yh, bf16* __restrict__ Yl) {
    __shared__ float red[256];
    int r = blockIdx.x;
    int t = threadIdx.x;
    float4 v = *(const float4*)(X + (size_t)r * DMODEL + t * 4);
    float ssum = v.x + v.y + v.z + v.w;
    red[t] = ssum;
    __syncthreads();
    for (int off = 128; off > 0; off >>= 1) {
        if (t < off) red[t] += red[t + off];
        __syncthreads();
    }
    float mu = red[0] * (1.f / DMODEL);
    __syncthreads();
    float d0 = v.x - mu, d1 = v.y - mu, d2 = v.z - mu, d3 = v.w - mu;
    red[t] = d0 * d0 + d1 * d1 + d2 * d2 + d3 * d3;
    __syncthreads();
    for (int off = 128; off > 0; off >>= 1) {
        if (t < off) red[t] += red[t + off];
        __syncthreads();
    }
    float var = red[0] * (1.f / DMODEL);
    float rs = rsqrtf(var + 1e-5f);
    float4 sc = *(const float4*)(s + t * 4);
    float4 be = *(const float4*)(bvec + t * 4);
    float4 out;
    out.x = d0 * rs * sc.x + be.x;
    out.y = d1 * rs * sc.y + be.y;
    out.z = d2 * rs * sc.z + be.z;
    out.w = d3 * rs * sc.w + be.w;
    *(float4*)(Y + (size_t)r * DMODEL + t * 4) = out;
    uint32_t lo0, lo1;
    uint32_t hi0 = pack_split2(out.x, out.y, lo0);
    uint32_t hi1 = pack_split2(out.z, out.w, lo1);
    uint2 hv = {hi0, hi1}, lv = {lo0, lo1};
    *(uint2*)(Yh + (size_t)r * DMODEL + t * 4) = hv;
    *(uint2*)(Yl + (size_t)r * DMODEL + t * 4) = lv;
}

// ---------------- output head ----------------
__global__ void head_kernel(const float* __restrict__ h, const float* __restrict__ ow,
                            const float* __restrict__ ob, float* __restrict__ out) {
    int t = threadIdx.x;
    int b = t >> 4, a = t & 15;
    const float* hrow = h + (size_t)(b * SEQ + (SEQ - 1)) * DMODEL;
    float acc = 0.f;
    for (int m = 0; m < DMODEL; ++m) acc = fmaf(hrow[m], ow[m * 16 + a], acc);
    acc += ob[a];
    float mx = acc;
    for (int off = 8; off > 0; off >>= 1)
        mx = fmaxf(mx, __shfl_xor_sync(0xffffffffu, mx, off));
    float e = expf(acc - mx);
    float sum = e;
    for (int off = 8; off > 0; off >>= 1)
        sum += __shfl_xor_sync(0xffffffffu, sum, off);
    out[b * 16 + a] = acc - mx - logf(sum);
}

// ---------------- launch ----------------
extern "C" void kernel_launch(void* const* d_in, const int* in_sizes, int n_in,
                              void* d_out, int out_size) {
    const int*   x     = (const int*)d_in[0];
    const int*   mask  = (const int*)d_in[1];
    const float* embed = (const float*)d_in[2];
    const float* Wq    = (const float*)d_in[3];
    const float* Wk    = (const float*)d_in[4];
    const float* Wv    = (const float*)d_in[5];
    const float* Wo_w  = (const float*)d_in[6];
    const float* Wo_b  = (const float*)d_in[7];
    const float* ln1_s = (const float*)d_in[8];
    const float* ln1_b = (const float*)d_in[9];
    const float* ff_w1 = (const float*)d_in[10];
    const float* ff_b1 = (const float*)d_in[11];
    const float* ff_w2 = (const float*)d_in[12];
    const float* ff_b2 = (const float*)d_in[13];
    const float* ln2_s = (const float*)d_in[14];
    const float* ln2_b = (const float*)d_in[15];
    const float* out_w = (const float*)d_in[16];
    const float* out_b = (const float*)d_in[17];
    float* out = (float*)d_out;

    float *h, *tmp, *qkv, *pe;
    unsigned long long* mb;
    bf16 *wtH, *wtL, *hH, *hL, *cxH, *cxL, *ffH, *ffL;
    cudaGetSymbolAddress((void**)&h,   g_h);
    cudaGetSymbolAddress((void**)&tmp, g_tmp);
    cudaGetSymbolAddress((void**)&qkv, g_qkv);
    cudaGetSymbolAddress((void**)&pe,  g_pe);
    cudaGetSymbolAddress((void**)&mb,  g_mb);
    cudaGetSymbolAddress((void**)&wtH, g_wt_hi);
    cudaGetSymbolAddress((void**)&wtL, g_wt_lo);
    cudaGetSymbolAddress((void**)&hH,  g_hh);
    cudaGetSymbolAddress((void**)&hL,  g_hl);
    cudaGetSymbolAddress((void**)&cxH, g_cxh);
    cudaGetSymbolAddress((void**)&cxL, g_cxl);
    cudaGetSymbolAddress((void**)&ffH, g_ffh);
    cudaGetSymbolAddress((void**)&ffL, g_ffl);

    const int flash_smem = (4096 * 3 + 64 * 65 + 3 * 64) * 4;
    cudaFuncSetAttribute(flash_kernel, cudaFuncAttributeMaxDynamicSharedMemorySize, flash_smem);
    cudaFuncSetAttribute(gemm_mma, cudaFuncAttributeMaxDynamicSharedMemorySize, GSMEM);

    dim3 tb(32, 8);
    dim3 gQKV(D3 / BNT, BL / BMT);   // (24, 64)
    dim3 gD(DMODEL / BNT, BL / BMT); // (8, 64)
    dim3 gF(DFF / BNT, BL / BMT);    // (32, 64)

    setup_kernel<<<4096 + 512, 256>>>(mask, mb, pe);                    // 0
    embed_kernel<<<BL, 256>>>(x, embed, pe, h, hH, hL);                 // 1

    for (int i = 0; i < NLAYERS; ++i) {
        size_t oq = (size_t)i * 3 * M1;
        size_t oo = 18 * (size_t)M1 + (size_t)i * M1;
        size_t o1 = 24 * (size_t)M1 + (size_t)i * 4 * M1;
        size_t o2 = 48 * (size_t)M1 + (size_t)i * 4 * M1;

        tsplit_qkv_kernel<<<dim3(32, 32, 3), tb>>>(
            Wq + (size_t)i * NHEADS * DMODEL * DQKV,
            Wk + (size_t)i * NHEADS * DMODEL * DQKV,
            Wv + (size_t)i * NHEADS * DMODEL * DQKV,
            wtH + oq, wtL + oq);                                        // 2 (layer 0)

        // fused QKV: [BL, 3072]                                        // 3 (layer 0, profiled)
        gemm_mma<<<gQKV, 256, GSMEM>>>(hH, hL, wtH + oq, wtL + oq, qkv, nullptr, nullptr,
                                       D3, DMODEL, nullptr, nullptr, 0);

        tsplit_kernel<<<dim3(32, 32), tb>>>(Wo_w + (size_t)i * DMODEL * DMODEL,
                                            wtH + oo, wtL + oo, DMODEL, DMODEL, 0);
        tsplit_kernel<<<dim3(128, 32), tb>>>(ff_w1 + (size_t)i * DMODEL * DFF,
                                             wtH + o1, wtL + o1, DMODEL, DFF, 0);
        tsplit_kernel<<<dim3(32, 128), tb>>>(ff_w2 + (size_t)i * DFF * DMODEL,
                                             wtH + o2, wtL + o2, DFF, DMODEL, 0);

        flash_kernel<<<dim3(SEQ / 64, NHEADS, BATCH), 256, flash_smem>>>(qkv, mb, cxH, cxL);

        gemm_mma<<<gD, 256, GSMEM>>>(cxH, cxL, wtH + oo, wtL + oo, tmp, nullptr, nullptr,
                                     DMODEL, DMODEL, Wo_b + (size_t)i * DMODEL, h, 0);
        layernorm_kernel<<<BL, 256>>>(tmp, ln1_s + (size_t)i * DMODEL, ln1_b + (size_t)i * DMODEL, h, hH, hL);

        gemm_mma<<<gF, 256, GSMEM>>>(hH, hL, wtH + o1, wtL + o1, nullptr, ffH, ffL,
                                     DFF, DMODEL, ff_b1 + (size_t)i * DFF, nullptr, 1);
        gemm_mma<<<gD, 256, GSMEM>>>(ffH, ffL, wtH + o2, wtL + o2, tmp, nullptr, nullptr,
                                     DMODEL, DFF, ff_b2 + (size_t)i * DMODEL, h, 0);
        layernorm_kernel<<<BL, 256>>>(tmp, ln2_s + (size_t)i * DMODEL, ln2_b + (size_t)i * DMODEL, h, hH, hL);
    }

    head_kernel<<<1, 128>>>(h, out_w, out_b, out);
}

// round 10
// speedup vs baseline: 1.6693x; 1.0531x over previous
#include <cuda_runtime.h>
#include <cuda_bf16.h>
#include <math.h>
#include <stdint.h>

// ---------------- dims ----------------
#define BATCH 8
#define SEQ   1024
#define DMODEL 1024
#define NHEADS 16
#define DQKV  64
#define DFF   4096
#define NLAYERS 6
#define BL    (BATCH*SEQ)          // 8192
#define D3    (3*DMODEL)           // 3072

typedef __nv_bfloat16 bf16;

// ---------------- scratch ----------------
__device__ float g_h  [BL*DMODEL];
__device__ float g_tmp[BL*DMODEL];
__device__ float g_qkv[BL*D3];
__device__ float g_pe [SEQ*DMODEL];
__device__ unsigned long long g_mb[BL*(SEQ/64)];

// split activations
__device__ bf16 g_hh [BL*DMODEL];
__device__ bf16 g_hl [BL*DMODEL];
__device__ bf16 g_cxh[BL*DMODEL];
__device__ bf16 g_cxl[BL*DMODEL];
__device__ bf16 g_ffh[BL*DFF];
__device__ bf16 g_ffl[BL*DFF];

// transposed + split weights (bf16 hi/lo), layout [N][K] K-major
#define WT_TOTAL (72u*1048576u)
__device__ bf16 g_wt_hi[WT_TOTAL];
__device__ bf16 g_wt_lo[WT_TOTAL];

// ================= PTX helpers =================
__device__ __forceinline__ uint32_t smem_u32(const void* p) {
    uint32_t a;
    asm("{ .reg .u64 t; cvta.to.shared.u64 t, %1; cvt.u32.u64 %0, t; }" : "=r"(a) : "l"(p));
    return a;
}
__device__ __forceinline__ void cp16(uint32_t s, const void* g) {
    asm volatile("cp.async.cg.shared.global [%0], [%1], 16;" :: "r"(s), "l"(g));
}
__device__ __forceinline__ void cp_commit() { asm volatile("cp.async.commit_group;"); }
template <int N> __device__ __forceinline__ void cp_wait() {
    asm volatile("cp.async.wait_group %0;" :: "n"(N));
}
__device__ __forceinline__ void ldm4(uint32_t& r0, uint32_t& r1, uint32_t& r2, uint32_t& r3, uint32_t a) {
    asm volatile("ldmatrix.sync.aligned.m8n8.x4.shared.b16 {%0,%1,%2,%3}, [%4];"
        : "=r"(r0), "=r"(r1), "=r"(r2), "=r"(r3) : "r"(a));
}
__device__ __forceinline__ void mma16816(float* c, uint32_t a0, uint32_t a1, uint32_t a2, uint32_t a3,
                                         uint32_t b0, uint32_t b1) {
    asm volatile("mma.sync.aligned.m16n8k16.row.col.f32.bf16.bf16.f32 "
        "{%0,%1,%2,%3}, {%4,%5,%6,%7}, {%8,%9}, {%0,%1,%2,%3};"
        : "+f"(c[0]), "+f"(c[1]), "+f"(c[2]), "+f"(c[3])
        : "r"(a0), "r"(a1), "r"(a2), "r"(a3), "r"(b0), "r"(b1));
}
__device__ __forceinline__ uint32_t pack_split2(float v0, float v1, uint32_t& lo_out) {
    bf16 h0 = __float2bfloat16(v0);
    bf16 h1 = __float2bfloat16(v1);
    bf16 l0 = __float2bfloat16(v0 - __bfloat162float(h0));
    bf16 l1 = __float2bfloat16(v1 - __bfloat162float(h1));
    uint32_t hi = ((uint32_t)*(uint16_t*)&h1 << 16) | *(uint16_t*)&h0;
    lo_out = ((uint32_t)*(uint16_t*)&l1 << 16) | *(uint16_t*)&l0;
    return hi;
}

// ---------------- setup: positional encoding + mask bitwords (fused) ----------------
__global__ void setup_kernel(const int* __restrict__ mask, unsigned long long* __restrict__ mb,
                             float* __restrict__ pe) {
    int bid = blockIdx.x;
    if (bid < 4096) {
        int idx = bid * 256 + threadIdx.x;
        int l = idx >> 10;
        int c = idx & 1023;
        double p = (double)(c & ~1) / (double)DMODEL;
        double divisor = pow(10000.0, p);
        double ang = (double)(l + 1) / divisor;
        pe[idx] = (float)((c & 1) ? cos(ang) : sin(ang));
    } else {
        int warp = (((bid - 4096) * 256) + threadIdx.x) >> 5;
        int lane = threadIdx.x & 31;
        const int nwarps = 512 * 256 / 32;
        for (int w = warp; w < BL * (SEQ / 64); w += nwarps) {
            int row = w >> 4;
            int kt  = w & 15;
            size_t base = (size_t)row * SEQ + kt * 64;
            int m0 = mask[base + lane];
            int m1 = mask[base + 32 + lane];
            unsigned lo = __ballot_sync(0xffffffffu, m0 != 0);
            unsigned hi = __ballot_sync(0xffffffffu, m1 != 0);
            if (lane == 0) mb[w] = (unsigned long long)lo | ((unsigned long long)hi << 32);
        }
    }
}

// ---------------- embedding + PE (+ split) ----------------
__global__ void embed_kernel(const int* __restrict__ x, const float* __restrict__ embed,
                             const float* __restrict__ pe, float* __restrict__ h,
                             bf16* __restrict__ Hh, bf16* __restrict__ Hl) {
    int r = blockIdx.x;
    int t = threadIdx.x;
    int l = r & 1023;
    int tok = x[r];
    float4 e  = *(const float4*)(embed + (size_t)tok * DMODEL + t * 4);
    float4 pp = *(const float4*)(pe + (size_t)l * DMODEL + t * 4);
    float4 o;
    o.x = e.x * 32.0f + pp.x;
    o.y = e.y * 32.0f + pp.y;
    o.z = e.z * 32.0f + pp.z;
    o.w = e.w * 32.0f + pp.w;
    *(float4*)(h + (size_t)r * DMODEL + t * 4) = o;
    uint32_t hi0, hi1, lo0, lo1;
    hi0 = pack_split2(o.x, o.y, lo0);
    hi1 = pack_split2(o.z, o.w, lo1);
    uint2 hv = {hi0, hi1}, lv = {lo0, lo1};
    *(uint2*)(Hh + (size_t)r * DMODEL + t * 4) = hv;
    *(uint2*)(Hl + (size_t)r * DMODEL + t * 4) = lv;
}

// ---------------- weight transpose + bf16 split ----------------
__device__ __forceinline__ void tsplit_body(const float* W, bf16* Oh, bf16* Ol,
                                            int K, int N, int mode) {
    __shared__ float tile[32][33];
    int n0 = blockIdx.x * 32, k0 = blockIdx.y * 32;
    int tx = threadIdx.x, ty = threadIdx.y;
#pragma unroll
    for (int i = 0; i < 32; i += 8) {
        int k = k0 + ty + i, n = n0 + tx;
        float v;
        if (mode == 0) v = W[(size_t)k * N + n];
        else v = W[(size_t)(n >> 6) * (K * 64) + (size_t)k * 64 + (n & 63)];
        tile[ty + i][tx] = v;
    }
    __syncthreads();
#pragma unroll
    for (int i = 0; i < 32; i += 8) {
        int n = n0 + ty + i, k = k0 + tx;
        float v = tile[tx][ty + i];
        bf16 hi = __float2bfloat16(v);
        bf16 lo = __float2bfloat16(v - __bfloat162float(hi));
        Oh[(size_t)n * K + k] = hi;
        Ol[(size_t)n * K + k] = lo;
    }
}

__global__ void tsplit_kernel(const float* __restrict__ W, bf16* __restrict__ Oh, bf16* __restrict__ Ol,
                              int K, int N, int mode) {
    tsplit_body(W, Oh, Ol, K, N, mode);
}

#define M1 1048576u
__global__ void tsplit_qkv_kernel(const float* __restrict__ Wq, const float* __restrict__ Wk,
                                  const float* __restrict__ Wv, bf16* __restrict__ Oh,
                                  bf16* __restrict__ Ol) {
    int z = blockIdx.z;
    const float* W = (z == 0) ? Wq : (z == 1) ? Wk : Wv;
    tsplit_body(W, Oh + (size_t)z * M1, Ol + (size_t)z * M1, DMODEL, DMODEL, 1);
}

// ---------------- HMMA GEMM: 128x64 tile, BKC=64, 2-stage cp.async, 2 CTAs/SM ----------------
#define BMT 128
#define BNT 64
#define BKC 64
#define TSTRIDE 72                         // 64 + 8 pad (bf16)
#define TILEBA (BMT * TSTRIDE * 2)         // 18432 B
#define TILEBB (BNT * TSTRIDE * 2)         // 9216 B
#define STAGEB (2 * TILEBA + 2 * TILEBB)   // 55296 B
#define GSMEM (2 * STAGEB)                 // 110592 B -> 2 CTAs/SM

__global__ void __launch_bounds__(256, 2)
gemm_mma(const bf16* __restrict__ Ah, const bf16* __restrict__ Al,
         const bf16* __restrict__ Bh, const bf16* __restrict__ Bl,
         float* __restrict__ C, bf16* __restrict__ Oh, bf16* __restrict__ Ol,
         int N, int K,
         const float* __restrict__ bias, const float* __restrict__ res, int relu) {
    extern __shared__ char smem[];
    const uint32_t sbase = smem_u32(smem);
    const int t = threadIdx.x;
    const int wid = t >> 5, lane = t & 31;
    const int wm = wid >> 1, wn = wid & 1;       // 4 x 2 warps, warp tile 32x32
    const int row0 = blockIdx.y * BMT, col0 = blockIdx.x * BNT;

    const bf16* srcA[2];
    const bf16* srcB[2];
    srcA[0] = Ah + (size_t)row0 * K;
    srcA[1] = Al + (size_t)row0 * K;
    srcB[0] = Bh + (size_t)col0 * K;
    srcB[1] = Bl + (size_t)col0 * K;

    const int nst = K / BKC;
    const int lrow8 = t >> 3, lchunk = t & 7;    // 8 x 16B chunks per 64-elem row

    auto load_stage = [&](int kc, int buf) {
        uint32_t sb = sbase + buf * STAGEB;
#pragma unroll
        for (int m = 0; m < 2; ++m) {
            const bf16* g = srcA[m] + (size_t)kc * BKC;
            uint32_t tb = sb + m * TILEBA;
#pragma unroll
            for (int p = 0; p < 4; ++p) {
                int row = lrow8 + p * 32;
                cp16(tb + (row * TSTRIDE + lchunk * 8) * 2,
                     g + (size_t)row * K + lchunk * 8);
            }
        }
#pragma unroll
        for (int m = 0; m < 2; ++m) {
            const bf16* g = srcB[m] + (size_t)kc * BKC;
            uint32_t tb = sb + 2 * TILEBA + m * TILEBB;
#pragma unroll
            for (int p = 0; p < 2; ++p) {
                int row = lrow8 + p * 32;
                cp16(tb + (row * TSTRIDE + lchunk * 8) * 2,
                     g + (size_t)row * K + lchunk * 8);
            }
        }
        cp_commit();
    };

    float acc[2][4][4];
#pragma unroll
    for (int i = 0; i < 2; ++i)
#pragma unroll
        for (int j = 0; j < 4; ++j)
#pragma unroll
            for (int r = 0; r < 4; ++r) acc[i][j][r] = 0.f;

    const int lrow = lane & 15;
    const int lcol = (lane >> 4) << 3;

    load_stage(0, 0);

    for (int kc = 0; kc < nst; ++kc) {
        int buf = kc & 1;
        if (kc + 1 < nst) {
            load_stage(kc + 1, buf ^ 1);
            cp_wait<1>();
        } else {
            cp_wait<0>();
        }
        __syncthreads();

        uint32_t sb = sbase + buf * STAGEB;
        uint32_t sAh = sb;
        uint32_t sAl = sb + TILEBA;
        uint32_t sBh = sb + 2 * TILEBA;
        uint32_t sBl = sb + 2 * TILEBA + TILEBB;

#pragma unroll
        for (int ks = 0; ks < 4; ++ks) {
            int kof = ks * 16 + lcol;
            uint32_t ah[2][4], al[2][4];
#pragma unroll
            for (int mi = 0; mi < 2; ++mi) {
                int row = wm * 32 + mi * 16 + lrow;
                uint32_t off = (row * TSTRIDE + kof) * 2;
                ldm4(ah[mi][0], ah[mi][1], ah[mi][2], ah[mi][3], sAh + off);
                ldm4(al[mi][0], al[mi][1], al[mi][2], al[mi][3], sAl + off);
            }
            uint32_t bh[2][4], bl[2][4];
#pragma unroll
            for (int nh = 0; nh < 2; ++nh) {
                int row = wn * 32 + nh * 16 + lrow;
                uint32_t off = (row * TSTRIDE + kof) * 2;
                ldm4(bh[nh][0], bh[nh][1], bh[nh][2], bh[nh][3], sBh + off);
                ldm4(bl[nh][0], bl[nh][1], bl[nh][2], bl[nh][3], sBl + off);
            }
#pragma unroll
            for (int mi = 0; mi < 2; ++mi) {
#pragma unroll
                for (int ni = 0; ni < 4; ++ni) {
                    int nh = ni >> 1, np = ni & 1;
                    uint32_t b0h = bh[nh][np], b1h = bh[nh][np + 2];
                    uint32_t b0l = bl[nh][np], b1l = bl[nh][np + 2];
                    mma16816(acc[mi][ni], ah[mi][0], ah[mi][1], ah[mi][2], ah[mi][3], b0h, b1h);
                    mma16816(acc[mi][ni], ah[mi][0], ah[mi][1], ah[mi][2], ah[mi][3], b0l, b1l);
                    mma16816(acc[mi][ni], al[mi][0], al[mi][1], al[mi][2], al[mi][3], b0h, b1h);
                }
            }
        }
        __syncthreads();
    }

    // epilogue: warp tile rows wm*32 + mi*16, cols wn*32 + ni*8
    const int erow = lane >> 2, ecol = (lane & 3) * 2;
#pragma unroll
    for (int mi = 0; mi < 2; ++mi) {
#pragma unroll
        for (int p = 0; p < 2; ++p) {
            int r = row0 + wm * 32 + mi * 16 + p * 8 + erow;
            const float* rrow = res ? res + (size_t)r * N : (const float*)0;
#pragma unroll
            for (int ni = 0; ni < 4; ++ni) {
                int c = col0 + wn * 32 + ni * 8 + ecol;
                float v0 = acc[mi][ni][p * 2 + 0];
                float v1 = acc[mi][ni][p * 2 + 1];
                if (bias) { v0 += bias[c]; v1 += bias[c + 1]; }
                if (rrow) {
                    float2 rv = *(const float2*)(rrow + c);
                    v0 += rv.x; v1 += rv.y;
                }
                if (relu) { v0 = fmaxf(v0, 0.f); v1 = fmaxf(v1, 0.f); }
                if (C) {
                    float2 o = {v0, v1};
                    *(float2*)(C + (size_t)r * N + c) = o;
                }
                if (Oh) {
                    uint32_t lo, hi = pack_split2(v0, v1, lo);
                    *(uint32_t*)(Oh + (size_t)r * N + c) = hi;
                    *(uint32_t*)(Ol + (size_t)r * N + c) = lo;
                }
            }
        }
    }
}

// ---------------- flash attention (fp32, __expf softmax, split ctx out) ----------------
#define QSW(d, r) (((d) << 6) + (((((r) >> 2) ^ ((d) & 15))) << 2) + ((r) & 3))

__global__ void __launch_bounds__(256)
flash_kernel(const float* __restrict__ qkv, const unsigned long long* __restrict__ mb,
             bf16* __restrict__ cxh, bf16* __restrict__ cxl) {
    extern __shared__ float sm[];
    float* Qs = sm;
    float* Ks = Qs + 4096;
    float* Vs = Ks + 4096;
    float* Ss = Vs + 4096;
    float* rowM = Ss + 64 * 65;
    float* rowL = rowM + 64;
    float* rowA = rowL + 64;

    int b = blockIdx.z, hh = blockIdx.y, qt = blockIdx.x;
    int t = threadIdx.x, tx = t & 15, ty = t >> 4;
    int rowbase = b * SEQ + qt * 64;
    const float* qbase = qkv + (size_t)rowbase * D3 + hh * 64;

#pragma unroll
    for (int it = 0; it < 4; ++it) {
        int f = t + it * 256;
        int r = f >> 4;
        int d4 = (f & 15) << 2;
        float4 val = *(const float4*)(qbase + (size_t)r * D3 + d4);
        Qs[QSW(d4 + 0, r)] = val.x;
        Qs[QSW(d4 + 1, r)] = val.y;
        Qs[QSW(d4 + 2, r)] = val.z;
        Qs[QSW(d4 + 3, r)] = val.w;
    }
    if (t < 64) { rowM[t] = -INFINITY; rowL[t] = 0.f; }

    float o[4][4];
#pragma unroll
    for (int i = 0; i < 4; ++i)
#pragma unroll
        for (int j = 0; j < 4; ++j) o[i][j] = 0.f;

    const unsigned long long* mrow = mb + (size_t)rowbase * (SEQ / 64);

    for (int kt = 0; kt < SEQ / 64; ++kt) {
        __syncthreads();
        const float* kbase = qkv + (size_t)(b * SEQ + kt * 64) * D3 + DMODEL + hh * 64;
        const float* vbase = qkv + (size_t)(b * SEQ + kt * 64) * D3 + 2 * DMODEL + hh * 64;
#pragma unroll
        for (int it = 0; it < 4; ++it) {
            int f = t + it * 256;
            int r = f >> 4;
            int d4 = (f & 15) << 2;
            float4 kv4 = *(const float4*)(kbase + (size_t)r * D3 + d4);
            Ks[QSW(d4 + 0, r)] = kv4.x;
            Ks[QSW(d4 + 1, r)] = kv4.y;
            Ks[QSW(d4 + 2, r)] = kv4.z;
            Ks[QSW(d4 + 3, r)] = kv4.w;
            float4 vv = *(const float4*)(vbase + (size_t)r * D3 + d4);
            *(float4*)(Vs + r * 64 + d4) = vv;
        }
        __syncthreads();

        float s[4][4];
#pragma unroll
        for (int i = 0; i < 4; ++i)
#pragma unroll
            for (int j = 0; j < 4; ++j) s[i][j] = 0.f;
#pragma unroll 8
        for (int d = 0; d < 64; ++d) {
            float4 a4 = *(const float4*)(Qs + (d << 6) + ((ty ^ (d & 15)) << 2));
            float4 b4 = *(const float4*)(Ks + (d << 6) + ((tx ^ (d & 15)) << 2));
            float a[4] = {a4.x, a4.y, a4.z, a4.w};
            float bb[4] = {b4.x, b4.y, b4.z, b4.w};
#pragma unroll
            for (int i = 0; i < 4; ++i)
#pragma unroll
                for (int j = 0; j < 4; ++j) s[i][j] = fmaf(a[i], bb[j], s[i][j]);
        }
#pragma unroll
        for (int i = 0; i < 4; ++i) {
            int ri = ty * 4 + i;
            unsigned long long wbits = mrow[ri * (SEQ / 64) + kt];
#pragma unroll
            for (int j = 0; j < 4; ++j) {
                int cj = tx * 4 + j;
                float vv = s[i][j] * 0.125f;
                if (!((wbits >> cj) & 1ULL)) vv = -1e9f;
                Ss[ri * 65 + cj] = vv;
            }
        }
        __syncthreads();

        {
            int r = t >> 2, sub = t & 3;
            float* srow = Ss + r * 65 + sub * 16;
            float mold = rowM[r];
            float mx = mold;
#pragma unroll
            for (int j = 0; j < 16; ++j) mx = fmaxf(mx, srow[j]);
            mx = fmaxf(mx, __shfl_xor_sync(0xffffffffu, mx, 1));
            mx = fmaxf(mx, __shfl_xor_sync(0xffffffffu, mx, 2));
            float sum = 0.f;
#pragma unroll
            for (int j = 0; j < 16; ++j) {
                float p = __expf(srow[j] - mx);
                srow[j] = p;
                sum += p;
            }
            sum += __shfl_xor_sync(0xffffffffu, sum, 1);
            sum += __shfl_xor_sync(0xffffffffu, sum, 2);
            if (sub == 0) {
                float alpha = __expf(mold - mx);
                rowL[r] = rowL[r] * alpha + sum;
                rowM[r] = mx;
                rowA[r] = alpha;
            }
        }
        __syncthreads();

        float al[4];
#pragma unroll
        for (int i = 0; i < 4; ++i) al[i] = rowA[ty * 4 + i];
#pragma unroll
        for (int i = 0; i < 4; ++i)
#pragma unroll
            for (int j = 0; j < 4; ++j) o[i][j] *= al[i];
#pragma unroll 8
        for (int j = 0; j < 64; ++j) {
            float p0 = Ss[(ty * 4 + 0) * 65 + j];
            float p1 = Ss[(ty * 4 + 1) * 65 + j];
            float p2 = Ss[(ty * 4 + 2) * 65 + j];
            float p3 = Ss[(ty * 4 + 3) * 65 + j];
            float4 vv = *(const float4*)(Vs + j * 64 + tx * 4);
            o[0][0] = fmaf(p0, vv.x, o[0][0]); o[0][1] = fmaf(p0, vv.y, o[0][1]);
            o[0][2] = fmaf(p0, vv.z, o[0][2]); o[0][3] = fmaf(p0, vv.w, o[0][3]);
            o[1][0] = fmaf(p1, vv.x, o[1][0]); o[1][1] = fmaf(p1, vv.y, o[1][1]);
            o[1][2] = fmaf(p1, vv.z, o[1][2]); o[1][3] = fmaf(p1, vv.w, o[1][3]);
            o[2][0] = fmaf(p2, vv.x, o[2][0]); o[2][1] = fmaf(p2, vv.y, o[2][1]);
            o[2][2] = fmaf(p2, vv.z, o[2][2]); o[2][3] = fmaf(p2, vv.w, o[2][3]);
            o[3][0] = fmaf(p3, vv.x, o[3][0]); o[3][1] = fmaf(p3, vv.y, o[3][1]);
            o[3][2] = fmaf(p3, vv.z, o[3][2]); o[3][3] = fmaf(p3, vv.w, o[3][3]);
        }
    }
    __syncthreads();
#pragma unroll
    for (int i = 0; i < 4; ++i) {
        float inv = 1.f / rowL[ty * 4 + i];
        int grow = rowbase + ty * 4 + i;
        float v0 = o[i][0] * inv, v1 = o[i][1] * inv, v2 = o[i][2] * inv, v3 = o[i][3] * inv;
        uint32_t lo0, lo1;
        uint32_t hi0 = pack_split2(v0, v1, lo0);
        uint32_t hi1 = pack_split2(v2, v3, lo1);
        uint2 hv = {hi0, hi1}, lv = {lo0, lo1};
        size_t off = (size_t)grow * DMODEL + hh * 64 + tx * 4;
        *(uint2*)(cxh + off) = hv;
        *(uint2*)(cxl + off) = lv;
    }
}

// ---------------- layernorm (+ split out) ----------------
__global__ void layernorm_kernel(const float* __restrict__ X, const float* __restrict__ s,
                                 const float* __restrict__ bvec, float* __restrict__ Y,
                                 bf16* __restrict__ Yh, bf16* __restrict__ Yl) {
    __shared__ float red[256];
    int r = blockIdx.x;
    int t = threadIdx.x;
    float4 v = *(const float4*)(X + (size_t)r * DMODEL + t * 4);
    float ssum = v.x + v.y + v.z + v.w;
    red[t] = ssum;
    __syncthreads();
    for (int off = 128; off > 0; off >>= 1) {
        if (t < off) red[t] += red[t + off];
        __syncthreads();
    }
    float mu = red[0] * (1.f / DMODEL);
    __syncthreads();
    float d0 = v.x - mu, d1 = v.y - mu, d2 = v.z - mu, d3 = v.w - mu;
    red[t] = d0 * d0 + d1 * d1 + d2 * d2 + d3 * d3;
    __syncthreads();
    for (int off = 128; off > 0; off >>= 1) {
        if (t < off) red[t] += red[t + off];
        __syncthreads();
    }
    float var = red[0] * (1.f / DMODEL);
    float rs = rsqrtf(var + 1e-5f);
    float4 sc = *(const float4*)(s + t * 4);
    float4 be = *(const float4*)(bvec + t * 4);
    float4 out;
    out.x = d0 * rs * sc.x + be.x;
    out.y = d1 * rs * sc.y + be.y;
    out.z = d2 * rs * sc.z + be.z;
    out.w = d3 * rs * sc.w + be.w;
    *(float4*)(Y + (size_t)r * DMODEL + t * 4) = out;
    uint32_t lo0, lo1;
    uint32_t hi0 = pack_split2(out.x, out.y, lo0);
    uint32_t hi1 = pack_split2(out.z, out.w, lo1);
    uint2 hv = {hi0, hi1}, lv = {lo0, lo1};
    *(uint2*)(Yh + (size_t)r * DMODEL + t * 4) = hv;
    *(uint2*)(Yl + (size_t)r * DMODEL + t * 4) = lv;
}

// ---------------- output head ----------------
__global__ void head_kernel(const float* __restrict__ h, const float* __restrict__ ow,
                            const float* __restrict__ ob, float* __restrict__ out) {
    int t = threadIdx.x;
    int b = t >> 4, a = t & 15;
    const float* hrow = h + (size_t)(b * SEQ + (SEQ - 1)) * DMODEL;
    float acc = 0.f;
    for (int m = 0; m < DMODEL; ++m) acc = fmaf(hrow[m], ow[m * 16 + a], acc);
    acc += ob[a];
    float mx = acc;
    for (int off = 8; off > 0; off >>= 1)
        mx = fmaxf(mx, __shfl_xor_sync(0xffffffffu, mx, off));
    float e = expf(acc - mx);
    float sum = e;
    for (int off = 8; off > 0; off >>= 1)
        sum += __shfl_xor_sync(0xffffffffu, sum, off);
    out[b * 16 + a] = acc - mx - logf(sum);
}

// ---------------- launch ----------------
extern "C" void kernel_launch(void* const* d_in, const int* in_sizes, int n_in,
                              void* d_out, int out_size) {
    const int*   x     = (const int*)d_in[0];
    const int*   mask  = (const int*)d_in[1];
    const float* embed = (const float*)d_in[2];
    const float* Wq    = (const float*)d_in[3];
    const float* Wk    = (const float*)d_in[4];
    const float* Wv    = (const float*)d_in[5];
    const float* Wo_w  = (const float*)d_in[6];
    const float* Wo_b  = (const float*)d_in[7];
    const float* ln1_s = (const float*)d_in[8];
    const float* ln1_b = (const float*)d_in[9];
    const float* ff_w1 = (const float*)d_in[10];
    const float* ff_b1 = (const float*)d_in[11];
    const float* ff_w2 = (const float*)d_in[12];
    const float* ff_b2 = (const float*)d_in[13];
    const float* ln2_s = (const float*)d_in[14];
    const float* ln2_b = (const float*)d_in[15];
    const float* out_w = (const float*)d_in[16];
    const float* out_b = (const float*)d_in[17];
    float* out = (float*)d_out;

    float *h, *tmp, *qkv, *pe;
    unsigned long long* mb;
    bf16 *wtH, *wtL, *hH, *hL, *cxH, *cxL, *ffH, *ffL;
    cudaGetSymbolAddress((void**)&h,   g_h);
    cudaGetSymbolAddress((void**)&tmp, g_tmp);
    cudaGetSymbolAddress((void**)&qkv, g_qkv);
    cudaGetSymbolAddress((void**)&pe,  g_pe);
    cudaGetSymbolAddress((void**)&mb,  g_mb);
    cudaGetSymbolAddress((void**)&wtH, g_wt_hi);
    cudaGetSymbolAddress((void**)&wtL, g_wt_lo);
    cudaGetSymbolAddress((void**)&hH,  g_hh);
    cudaGetSymbolAddress((void**)&hL,  g_hl);
    cudaGetSymbolAddress((void**)&cxH, g_cxh);
    cudaGetSymbolAddress((void**)&cxL, g_cxl);
    cudaGetSymbolAddress((void**)&ffH, g_ffh);
    cudaGetSymbolAddress((void**)&ffL, g_ffl);

    const int flash_smem = (4096 * 3 + 64 * 65 + 3 * 64) * 4;
    cudaFuncSetAttribute(flash_kernel, cudaFuncAttributeMaxDynamicSharedMemorySize, flash_smem);
    cudaFuncSetAttribute(gemm_mma, cudaFuncAttributeMaxDynamicSharedMemorySize, GSMEM);

    dim3 tb(32, 8);
    dim3 gQKV(D3 / BNT, BL / BMT);   // (48, 64)
    dim3 gD(DMODEL / BNT, BL / BMT); // (16, 64)
    dim3 gF(DFF / BNT, BL / BMT);    // (64, 64)

    setup_kernel<<<4096 + 512, 256>>>(mask, mb, pe);                    // 0
    embed_kernel<<<BL, 256>>>(x, embed, pe, h, hH, hL);                 // 1

    for (int i = 0; i < NLAYERS; ++i) {
        size_t oq = (size_t)i * 3 * M1;
        size_t oo = 18 * (size_t)M1 + (size_t)i * M1;
        size_t o1 = 24 * (size_t)M1 + (size_t)i * 4 * M1;
        size_t o2 = 48 * (size_t)M1 + (size_t)i * 4 * M1;

        tsplit_qkv_kernel<<<dim3(32, 32, 3), tb>>>(
            Wq + (size_t)i * NHEADS * DMODEL * DQKV,
            Wk + (size_t)i * NHEADS * DMODEL * DQKV,
            Wv + (size_t)i * NHEADS * DMODEL * DQKV,
            wtH + oq, wtL + oq);                                        // 2 (layer 0)

        // fused QKV: [BL, 3072]                                        // 3 (layer 0, profiled)
        gemm_mma<<<gQKV, 256, GSMEM>>>(hH, hL, wtH + oq, wtL + oq, qkv, nullptr, nullptr,
                                       D3, DMODEL, nullptr, nullptr, 0);

        tsplit_kernel<<<dim3(32, 32), tb>>>(Wo_w + (size_t)i * DMODEL * DMODEL,
                                            wtH + oo, wtL + oo, DMODEL, DMODEL, 0);
        tsplit_kernel<<<dim3(128, 32), tb>>>(ff_w1 + (size_t)i * DMODEL * DFF,
                                             wtH + o1, wtL + o1, DMODEL, DFF, 0);
        tsplit_kernel<<<dim3(32, 128), tb>>>(ff_w2 + (size_t)i * DFF * DMODEL,
                                             wtH + o2, wtL + o2, DFF, DMODEL, 0);

        flash_kernel<<<dim3(SEQ / 64, NHEADS, BATCH), 256, flash_smem>>>(qkv, mb, cxH, cxL);

        gemm_mma<<<gD, 256, GSMEM>>>(cxH, cxL, wtH + oo, wtL + oo, tmp, nullptr, nullptr,
                                     DMODEL, DMODEL, Wo_b + (size_t)i * DMODEL, h, 0);
        layernorm_kernel<<<BL, 256>>>(tmp, ln1_s + (size_t)i * DMODEL, ln1_b + (size_t)i * DMODEL, h, hH, hL);

        gemm_mma<<<gF, 256, GSMEM>>>(hH, hL, wtH + o1, wtL + o1, nullptr, ffH, ffL,
                                     DFF, DMODEL, ff_b1 + (size_t)i * DFF, nullptr, 1);
        gemm_mma<<<gD, 256, GSMEM>>>(ffH, ffL, wtH + o2, wtL + o2, tmp, nullptr, nullptr,
                                     DMODEL, DFF, ff_b2 + (size_t)i * DMODEL, h, 0);
        layernorm_kernel<<<BL, 256>>>(tmp, ln2_s + (size_t)i * DMODEL, ln2_b + (size_t)i * DMODEL, h, hH, hL);
    }

    head_kernel<<<1, 128>>>(h, out_w, out_b, out);
}

// round 11
// speedup vs baseline: 1.8700x; 1.1202x over previous
#include <cuda_runtime.h>
#include <cuda_bf16.h>
#include <math.h>
#include <stdint.h>

// ---------------- dims ----------------
#define BATCH 8
#define SEQ   1024
#define DMODEL 1024
#define NHEADS 16
#define DQKV  64
#define DFF   4096
#define NLAYERS 6
#define BL    (BATCH*SEQ)          // 8192
#define D3    (3*DMODEL)           // 3072

typedef __nv_bfloat16 bf16;

// ---------------- scratch ----------------
__device__ float g_h  [BL*DMODEL];
__device__ float g_tmp[BL*DMODEL];
__device__ float g_pe [SEQ*DMODEL];
__device__ unsigned long long g_mb[BL*(SEQ/64)];

// split activations
__device__ bf16 g_hh  [BL*DMODEL];
__device__ bf16 g_hl  [BL*DMODEL];
__device__ bf16 g_qkvh[BL*D3];
__device__ bf16 g_qkvl[BL*D3];
__device__ bf16 g_cxh [BL*DMODEL];
__device__ bf16 g_cxl [BL*DMODEL];
__device__ bf16 g_ffh [BL*DFF];
__device__ bf16 g_ffl [BL*DFF];

// transposed + split weights (bf16 hi/lo), layout [N][K] K-major
#define WT_TOTAL (72u*1048576u)
__device__ bf16 g_wt_hi[WT_TOTAL];
__device__ bf16 g_wt_lo[WT_TOTAL];

// ================= PTX helpers =================
__device__ __forceinline__ uint32_t smem_u32(const void* p) {
    uint32_t a;
    asm("{ .reg .u64 t; cvta.to.shared.u64 t, %1; cvt.u32.u64 %0, t; }" : "=r"(a) : "l"(p));
    return a;
}
__device__ __forceinline__ void cp16(uint32_t s, const void* g) {
    asm volatile("cp.async.cg.shared.global [%0], [%1], 16;" :: "r"(s), "l"(g));
}
__device__ __forceinline__ void cp_commit() { asm volatile("cp.async.commit_group;"); }
template <int N> __device__ __forceinline__ void cp_wait() {
    asm volatile("cp.async.wait_group %0;" :: "n"(N));
}
__device__ __forceinline__ void ldm4(uint32_t& r0, uint32_t& r1, uint32_t& r2, uint32_t& r3, uint32_t a) {
    asm volatile("ldmatrix.sync.aligned.m8n8.x4.shared.b16 {%0,%1,%2,%3}, [%4];"
        : "=r"(r0), "=r"(r1), "=r"(r2), "=r"(r3) : "r"(a));
}
__device__ __forceinline__ void mma16816(float* c, uint32_t a0, uint32_t a1, uint32_t a2, uint32_t a3,
                                         uint32_t b0, uint32_t b1) {
    asm volatile("mma.sync.aligned.m16n8k16.row.col.f32.bf16.bf16.f32 "
        "{%0,%1,%2,%3}, {%4,%5,%6,%7}, {%8,%9}, {%0,%1,%2,%3};"
        : "+f"(c[0]), "+f"(c[1]), "+f"(c[2]), "+f"(c[3])
        : "r"(a0), "r"(a1), "r"(a2), "r"(a3), "r"(b0), "r"(b1));
}
__device__ __forceinline__ uint32_t pack_split2(float v0, float v1, uint32_t& lo_out) {
    bf16 h0 = __float2bfloat16(v0);
    bf16 h1 = __float2bfloat16(v1);
    bf16 l0 = __float2bfloat16(v0 - __bfloat162float(h0));
    bf16 l1 = __float2bfloat16(v1 - __bfloat162float(h1));
    uint32_t hi = ((uint32_t)*(uint16_t*)&h1 << 16) | *(uint16_t*)&h0;
    lo_out = ((uint32_t)*(uint16_t*)&l1 << 16) | *(uint16_t*)&l0;
    return hi;
}

// ---------------- setup: positional encoding + mask bitwords ----------------
__global__ void setup_kernel(const int* __restrict__ mask, unsigned long long* __restrict__ mb,
                             float* __restrict__ pe) {
    int bid = blockIdx.x;
    if (bid < 4096) {
        int idx = bid * 256 + threadIdx.x;
        int l = idx >> 10;
        int c = idx & 1023;
        double p = (double)(c & ~1) / (double)DMODEL;
        double divisor = pow(10000.0, p);
        double ang = (double)(l + 1) / divisor;
        pe[idx] = (float)((c & 1) ? cos(ang) : sin(ang));
    } else {
        int warp = (((bid - 4096) * 256) + threadIdx.x) >> 5;
        int lane = threadIdx.x & 31;
        const int nwarps = 512 * 256 / 32;
        for (int w = warp; w < BL * (SEQ / 64); w += nwarps) {
            int row = w >> 4;
            int kt  = w & 15;
            size_t base = (size_t)row * SEQ + kt * 64;
            int m0 = mask[base + lane];
            int m1 = mask[base + 32 + lane];
            unsigned lo = __ballot_sync(0xffffffffu, m0 != 0);
            unsigned hi = __ballot_sync(0xffffffffu, m1 != 0);
            if (lane == 0) mb[w] = (unsigned long long)lo | ((unsigned long long)hi << 32);
        }
    }
}

// ---------------- embedding + PE (+ split) ----------------
__global__ void embed_kernel(const int* __restrict__ x, const float* __restrict__ embed,
                             const float* __restrict__ pe, float* __restrict__ h,
                             bf16* __restrict__ Hh, bf16* __restrict__ Hl) {
    int r = blockIdx.x;
    int t = threadIdx.x;
    int l = r & 1023;
    int tok = x[r];
    float4 e  = *(const float4*)(embed + (size_t)tok * DMODEL + t * 4);
    float4 pp = *(const float4*)(pe + (size_t)l * DMODEL + t * 4);
    float4 o;
    o.x = e.x * 32.0f + pp.x;
    o.y = e.y * 32.0f + pp.y;
    o.z = e.z * 32.0f + pp.z;
    o.w = e.w * 32.0f + pp.w;
    *(float4*)(h + (size_t)r * DMODEL + t * 4) = o;
    uint32_t hi0, hi1, lo0, lo1;
    hi0 = pack_split2(o.x, o.y, lo0);
    hi1 = pack_split2(o.z, o.w, lo1);
    uint2 hv = {hi0, hi1}, lv = {lo0, lo1};
    *(uint2*)(Hh + (size_t)r * DMODEL + t * 4) = hv;
    *(uint2*)(Hl + (size_t)r * DMODEL + t * 4) = lv;
}

// ---------------- weight transpose + bf16 split ----------------
__device__ __forceinline__ void tsplit_body(const float* W, bf16* Oh, bf16* Ol,
                                            int K, int N, int mode) {
    __shared__ float tile[32][33];
    int n0 = blockIdx.x * 32, k0 = blockIdx.y * 32;
    int tx = threadIdx.x, ty = threadIdx.y;
#pragma unroll
    for (int i = 0; i < 32; i += 8) {
        int k = k0 + ty + i, n = n0 + tx;
        float v;
        if (mode == 0) v = W[(size_t)k * N + n];
        else v = W[(size_t)(n >> 6) * (K * 64) + (size_t)k * 64 + (n & 63)];
        tile[ty + i][tx] = v;
    }
    __syncthreads();
#pragma unroll
    for (int i = 0; i < 32; i += 8) {
        int n = n0 + ty + i, k = k0 + tx;
        float v = tile[tx][ty + i];
        bf16 hi = __float2bfloat16(v);
        bf16 lo = __float2bfloat16(v - __bfloat162float(hi));
        Oh[(size_t)n * K + k] = hi;
        Ol[(size_t)n * K + k] = lo;
    }
}

__global__ void tsplit_kernel(const float* __restrict__ W, bf16* __restrict__ Oh, bf16* __restrict__ Ol,
                              int K, int N, int mode) {
    tsplit_body(W, Oh, Ol, K, N, mode);
}

#define M1 1048576u
__global__ void tsplit_qkv_kernel(const float* __restrict__ Wq, const float* __restrict__ Wk,
                                  const float* __restrict__ Wv, bf16* __restrict__ Oh,
                                  bf16* __restrict__ Ol) {
    int z = blockIdx.z;
    const float* W = (z == 0) ? Wq : (z == 1) ? Wk : Wv;
    tsplit_body(W, Oh + (size_t)z * M1, Ol + (size_t)z * M1, DMODEL, DMODEL, 1);
}

// ---------------- HMMA GEMM: 128x64 tile, BKC=64, 2-stage cp.async, 2 CTAs/SM ----------------
#define BMT 128
#define BNT 64
#define BKC 64
#define TSTRIDE 72
#define TILEBA (BMT * TSTRIDE * 2)
#define TILEBB (BNT * TSTRIDE * 2)
#define STAGEB (2 * TILEBA + 2 * TILEBB)
#define GSMEM (2 * STAGEB)

__global__ void __launch_bounds__(256, 2)
gemm_mma(const bf16* __restrict__ Ah, const bf16* __restrict__ Al,
         const bf16* __restrict__ Bh, const bf16* __restrict__ Bl,
         float* __restrict__ C, bf16* __restrict__ Oh, bf16* __restrict__ Ol,
         int N, int K,
         const float* __restrict__ bias, const float* __restrict__ res, int relu) {
    extern __shared__ char smem[];
    const uint32_t sbase = smem_u32(smem);
    const int t = threadIdx.x;
    const int wid = t >> 5, lane = t & 31;
    const int wm = wid >> 1, wn = wid & 1;
    const int row0 = blockIdx.y * BMT, col0 = blockIdx.x * BNT;

    const bf16* srcA[2];
    const bf16* srcB[2];
    srcA[0] = Ah + (size_t)row0 * K;
    srcA[1] = Al + (size_t)row0 * K;
    srcB[0] = Bh + (size_t)col0 * K;
    srcB[1] = Bl + (size_t)col0 * K;

    const int nst = K / BKC;
    const int lrow8 = t >> 3, lchunk = t & 7;

    auto load_stage = [&](int kc, int buf) {
        uint32_t sb = sbase + buf * STAGEB;
#pragma unroll
        for (int m = 0; m < 2; ++m) {
            const bf16* g = srcA[m] + (size_t)kc * BKC;
            uint32_t tb = sb + m * TILEBA;
#pragma unroll
            for (int p = 0; p < 4; ++p) {
                int row = lrow8 + p * 32;
                cp16(tb + (row * TSTRIDE + lchunk * 8) * 2,
                     g + (size_t)row * K + lchunk * 8);
            }
        }
#pragma unroll
        for (int m = 0; m < 2; ++m) {
            const bf16* g = srcB[m] + (size_t)kc * BKC;
            uint32_t tb = sb + 2 * TILEBA + m * TILEBB;
#pragma unroll
            for (int p = 0; p < 2; ++p) {
                int row = lrow8 + p * 32;
                cp16(tb + (row * TSTRIDE + lchunk * 8) * 2,
                     g + (size_t)row * K + lchunk * 8);
            }
        }
        cp_commit();
    };

    float acc[2][4][4];
#pragma unroll
    for (int i = 0; i < 2; ++i)
#pragma unroll
        for (int j = 0; j < 4; ++j)
#pragma unroll
            for (int r = 0; r < 4; ++r) acc[i][j][r] = 0.f;

    const int lrow = lane & 15;
    const int lcol = (lane >> 4) << 3;

    load_stage(0, 0);

    for (int kc = 0; kc < nst; ++kc) {
        int buf = kc & 1;
        if (kc + 1 < nst) {
            load_stage(kc + 1, buf ^ 1);
            cp_wait<1>();
        } else {
            cp_wait<0>();
        }
        __syncthreads();

        uint32_t sb = sbase + buf * STAGEB;
        uint32_t sAh = sb;
        uint32_t sAl = sb + TILEBA;
        uint32_t sBh = sb + 2 * TILEBA;
        uint32_t sBl = sb + 2 * TILEBA + TILEBB;

#pragma unroll
        for (int ks = 0; ks < 4; ++ks) {
            int kof = ks * 16 + lcol;
            uint32_t ah[2][4], al[2][4];
#pragma unroll
            for (int mi = 0; mi < 2; ++mi) {
                int row = wm * 32 + mi * 16 + lrow;
                uint32_t off = (row * TSTRIDE + kof) * 2;
                ldm4(ah[mi][0], ah[mi][1], ah[mi][2], ah[mi][3], sAh + off);
                ldm4(al[mi][0], al[mi][1], al[mi][2], al[mi][3], sAl + off);
            }
            uint32_t bh[2][4], bl[2][4];
#pragma unroll
            for (int nh = 0; nh < 2; ++nh) {
                int row = wn * 32 + nh * 16 + lrow;
                uint32_t off = (row * TSTRIDE + kof) * 2;
                ldm4(bh[nh][0], bh[nh][1], bh[nh][2], bh[nh][3], sBh + off);
                ldm4(bl[nh][0], bl[nh][1], bl[nh][2], bl[nh][3], sBl + off);
            }
#pragma unroll
            for (int mi = 0; mi < 2; ++mi) {
#pragma unroll
                for (int ni = 0; ni < 4; ++ni) {
                    int nh = ni >> 1, np = ni & 1;
                    uint32_t b0h = bh[nh][np], b1h = bh[nh][np + 2];
                    uint32_t b0l = bl[nh][np], b1l = bl[nh][np + 2];
                    mma16816(acc[mi][ni], ah[mi][0], ah[mi][1], ah[mi][2], ah[mi][3], b0h, b1h);
                    mma16816(acc[mi][ni], ah[mi][0], ah[mi][1], ah[mi][2], ah[mi][3], b0l, b1l);
                    mma16816(acc[mi][ni], al[mi][0], al[mi][1], al[mi][2], al[mi][3], b0h, b1h);
                }
            }
        }
        __syncthreads();
    }

    const int erow = lane >> 2, ecol = (lane & 3) * 2;
#pragma unroll
    for (int mi = 0; mi < 2; ++mi) {
#pragma unroll
        for (int p = 0; p < 2; ++p) {
            int r = row0 + wm * 32 + mi * 16 + p * 8 + erow;
            const float* rrow = res ? res + (size_t)r * N : (const float*)0;
#pragma unroll
            for (int ni = 0; ni < 4; ++ni) {
                int c = col0 + wn * 32 + ni * 8 + ecol;
                float v0 = acc[mi][ni][p * 2 + 0];
                float v1 = acc[mi][ni][p * 2 + 1];
                if (bias) { v0 += bias[c]; v1 += bias[c + 1]; }
                if (rrow) {
                    float2 rv = *(const float2*)(rrow + c);
                    v0 += rv.x; v1 += rv.y;
                }
                if (relu) { v0 = fmaxf(v0, 0.f); v1 = fmaxf(v1, 0.f); }
                if (C) {
                    float2 o = {v0, v1};
                    *(float2*)(C + (size_t)r * N + c) = o;
                }
                if (Oh) {
                    uint32_t lo, hi = pack_split2(v0, v1, lo);
                    *(uint32_t*)(Oh + (size_t)r * N + c) = hi;
                    *(uint32_t*)(Ol + (size_t)r * N + c) = lo;
                }
            }
        }
    }
}

// ---------------- tensorized flash attention ----------------
// QKV in split bf16 [BL][3072] (hi/lo). 64x64 tiles, 8 warps (4x2),
// warp tile 16x32. S and PV via 3-term bf16 MMA, online softmax in smem.
#define FTST 72
#define FT_TILE (64 * FTST * 2)            // 9216 B
#define F_QH 0
#define F_QL (F_QH + FT_TILE)
#define F_KH (F_QL + FT_TILE)
#define F_KL (F_KH + FT_TILE)
#define F_VTH (F_KL + FT_TILE)
#define F_VTL (F_VTH + FT_TILE)
#define F_PH (F_VTL + FT_TILE)
#define F_PL (F_PH + FT_TILE)
#define F_SS (F_PL + FT_TILE)              // 64*65 floats = 16640 B
#define F_ROWM (F_SS + 64*65*4)
#define F_ROWL (F_ROWM + 256)
#define F_ROWA (F_ROWL + 256)
#define FLASH_SMEM (F_ROWA + 256 + 64)

__global__ void __launch_bounds__(256, 2)
flash_kernel(const bf16* __restrict__ qkvh, const bf16* __restrict__ qkvl,
             const unsigned long long* __restrict__ mb,
             bf16* __restrict__ cxh, bf16* __restrict__ cxl) {
    extern __shared__ char smem[];
    const uint32_t sbase = smem_u32(smem);
    float* Ss   = (float*)(smem + F_SS);
    float* rowM = (float*)(smem + F_ROWM);
    float* rowL = (float*)(smem + F_ROWL);
    float* rowA = (float*)(smem + F_ROWA);
    bf16* Ph = (bf16*)(smem + F_PH);
    bf16* Pl = (bf16*)(smem + F_PL);

    const int b = blockIdx.z, hh = blockIdx.y, qt = blockIdx.x;
    const int t = threadIdx.x;
    const int wid = t >> 5, lane = t & 31;
    const int wm = wid >> 1, wn = wid & 1;      // warp tile: rows wm*16, cols wn*32
    const int rowbase = b * SEQ + qt * 64;
    const int lrow = lane & 15;
    const int lcol = (lane >> 4) << 3;
    const int erow = lane >> 2, ecol = (lane & 3) * 2;

    // load Q tiles (hi/lo), [row][d] stride FTST
    {
        const bf16* qh = qkvh + (size_t)rowbase * D3 + hh * 64;
        const bf16* ql = qkvl + (size_t)rowbase * D3 + hh * 64;
#pragma unroll
        for (int it = 0; it < 2; ++it) {
            int f = t + it * 256;
            int r = f >> 3, ch = (f & 7) * 8;
            *(uint4*)(smem + F_QH + (r * FTST + ch) * 2) = *(const uint4*)(qh + (size_t)r * D3 + ch);
            *(uint4*)(smem + F_QL + (r * FTST + ch) * 2) = *(const uint4*)(ql + (size_t)r * D3 + ch);
        }
    }
    if (t < 64) { rowM[t] = -INFINITY; rowL[t] = 0.f; }

    float oa[4][4];
#pragma unroll
    for (int i = 0; i < 4; ++i)
#pragma unroll
        for (int j = 0; j < 4; ++j) oa[i][j] = 0.f;

    const unsigned long long* mrow = mb + (size_t)rowbase * (SEQ / 64);

    for (int kt = 0; kt < SEQ / 64; ++kt) {
        __syncthreads();
        // load K (hi/lo) [key][d]; V transposed -> Vt [d][key]
        {
            const bf16* kh = qkvh + (size_t)(b * SEQ + kt * 64) * D3 + DMODEL + hh * 64;
            const bf16* kl = qkvl + (size_t)(b * SEQ + kt * 64) * D3 + DMODEL + hh * 64;
            const bf16* vh = qkvh + (size_t)(b * SEQ + kt * 64) * D3 + 2 * DMODEL + hh * 64;
            const bf16* vl = qkvl + (size_t)(b * SEQ + kt * 64) * D3 + 2 * DMODEL + hh * 64;
#pragma unroll
            for (int it = 0; it < 2; ++it) {
                int f = t + it * 256;
                int r = f >> 3, ch = (f & 7) * 8;
                *(uint4*)(smem + F_KH + (r * FTST + ch) * 2) = *(const uint4*)(kh + (size_t)r * D3 + ch);
                *(uint4*)(smem + F_KL + (r * FTST + ch) * 2) = *(const uint4*)(kl + (size_t)r * D3 + ch);
                uint4 v4h = *(const uint4*)(vh + (size_t)r * D3 + ch);
                uint4 v4l = *(const uint4*)(vl + (size_t)r * D3 + ch);
                const uint16_t* eh = (const uint16_t*)&v4h;
                const uint16_t* el = (const uint16_t*)&v4l;
#pragma unroll
                for (int e = 0; e < 8; ++e) {
                    int d = ch + e;
                    *(uint16_t*)(smem + F_VTH + (d * FTST + r) * 2) = eh[e];
                    *(uint16_t*)(smem + F_VTL + (d * FTST + r) * 2) = el[e];
                }
            }
        }
        __syncthreads();

        // S = Q K^T (3-term)
        float sc[4][4];
#pragma unroll
        for (int i = 0; i < 4; ++i)
#pragma unroll
            for (int j = 0; j < 4; ++j) sc[i][j] = 0.f;
#pragma unroll
        for (int ks = 0; ks < 4; ++ks) {
            int kof = ks * 16 + lcol;
            uint32_t ah[4], al[4];
            {
                int row = wm * 16 + lrow;
                uint32_t off = (row * FTST + kof) * 2;
                ldm4(ah[0], ah[1], ah[2], ah[3], sbase + F_QH + off);
                ldm4(al[0], al[1], al[2], al[3], sbase + F_QL + off);
            }
            uint32_t bh[2][4], bl[2][4];
#pragma unroll
            for (int nh = 0; nh < 2; ++nh) {
                int row = wn * 32 + nh * 16 + lrow;
                uint32_t off = (row * FTST + kof) * 2;
                ldm4(bh[nh][0], bh[nh][1], bh[nh][2], bh[nh][3], sbase + F_KH + off);
                ldm4(bl[nh][0], bl[nh][1], bl[nh][2], bl[nh][3], sbase + F_KL + off);
            }
#pragma unroll
            for (int ni = 0; ni < 4; ++ni) {
                int nh = ni >> 1, np = ni & 1;
                uint32_t b0h = bh[nh][np], b1h = bh[nh][np + 2];
                uint32_t b0l = bl[nh][np], b1l = bl[nh][np + 2];
                mma16816(sc[ni], ah[0], ah[1], ah[2], ah[3], b0h, b1h);
                mma16816(sc[ni], ah[0], ah[1], ah[2], ah[3], b0l, b1l);
                mma16816(sc[ni], al[0], al[1], al[2], al[3], b0h, b1h);
            }
        }
        // scale + mask + store to Ss
#pragma unroll
        for (int p = 0; p < 2; ++p) {
            int rl = wm * 16 + p * 8 + erow;
            unsigned long long wbits = mrow[rl * (SEQ / 64) + kt];
#pragma unroll
            for (int ni = 0; ni < 4; ++ni) {
                int c = wn * 32 + ni * 8 + ecol;
                float v0 = sc[ni][p * 2 + 0] * 0.125f;
                float v1 = sc[ni][p * 2 + 1] * 0.125f;
                if (!((wbits >> c) & 1ULL)) v0 = -1e9f;
                if (!((wbits >> (c + 1)) & 1ULL)) v1 = -1e9f;
                Ss[rl * 65 + c] = v0;
                Ss[rl * 65 + c + 1] = v1;
            }
        }
        __syncthreads();

        // online softmax: 4 threads per row; emit split P
        {
            int r = t >> 2, sub = t & 3;
            float* srow = Ss + r * 65 + sub * 16;
            bf16* phrow = Ph + r * FTST + sub * 16;
            bf16* plrow = Pl + r * FTST + sub * 16;
            float mold = rowM[r];
            float mx = mold;
#pragma unroll
            for (int j = 0; j < 16; ++j) mx = fmaxf(mx, srow[j]);
            mx = fmaxf(mx, __shfl_xor_sync(0xffffffffu, mx, 1));
            mx = fmaxf(mx, __shfl_xor_sync(0xffffffffu, mx, 2));
            float sum = 0.f;
#pragma unroll
            for (int j = 0; j < 16; ++j) {
                float p = __expf(srow[j] - mx);
                sum += p;
                bf16 ph = __float2bfloat16(p);
                bf16 pl = __float2bfloat16(p - __bfloat162float(ph));
                phrow[j] = ph;
                plrow[j] = pl;
            }
            sum += __shfl_xor_sync(0xffffffffu, sum, 1);
            sum += __shfl_xor_sync(0xffffffffu, sum, 2);
            if (sub == 0) {
                float alpha = __expf(mold - mx);
                rowL[r] = rowL[r] * alpha + sum;
                rowM[r] = mx;
                rowA[r] = alpha;
            }
        }
        __syncthreads();

        // O = O*alpha + P V (3-term)
        {
            float a0 = rowA[wm * 16 + erow];
            float a1 = rowA[wm * 16 + 8 + erow];
#pragma unroll
            for (int ni = 0; ni < 4; ++ni) {
                oa[ni][0] *= a0; oa[ni][1] *= a0;
                oa[ni][2] *= a1; oa[ni][3] *= a1;
            }
        }
#pragma unroll
        for (int ks = 0; ks < 4; ++ks) {
            int kof = ks * 16 + lcol;
            uint32_t ah[4], al[4];
            {
                int row = wm * 16 + lrow;
                uint32_t off = (row * FTST + kof) * 2;
                ldm4(ah[0], ah[1], ah[2], ah[3], sbase + F_PH + off);
                ldm4(al[0], al[1], al[2], al[3], sbase + F_PL + off);
            }
            uint32_t bh[2][4], bl[2][4];
#pragma unroll
            for (int nh = 0; nh < 2; ++nh) {
                int row = wn * 32 + nh * 16 + lrow;
                uint32_t off = (row * FTST + kof) * 2;
                ldm4(bh[nh][0], bh[nh][1], bh[nh][2], bh[nh][3], sbase + F_VTH + off);
                ldm4(bl[nh][0], bl[nh][1], bl[nh][2], bl[nh][3], sbase + F_VTL + off);
            }
#pragma unroll
            for (int ni = 0; ni < 4; ++ni) {
                int nh = ni >> 1, np = ni & 1;
                uint32_t b0h = bh[nh][np], b1h = bh[nh][np + 2];
                uint32_t b0l = bl[nh][np], b1l = bl[nh][np + 2];
                mma16816(oa[ni], ah[0], ah[1], ah[2], ah[3], b0h, b1h);
                mma16816(oa[ni], ah[0], ah[1], ah[2], ah[3], b0l, b1l);
                mma16816(oa[ni], al[0], al[1], al[2], al[3], b0h, b1h);
            }
        }
    }

    // normalize + write split ctx
#pragma unroll
    for (int p = 0; p < 2; ++p) {
        int rl = wm * 16 + p * 8 + erow;
        float inv = 1.f / rowL[rl];
        int grow = rowbase + rl;
#pragma unroll
        for (int ni = 0; ni < 4; ++ni) {
            int c = wn * 32 + ni * 8 + ecol;
            float v0 = oa[ni][p * 2 + 0] * inv;
            float v1 = oa[ni][p * 2 + 1] * inv;
            uint32_t lo, hi = pack_split2(v0, v1, lo);
            size_t off = (size_t)grow * DMODEL + hh * 64 + c;
            *(uint32_t*)(cxh + off) = hi;
            *(uint32_t*)(cxl + off) = lo;
        }
    }
}

// ---------------- layernorm (+ split out) ----------------
__global__ void layernorm_kernel(const float* __restrict__ X, const float* __restrict__ s,
                                 const float* __restrict__ bvec, float* __restrict__ Y,
                                 bf16* __restrict__ Yh, bf16* __restrict__ Yl) {
    __shared__ float red[256];
    int r = blockIdx.x;
    int t = threadIdx.x;
    float4 v = *(const float4*)(X + (size_t)r * DMODEL + t * 4);
    float ssum = v.x + v.y + v.z + v.w;
    red[t] = ssum;
    __syncthreads();
    for (int off = 128; off > 0; off >>= 1) {
        if (t < off) red[t] += red[t + off];
        __syncthreads();
    }
    float mu = red[0] * (1.f / DMODEL);
    __syncthreads();
    float d0 = v.x - mu, d1 = v.y - mu, d2 = v.z - mu, d3 = v.w - mu;
    red[t] = d0 * d0 + d1 * d1 + d2 * d2 + d3 * d3;
    __syncthreads();
    for (int off = 128; off > 0; off >>= 1) {
        if (t < off) red[t] += red[t + off];
        __syncthreads();
    }
    float var = red[0] * (1.f / DMODEL);
    float rs = rsqrtf(var + 1e-5f);
    float4 sc = *(const float4*)(s + t * 4);
    float4 be = *(const float4*)(bvec + t * 4);
    float4 out;
    out.x = d0 * rs * sc.x + be.x;
    out.y = d1 * rs * sc.y + be.y;
    out.z = d2 * rs * sc.z + be.z;
    out.w = d3 * rs * sc.w + be.w;
    *(float4*)(Y + (size_t)r * DMODEL + t * 4) = out;
    uint32_t lo0, lo1;
    uint32_t hi0 = pack_split2(out.x, out.y, lo0);
    uint32_t hi1 = pack_split2(out.z, out.w, lo1);
    uint2 hv = {hi0, hi1}, lv = {lo0, lo1};
    *(uint2*)(Yh + (size_t)r * DMODEL + t * 4) = hv;
    *(uint2*)(Yl + (size_t)r * DMODEL + t * 4) = lv;
}

// ---------------- output head ----------------
__global__ void head_kernel(const float* __restrict__ h, const float* __restrict__ ow,
                            const float* __restrict__ ob, float* __restrict__ out) {
    int t = threadIdx.x;
    int b = t >> 4, a = t & 15;
    const float* hrow = h + (size_t)(b * SEQ + (SEQ - 1)) * DMODEL;
    float acc = 0.f;
    for (int m = 0; m < DMODEL; ++m) acc = fmaf(hrow[m], ow[m * 16 + a], acc);
    acc += ob[a];
    float mx = acc;
    for (int off = 8; off > 0; off >>= 1)
        mx = fmaxf(mx, __shfl_xor_sync(0xffffffffu, mx, off));
    float e = expf(acc - mx);
    float sum = e;
    for (int off = 8; off > 0; off >>= 1)
        sum += __shfl_xor_sync(0xffffffffu, sum, off);
    out[b * 16 + a] = acc - mx - logf(sum);
}

// ---------------- launch ----------------
extern "C" void kernel_launch(void* const* d_in, const int* in_sizes, int n_in,
                              void* d_out, int out_size) {
    const int*   x     = (const int*)d_in[0];
    const int*   mask  = (const int*)d_in[1];
    const float* embed = (const float*)d_in[2];
    const float* Wq    = (const float*)d_in[3];
    const float* Wk    = (const float*)d_in[4];
    const float* Wv    = (const float*)d_in[5];
    const float* Wo_w  = (const float*)d_in[6];
    const float* Wo_b  = (const float*)d_in[7];
    const float* ln1_s = (const float*)d_in[8];
    const float* ln1_b = (const float*)d_in[9];
    const float* ff_w1 = (const float*)d_in[10];
    const float* ff_b1 = (const float*)d_in[11];
    const float* ff_w2 = (const float*)d_in[12];
    const float* ff_b2 = (const float*)d_in[13];
    const float* ln2_s = (const float*)d_in[14];
    const float* ln2_b = (const float*)d_in[15];
    const float* out_w = (const float*)d_in[16];
    const float* out_b = (const float*)d_in[17];
    float* out = (float*)d_out;

    float *h, *tmp, *pe;
    unsigned long long* mb;
    bf16 *wtH, *wtL, *hH, *hL, *qvH, *qvL, *cxH, *cxL, *ffH, *ffL;
    cudaGetSymbolAddress((void**)&h,   g_h);
    cudaGetSymbolAddress((void**)&tmp, g_tmp);
    cudaGetSymbolAddress((void**)&pe,  g_pe);
    cudaGetSymbolAddress((void**)&mb,  g_mb);
    cudaGetSymbolAddress((void**)&wtH, g_wt_hi);
    cudaGetSymbolAddress((void**)&wtL, g_wt_lo);
    cudaGetSymbolAddress((void**)&hH,  g_hh);
    cudaGetSymbolAddress((void**)&hL,  g_hl);
    cudaGetSymbolAddress((void**)&qvH, g_qkvh);
    cudaGetSymbolAddress((void**)&qvL, g_qkvl);
    cudaGetSymbolAddress((void**)&cxH, g_cxh);
    cudaGetSymbolAddress((void**)&cxL, g_cxl);
    cudaGetSymbolAddress((void**)&ffH, g_ffh);
    cudaGetSymbolAddress((void**)&ffL, g_ffl);

    cudaFuncSetAttribute(flash_kernel, cudaFuncAttributeMaxDynamicSharedMemorySize, FLASH_SMEM);
    cudaFuncSetAttribute(gemm_mma, cudaFuncAttributeMaxDynamicSharedMemorySize, GSMEM);

    dim3 tb(32, 8);
    dim3 gQKV(D3 / BNT, BL / BMT);   // (48, 64)
    dim3 gD(DMODEL / BNT, BL / BMT); // (16, 64)
    dim3 gF(DFF / BNT, BL / BMT);    // (64, 64)

    setup_kernel<<<4096 + 512, 256>>>(mask, mb, pe);                    // 0
    embed_kernel<<<BL, 256>>>(x, embed, pe, h, hH, hL);                 // 1

    for (int i = 0; i < NLAYERS; ++i) {
        size_t oq = (size_t)i * 3 * M1;
        size_t oo = 18 * (size_t)M1 + (size_t)i * M1;
        size_t o1 = 24 * (size_t)M1 + (size_t)i * 4 * M1;
        size_t o2 = 48 * (size_t)M1 + (size_t)i * 4 * M1;

        tsplit_qkv_kernel<<<dim3(32, 32, 3), tb>>>(
            Wq + (size_t)i * NHEADS * DMODEL * DQKV,
            Wk + (size_t)i * NHEADS * DMODEL * DQKV,
            Wv + (size_t)i * NHEADS * DMODEL * DQKV,
            wtH + oq, wtL + oq);                                        // 2 (layer 0)

        // fused QKV -> split bf16 only                                 // 3 (layer 0, profiled)
        gemm_mma<<<gQKV, 256, GSMEM>>>(hH, hL, wtH + oq, wtL + oq, nullptr, qvH, qvL,
                                       D3, DMODEL, nullptr, nullptr, 0);

        tsplit_kernel<<<dim3(32, 32), tb>>>(Wo_w + (size_t)i * DMODEL * DMODEL,
                                            wtH + oo, wtL + oo, DMODEL, DMODEL, 0);
        tsplit_kernel<<<dim3(128, 32), tb>>>(ff_w1 + (size_t)i * DMODEL * DFF,
                                             wtH + o1, wtL + o1, DMODEL, DFF, 0);
        tsplit_kernel<<<dim3(32, 128), tb>>>(ff_w2 + (size_t)i * DFF * DMODEL,
                                             wtH + o2, wtL + o2, DFF, DMODEL, 0);

        flash_kernel<<<dim3(SEQ / 64, NHEADS, BATCH), 256, FLASH_SMEM>>>(qvH, qvL, mb, cxH, cxL);

        gemm_mma<<<gD, 256, GSMEM>>>(cxH, cxL, wtH + oo, wtL + oo, tmp, nullptr, nullptr,
                                     DMODEL, DMODEL, Wo_b + (size_t)i * DMODEL, h, 0);
        layernorm_kernel<<<BL, 256>>>(tmp, ln1_s + (size_t)i * DMODEL, ln1_b + (size_t)i * DMODEL, h, hH, hL);

        gemm_mma<<<gF, 256, GSMEM>>>(hH, hL, wtH + o1, wtL + o1, nullptr, ffH, ffL,
                                     DFF, DMODEL, ff_b1 + (size_t)i * DFF, nullptr, 1);
        gemm_mma<<<gD, 256, GSMEM>>>(ffH, ffL, wtH + o2, wtL + o2, tmp, nullptr, nullptr,
                                     DMODEL, DFF, ff_b2 + (size_t)i * DMODEL, h, 0);
        layernorm_kernel<<<BL, 256>>>(tmp, ln2_s + (size_t)i * DMODEL, ln2_b + (size_t)i * DMODEL, h, hH, hL);
    }

    head_kernel<<<1, 128>>>(h, out_w, out_b, out);
}

// round 12
// speedup vs baseline: 2.3880x; 1.2770x over previous
#include <cuda_runtime.h>
#include <cuda_fp16.h>
#include <math.h>
#include <stdint.h>

// ---------------- dims ----------------
#define BATCH 8
#define SEQ   1024
#define DMODEL 1024
#define NHEADS 16
#define DQKV  64
#define DFF   4096
#define NLAYERS 6
#define BL    (BATCH*SEQ)          // 8192
#define D3    (3*DMODEL)           // 3072

typedef __half hf;

// ---------------- scratch ----------------
__device__ float g_h  [BL*DMODEL];
__device__ float g_tmp[BL*DMODEL];
__device__ float g_pe [SEQ*DMODEL];
__device__ unsigned long long g_mb[BL*(SEQ/64)];

// split activations (fp16 hi/lo)
__device__ hf g_hh  [BL*DMODEL];
__device__ hf g_hl  [BL*DMODEL];
__device__ hf g_qkvh[BL*D3];
__device__ hf g_qkvl[BL*D3];
__device__ hf g_cxh [BL*DMODEL];
__device__ hf g_cxl [BL*DMODEL];
__device__ hf g_ffh [BL*DFF];
__device__ hf g_ffl [BL*DFF];

// transposed weights (single fp16), layout [N][K] K-major
#define WT_TOTAL (72u*1048576u)
__device__ hf g_wt[WT_TOTAL];

// ================= PTX helpers =================
__device__ __forceinline__ uint32_t smem_u32(const void* p) {
    uint32_t a;
    asm("{ .reg .u64 t; cvta.to.shared.u64 t, %1; cvt.u32.u64 %0, t; }" : "=r"(a) : "l"(p));
    return a;
}
__device__ __forceinline__ void cp16(uint32_t s, const void* g) {
    asm volatile("cp.async.cg.shared.global [%0], [%1], 16;" :: "r"(s), "l"(g));
}
__device__ __forceinline__ void cp_commit() { asm volatile("cp.async.commit_group;"); }
template <int N> __device__ __forceinline__ void cp_wait() {
    asm volatile("cp.async.wait_group %0;" :: "n"(N));
}
__device__ __forceinline__ void ldm4(uint32_t& r0, uint32_t& r1, uint32_t& r2, uint32_t& r3, uint32_t a) {
    asm volatile("ldmatrix.sync.aligned.m8n8.x4.shared.b16 {%0,%1,%2,%3}, [%4];"
        : "=r"(r0), "=r"(r1), "=r"(r2), "=r"(r3) : "r"(a));
}
__device__ __forceinline__ void mma16816(float* c, uint32_t a0, uint32_t a1, uint32_t a2, uint32_t a3,
                                         uint32_t b0, uint32_t b1) {
    asm volatile("mma.sync.aligned.m16n8k16.row.col.f32.f16.f16.f32 "
        "{%0,%1,%2,%3}, {%4,%5,%6,%7}, {%8,%9}, {%0,%1,%2,%3};"
        : "+f"(c[0]), "+f"(c[1]), "+f"(c[2]), "+f"(c[3])
        : "r"(a0), "r"(a1), "r"(a2), "r"(a3), "r"(b0), "r"(b1));
}
__device__ __forceinline__ uint32_t pack_split2h(float v0, float v1, uint32_t& lo_out) {
    hf h0 = __float2half_rn(v0);
    hf h1 = __float2half_rn(v1);
    hf l0 = __float2half_rn(v0 - __half2float(h0));
    hf l1 = __float2half_rn(v1 - __half2float(h1));
    uint32_t hi = ((uint32_t)__half_as_ushort(h1) << 16) | __half_as_ushort(h0);
    lo_out = ((uint32_t)__half_as_ushort(l1) << 16) | __half_as_ushort(l0);
    return hi;
}

// ---------------- setup: positional encoding + mask bitwords ----------------
__global__ void setup_kernel(const int* __restrict__ mask, unsigned long long* __restrict__ mb,
                             float* __restrict__ pe) {
    int bid = blockIdx.x;
    if (bid < 4096) {
        int idx = bid * 256 + threadIdx.x;
        int l = idx >> 10;
        int c = idx & 1023;
        double p = (double)(c & ~1) / (double)DMODEL;
        double divisor = pow(10000.0, p);
        double ang = (double)(l + 1) / divisor;
        pe[idx] = (float)((c & 1) ? cos(ang) : sin(ang));
    } else {
        int warp = (((bid - 4096) * 256) + threadIdx.x) >> 5;
        int lane = threadIdx.x & 31;
        const int nwarps = 512 * 256 / 32;
        for (int w = warp; w < BL * (SEQ / 64); w += nwarps) {
            int row = w >> 4;
            int kt  = w & 15;
            size_t base = (size_t)row * SEQ + kt * 64;
            int m0 = mask[base + lane];
            int m1 = mask[base + 32 + lane];
            unsigned lo = __ballot_sync(0xffffffffu, m0 != 0);
            unsigned hi = __ballot_sync(0xffffffffu, m1 != 0);
            if (lane == 0) mb[w] = (unsigned long long)lo | ((unsigned long long)hi << 32);
        }
    }
}

// ---------------- embedding + PE (+ split) ----------------
__global__ void embed_kernel(const int* __restrict__ x, const float* __restrict__ embed,
                             const float* __restrict__ pe, float* __restrict__ h,
                             hf* __restrict__ Hh, hf* __restrict__ Hl) {
    int r = blockIdx.x;
    int t = threadIdx.x;
    int l = r & 1023;
    int tok = x[r];
    float4 e  = *(const float4*)(embed + (size_t)tok * DMODEL + t * 4);
    float4 pp = *(const float4*)(pe + (size_t)l * DMODEL + t * 4);
    float4 o;
    o.x = e.x * 32.0f + pp.x;
    o.y = e.y * 32.0f + pp.y;
    o.z = e.z * 32.0f + pp.z;
    o.w = e.w * 32.0f + pp.w;
    *(float4*)(h + (size_t)r * DMODEL + t * 4) = o;
    uint32_t hi0, hi1, lo0, lo1;
    hi0 = pack_split2h(o.x, o.y, lo0);
    hi1 = pack_split2h(o.z, o.w, lo1);
    uint2 hv = {hi0, hi1}, lv = {lo0, lo1};
    *(uint2*)(Hh + (size_t)r * DMODEL + t * 4) = hv;
    *(uint2*)(Hl + (size_t)r * DMODEL + t * 4) = lv;
}

// ---------------- weight transpose + fp16 round ----------------
__device__ __forceinline__ void tsplit_body(const float* W, hf* O, int K, int N, int mode) {
    __shared__ float tile[32][33];
    int n0 = blockIdx.x * 32, k0 = blockIdx.y * 32;
    int tx = threadIdx.x, ty = threadIdx.y;
#pragma unroll
    for (int i = 0; i < 32; i += 8) {
        int k = k0 + ty + i, n = n0 + tx;
        float v;
        if (mode == 0) v = W[(size_t)k * N + n];
        else v = W[(size_t)(n >> 6) * (K * 64) + (size_t)k * 64 + (n & 63)];
        tile[ty + i][tx] = v;
    }
    __syncthreads();
#pragma unroll
    for (int i = 0; i < 32; i += 8) {
        int n = n0 + ty + i, k = k0 + tx;
        O[(size_t)n * K + k] = __float2half_rn(tile[tx][ty + i]);
    }
}

__global__ void tsplit_kernel(const float* __restrict__ W, hf* __restrict__ O,
                              int K, int N, int mode) {
    tsplit_body(W, O, K, N, mode);
}

#define M1 1048576u
__global__ void tsplit_qkv_kernel(const float* __restrict__ Wq, const float* __restrict__ Wk,
                                  const float* __restrict__ Wv, hf* __restrict__ O) {
    int z = blockIdx.z;
    const float* W = (z == 0) ? Wq : (z == 1) ? Wk : Wv;
    tsplit_body(W, O + (size_t)z * M1, DMODEL, DMODEL, 1);
}

// ---------------- HMMA GEMM: fp16 2-term, 128x64 tile, BKC=64, 2 CTAs/SM ----------------
#define BMT 128
#define BNT 64
#define BKC 64
#define TSTRIDE 72
#define TILEBA (BMT * TSTRIDE * 2)          // 18432 B
#define TILEBB (BNT * TSTRIDE * 2)          // 9216 B
#define STAGEB (2 * TILEBA + TILEBB)        // 46080 B (Ah, Al, B)
#define GSMEM (2 * STAGEB)                  // 92160 B -> 2 CTAs/SM

__global__ void __launch_bounds__(256, 2)
gemm_mma(const hf* __restrict__ Ah, const hf* __restrict__ Al,
         const hf* __restrict__ Bw,
         float* __restrict__ C, hf* __restrict__ Oh, hf* __restrict__ Ol,
         int N, int K,
         const float* __restrict__ bias, const float* __restrict__ res, int relu) {
    extern __shared__ char smem[];
    const uint32_t sbase = smem_u32(smem);
    const int t = threadIdx.x;
    const int wid = t >> 5, lane = t & 31;
    const int wm = wid >> 1, wn = wid & 1;       // 4 x 2 warps, warp tile 32x32
    const int row0 = blockIdx.y * BMT, col0 = blockIdx.x * BNT;

    const hf* srcA[2];
    srcA[0] = Ah + (size_t)row0 * K;
    srcA[1] = Al + (size_t)row0 * K;
    const hf* srcB = Bw + (size_t)col0 * K;

    const int nst = K / BKC;
    const int lrow8 = t >> 3, lchunk = t & 7;

    auto load_stage = [&](int kc, int buf) {
        uint32_t sb = sbase + buf * STAGEB;
#pragma unroll
        for (int m = 0; m < 2; ++m) {
            const hf* g = srcA[m] + (size_t)kc * BKC;
            uint32_t tb = sb + m * TILEBA;
#pragma unroll
            for (int p = 0; p < 4; ++p) {
                int row = lrow8 + p * 32;
                cp16(tb + (row * TSTRIDE + lchunk * 8) * 2,
                     g + (size_t)row * K + lchunk * 8);
            }
        }
        {
            const hf* g = srcB + (size_t)kc * BKC;
            uint32_t tb = sb + 2 * TILEBA;
#pragma unroll
            for (int p = 0; p < 2; ++p) {
                int row = lrow8 + p * 32;
                cp16(tb + (row * TSTRIDE + lchunk * 8) * 2,
                     g + (size_t)row * K + lchunk * 8);
            }
        }
        cp_commit();
    };

    float acc[2][4][4];
#pragma unroll
    for (int i = 0; i < 2; ++i)
#pragma unroll
        for (int j = 0; j < 4; ++j)
#pragma unroll
            for (int r = 0; r < 4; ++r) acc[i][j][r] = 0.f;

    const int lrow = lane & 15;
    const int lcol = (lane >> 4) << 3;

    load_stage(0, 0);

    for (int kc = 0; kc < nst; ++kc) {
        int buf = kc & 1;
        if (kc + 1 < nst) {
            load_stage(kc + 1, buf ^ 1);
            cp_wait<1>();
        } else {
            cp_wait<0>();
        }
        __syncthreads();

        uint32_t sb = sbase + buf * STAGEB;
        uint32_t sAh = sb;
        uint32_t sAl = sb + TILEBA;
        uint32_t sB  = sb + 2 * TILEBA;

#pragma unroll
        for (int ks = 0; ks < 4; ++ks) {
            int kof = ks * 16 + lcol;
            uint32_t ah[2][4], al[2][4];
#pragma unroll
            for (int mi = 0; mi < 2; ++mi) {
                int row = wm * 32 + mi * 16 + lrow;
                uint32_t off = (row * TSTRIDE + kof) * 2;
                ldm4(ah[mi][0], ah[mi][1], ah[mi][2], ah[mi][3], sAh + off);
                ldm4(al[mi][0], al[mi][1], al[mi][2], al[mi][3], sAl + off);
            }
            uint32_t bb[2][4];
#pragma unroll
            for (int nh = 0; nh < 2; ++nh) {
                int row = wn * 32 + nh * 16 + lrow;
                uint32_t off = (row * TSTRIDE + kof) * 2;
                ldm4(bb[nh][0], bb[nh][1], bb[nh][2], bb[nh][3], sB + off);
            }
#pragma unroll
            for (int mi = 0; mi < 2; ++mi) {
#pragma unroll
                for (int ni = 0; ni < 4; ++ni) {
                    int nh = ni >> 1, np = ni & 1;
                    uint32_t b0 = bb[nh][np], b1 = bb[nh][np + 2];
                    mma16816(acc[mi][ni], ah[mi][0], ah[mi][1], ah[mi][2], ah[mi][3], b0, b1);
                    mma16816(acc[mi][ni], al[mi][0], al[mi][1], al[mi][2], al[mi][3], b0, b1);
                }
            }
        }
        __syncthreads();
    }

    const int erow = lane >> 2, ecol = (lane & 3) * 2;
#pragma unroll
    for (int mi = 0; mi < 2; ++mi) {
#pragma unroll
        for (int p = 0; p < 2; ++p) {
            int r = row0 + wm * 32 + mi * 16 + p * 8 + erow;
            const float* rrow = res ? res + (size_t)r * N : (const float*)0;
#pragma unroll
            for (int ni = 0; ni < 4; ++ni) {
                int c = col0 + wn * 32 + ni * 8 + ecol;
                float v0 = acc[mi][ni][p * 2 + 0];
                float v1 = acc[mi][ni][p * 2 + 1];
                if (bias) { v0 += bias[c]; v1 += bias[c + 1]; }
                if (rrow) {
                    float2 rv = *(const float2*)(rrow + c);
                    v0 += rv.x; v1 += rv.y;
                }
                if (relu) { v0 = fmaxf(v0, 0.f); v1 = fmaxf(v1, 0.f); }
                if (C) {
                    float2 o = {v0, v1};
                    *(float2*)(C + (size_t)r * N + c) = o;
                }
                if (Oh) {
                    uint32_t lo, hi = pack_split2h(v0, v1, lo);
                    *(uint32_t*)(Oh + (size_t)r * N + c) = hi;
                    *(uint32_t*)(Ol + (size_t)r * N + c) = lo;
                }
            }
        }
    }
}

// ---------------- tensorized flash attention (fp16 2-term) ----------------
// S = Qh*Kh + Ql*Kh ; PV = P*Vh + P*Vl (P single fp16)
#define FTST 72
#define FT_TILE (64 * FTST * 2)            // 9216 B
#define F_QH 0
#define F_QL (F_QH + FT_TILE)
#define F_KH (F_QL + FT_TILE)
#define F_VTH (F_KH + FT_TILE)
#define F_VTL (F_VTH + FT_TILE)
#define F_P (F_VTL + FT_TILE)
#define F_SS (F_P + FT_TILE)               // 64*65 floats = 16640 B
#define F_ROWM (F_SS + 64*65*4)
#define F_ROWL (F_ROWM + 256)
#define F_ROWA (F_ROWL + 256)
#define FLASH_SMEM (F_ROWA + 256 + 64)

__global__ void __launch_bounds__(256, 2)
flash_kernel(const hf* __restrict__ qkvh, const hf* __restrict__ qkvl,
             const unsigned long long* __restrict__ mb,
             hf* __restrict__ cxh, hf* __restrict__ cxl) {
    extern __shared__ char smem[];
    const uint32_t sbase = smem_u32(smem);
    float* Ss   = (float*)(smem + F_SS);
    float* rowM = (float*)(smem + F_ROWM);
    float* rowL = (float*)(smem + F_ROWL);
    float* rowA = (float*)(smem + F_ROWA);
    hf* Pp = (hf*)(smem + F_P);

    const int b = blockIdx.z, hh = blockIdx.y, qt = blockIdx.x;
    const int t = threadIdx.x;
    const int wid = t >> 5, lane = t & 31;
    const int wm = wid >> 1, wn = wid & 1;
    const int rowbase = b * SEQ + qt * 64;
    const int lrow = lane & 15;
    const int lcol = (lane >> 4) << 3;
    const int erow = lane >> 2, ecol = (lane & 3) * 2;

    // load Q (hi/lo)
    {
        const hf* qh = qkvh + (size_t)rowbase * D3 + hh * 64;
        const hf* ql = qkvl + (size_t)rowbase * D3 + hh * 64;
#pragma unroll
        for (int it = 0; it < 2; ++it) {
            int f = t + it * 256;
            int r = f >> 3, ch = (f & 7) * 8;
            *(uint4*)(smem + F_QH + (r * FTST + ch) * 2) = *(const uint4*)(qh + (size_t)r * D3 + ch);
            *(uint4*)(smem + F_QL + (r * FTST + ch) * 2) = *(const uint4*)(ql + (size_t)r * D3 + ch);
        }
    }
    if (t < 64) { rowM[t] = -INFINITY; rowL[t] = 0.f; }

    float oa[4][4];
#pragma unroll
    for (int i = 0; i < 4; ++i)
#pragma unroll
        for (int j = 0; j < 4; ++j) oa[i][j] = 0.f;

    const unsigned long long* mrow = mb + (size_t)rowbase * (SEQ / 64);

    for (int kt = 0; kt < SEQ / 64; ++kt) {
        __syncthreads();
        // load K (hi) [key][d]; V hi/lo transposed -> Vt [d][key]
        {
            const hf* kh = qkvh + (size_t)(b * SEQ + kt * 64) * D3 + DMODEL + hh * 64;
            const hf* vh = qkvh + (size_t)(b * SEQ + kt * 64) * D3 + 2 * DMODEL + hh * 64;
            const hf* vl = qkvl + (size_t)(b * SEQ + kt * 64) * D3 + 2 * DMODEL + hh * 64;
#pragma unroll
            for (int it = 0; it < 2; ++it) {
                int f = t + it * 256;
                int r = f >> 3, ch = (f & 7) * 8;
                *(uint4*)(smem + F_KH + (r * FTST + ch) * 2) = *(const uint4*)(kh + (size_t)r * D3 + ch);
                uint4 v4h = *(const uint4*)(vh + (size_t)r * D3 + ch);
                uint4 v4l = *(const uint4*)(vl + (size_t)r * D3 + ch);
                const uint16_t* eh = (const uint16_t*)&v4h;
                const uint16_t* el = (const uint16_t*)&v4l;
#pragma unroll
                for (int e = 0; e < 8; ++e) {
                    int d = ch + e;
                    *(uint16_t*)(smem + F_VTH + (d * FTST + r) * 2) = eh[e];
                    *(uint16_t*)(smem + F_VTL + (d * FTST + r) * 2) = el[e];
                }
            }
        }
        __syncthreads();

        // S = Q K^T (2-term)
        float sc[4][4];
#pragma unroll
        for (int i = 0; i < 4; ++i)
#pragma unroll
            for (int j = 0; j < 4; ++j) sc[i][j] = 0.f;
#pragma unroll
        for (int ks = 0; ks < 4; ++ks) {
            int kof = ks * 16 + lcol;
            uint32_t ah[4], al[4];
            {
                int row = wm * 16 + lrow;
                uint32_t off = (row * FTST + kof) * 2;
                ldm4(ah[0], ah[1], ah[2], ah[3], sbase + F_QH + off);
                ldm4(al[0], al[1], al[2], al[3], sbase + F_QL + off);
            }
            uint32_t bb[2][4];
#pragma unroll
            for (int nh = 0; nh < 2; ++nh) {
                int row = wn * 32 + nh * 16 + lrow;
                uint32_t off = (row * FTST + kof) * 2;
                ldm4(bb[nh][0], bb[nh][1], bb[nh][2], bb[nh][3], sbase + F_KH + off);
            }
#pragma unroll
            for (int ni = 0; ni < 4; ++ni) {
                int nh = ni >> 1, np = ni & 1;
                uint32_t b0 = bb[nh][np], b1 = bb[nh][np + 2];
                mma16816(sc[ni], ah[0], ah[1], ah[2], ah[3], b0, b1);
                mma16816(sc[ni], al[0], al[1], al[2], al[3], b0, b1);
            }
        }
        // scale + mask + store to Ss
#pragma unroll
        for (int p = 0; p < 2; ++p) {
            int rl = wm * 16 + p * 8 + erow;
            unsigned long long wbits = mrow[rl * (SEQ / 64) + kt];
#pragma unroll
            for (int ni = 0; ni < 4; ++ni) {
                int c = wn * 32 + ni * 8 + ecol;
                float v0 = sc[ni][p * 2 + 0] * 0.125f;
                float v1 = sc[ni][p * 2 + 1] * 0.125f;
                if (!((wbits >> c) & 1ULL)) v0 = -1e9f;
                if (!((wbits >> (c + 1)) & 1ULL)) v1 = -1e9f;
                Ss[rl * 65 + c] = v0;
                Ss[rl * 65 + c + 1] = v1;
            }
        }
        __syncthreads();

        // online softmax: 4 threads per row; emit P (single fp16)
        {
            int r = t >> 2, sub = t & 3;
            float* srow = Ss + r * 65 + sub * 16;
            hf* prow = Pp + r * FTST + sub * 16;
            float mold = rowM[r];
            float mx = mold;
#pragma unroll
            for (int j = 0; j < 16; ++j) mx = fmaxf(mx, srow[j]);
            mx = fmaxf(mx, __shfl_xor_sync(0xffffffffu, mx, 1));
            mx = fmaxf(mx, __shfl_xor_sync(0xffffffffu, mx, 2));
            float sum = 0.f;
#pragma unroll
            for (int j = 0; j < 16; ++j) {
                float p = __expf(srow[j] - mx);
                sum += p;
                prow[j] = __float2half_rn(p);
            }
            sum += __shfl_xor_sync(0xffffffffu, sum, 1);
            sum += __shfl_xor_sync(0xffffffffu, sum, 2);
            if (sub == 0) {
                float alpha = __expf(mold - mx);
                rowL[r] = rowL[r] * alpha + sum;
                rowM[r] = mx;
                rowA[r] = alpha;
            }
        }
        __syncthreads();

        // O = O*alpha + P V (2-term: P*Vh + P*Vl)
        {
            float a0 = rowA[wm * 16 + erow];
            float a1 = rowA[wm * 16 + 8 + erow];
#pragma unroll
            for (int ni = 0; ni < 4; ++ni) {
                oa[ni][0] *= a0; oa[ni][1] *= a0;
                oa[ni][2] *= a1; oa[ni][3] *= a1;
            }
        }
#pragma unroll
        for (int ks = 0; ks < 4; ++ks) {
            int kof = ks * 16 + lcol;
            uint32_t ap[4];
            {
                int row = wm * 16 + lrow;
                uint32_t off = (row * FTST + kof) * 2;
                ldm4(ap[0], ap[1], ap[2], ap[3], sbase + F_P + off);
            }
            uint32_t bh[2][4], bl[2][4];
#pragma unroll
            for (int nh = 0; nh < 2; ++nh) {
                int row = wn * 32 + nh * 16 + lrow;
                uint32_t off = (row * FTST + kof) * 2;
                ldm4(bh[nh][0], bh[nh][1], bh[nh][2], bh[nh][3], sbase + F_VTH + off);
                ldm4(bl[nh][0], bl[nh][1], bl[nh][2], bl[nh][3], sbase + F_VTL + off);
            }
#pragma unroll
            for (int ni = 0; ni < 4; ++ni) {
                int nh = ni >> 1, np = ni & 1;
                mma16816(oa[ni], ap[0], ap[1], ap[2], ap[3], bh[nh][np], bh[nh][np + 2]);
                mma16816(oa[ni], ap[0], ap[1], ap[2], ap[3], bl[nh][np], bl[nh][np + 2]);
            }
        }
    }

    // normalize + write split ctx
#pragma unroll
    for (int p = 0; p < 2; ++p) {
        int rl = wm * 16 + p * 8 + erow;
        float inv = 1.f / rowL[rl];
        int grow = rowbase + rl;
#pragma unroll
        for (int ni = 0; ni < 4; ++ni) {
            int c = wn * 32 + ni * 8 + ecol;
            float v0 = oa[ni][p * 2 + 0] * inv;
            float v1 = oa[ni][p * 2 + 1] * inv;
            uint32_t lo, hi = pack_split2h(v0, v1, lo);
            size_t off = (size_t)grow * DMODEL + hh * 64 + c;
            *(uint32_t*)(cxh + off) = hi;
            *(uint32_t*)(cxl + off) = lo;
        }
    }
}

// ---------------- layernorm (+ split out) ----------------
__global__ void layernorm_kernel(const float* __restrict__ X, const float* __restrict__ s,
                                 const float* __restrict__ bvec, float* __restrict__ Y,
                                 hf* __restrict__ Yh, hf* __restrict__ Yl) {
    __shared__ float red[256];
    int r = blockIdx.x;
    int t = threadIdx.x;
    float4 v = *(const float4*)(X + (size_t)r * DMODEL + t * 4);
    float ssum = v.x + v.y + v.z + v.w;
    red[t] = ssum;
    __syncthreads();
    for (int off = 128; off > 0; off >>= 1) {
        if (t < off) red[t] += red[t + off];
        __syncthreads();
    }
    float mu = red[0] * (1.f / DMODEL);
    __syncthreads();
    float d0 = v.x - mu, d1 = v.y - mu, d2 = v.z - mu, d3 = v.w - mu;
    red[t] = d0 * d0 + d1 * d1 + d2 * d2 + d3 * d3;
    __syncthreads();
    for (int off = 128; off > 0; off >>= 1) {
        if (t < off) red[t] += red[t + off];
        __syncthreads();
    }
    float var = red[0] * (1.f / DMODEL);
    float rs = rsqrtf(var + 1e-5f);
    float4 sc = *(const float4*)(s + t * 4);
    float4 be = *(const float4*)(bvec + t * 4);
    float4 out;
    out.x = d0 * rs * sc.x + be.x;
    out.y = d1 * rs * sc.y + be.y;
    out.z = d2 * rs * sc.z + be.z;
    out.w = d3 * rs * sc.w + be.w;
    *(float4*)(Y + (size_t)r * DMODEL + t * 4) = out;
    uint32_t lo0, lo1;
    uint32_t hi0 = pack_split2h(out.x, out.y, lo0);
    uint32_t hi1 = pack_split2h(out.z, out.w, lo1);
    uint2 hv = {hi0, hi1}, lv = {lo0, lo1};
    *(uint2*)(Yh + (size_t)r * DMODEL + t * 4) = hv;
    *(uint2*)(Yl + (size_t)r * DMODEL + t * 4) = lv;
}

// ---------------- output head ----------------
__global__ void head_kernel(const float* __restrict__ h, const float* __restrict__ ow,
                            const float* __restrict__ ob, float* __restrict__ out) {
    int t = threadIdx.x;
    int b = t >> 4, a = t & 15;
    const float* hrow = h + (size_t)(b * SEQ + (SEQ - 1)) * DMODEL;
    float acc = 0.f;
    for (int m = 0; m < DMODEL; ++m) acc = fmaf(hrow[m], ow[m * 16 + a], acc);
    acc += ob[a];
    float mx = acc;
    for (int off = 8; off > 0; off >>= 1)
        mx = fmaxf(mx, __shfl_xor_sync(0xffffffffu, mx, off));
    float e = expf(acc - mx);
    float sum = e;
    for (int off = 8; off > 0; off >>= 1)
        sum += __shfl_xor_sync(0xffffffffu, sum, off);
    out[b * 16 + a] = acc - mx - logf(sum);
}

// ---------------- launch ----------------
extern "C" void kernel_launch(void* const* d_in, const int* in_sizes, int n_in,
                              void* d_out, int out_size) {
    const int*   x     = (const int*)d_in[0];
    const int*   mask  = (const int*)d_in[1];
    const float* embed = (const float*)d_in[2];
    const float* Wq    = (const float*)d_in[3];
    const float* Wk    = (const float*)d_in[4];
    const float* Wv    = (const float*)d_in[5];
    const float* Wo_w  = (const float*)d_in[6];
    const float* Wo_b  = (const float*)d_in[7];
    const float* ln1_s = (const float*)d_in[8];
    const float* ln1_b = (const float*)d_in[9];
    const float* ff_w1 = (const float*)d_in[10];
    const float* ff_b1 = (const float*)d_in[11];
    const float* ff_w2 = (const float*)d_in[12];
    const float* ff_b2 = (const float*)d_in[13];
    const float* ln2_s = (const float*)d_in[14];
    const float* ln2_b = (const float*)d_in[15];
    const float* out_w = (const float*)d_in[16];
    const float* out_b = (const float*)d_in[17];
    float* out = (float*)d_out;

    float *h, *tmp, *pe;
    unsigned long long* mb;
    hf *wt, *hH, *hL, *qvH, *qvL, *cxH, *cxL, *ffH, *ffL;
    cudaGetSymbolAddress((void**)&h,   g_h);
    cudaGetSymbolAddress((void**)&tmp, g_tmp);
    cudaGetSymbolAddress((void**)&pe,  g_pe);
    cudaGetSymbolAddress((void**)&mb,  g_mb);
    cudaGetSymbolAddress((void**)&wt,  g_wt);
    cudaGetSymbolAddress((void**)&hH,  g_hh);
    cudaGetSymbolAddress((void**)&hL,  g_hl);
    cudaGetSymbolAddress((void**)&qvH, g_qkvh);
    cudaGetSymbolAddress((void**)&qvL, g_qkvl);
    cudaGetSymbolAddress((void**)&cxH, g_cxh);
    cudaGetSymbolAddress((void**)&cxL, g_cxl);
    cudaGetSymbolAddress((void**)&ffH, g_ffh);
    cudaGetSymbolAddress((void**)&ffL, g_ffl);

    cudaFuncSetAttribute(flash_kernel, cudaFuncAttributeMaxDynamicSharedMemorySize, FLASH_SMEM);
    cudaFuncSetAttribute(gemm_mma, cudaFuncAttributeMaxDynamicSharedMemorySize, GSMEM);

    dim3 tb(32, 8);
    dim3 gQKV(D3 / BNT, BL / BMT);   // (48, 64)
    dim3 gD(DMODEL / BNT, BL / BMT); // (16, 64)
    dim3 gF(DFF / BNT, BL / BMT);    // (64, 64)

    setup_kernel<<<4096 + 512, 256>>>(mask, mb, pe);                    // 0
    embed_kernel<<<BL, 256>>>(x, embed, pe, h, hH, hL);                 // 1

    for (int i = 0; i < NLAYERS; ++i) {
        size_t oq = (size_t)i * 3 * M1;
        size_t oo = 18 * (size_t)M1 + (size_t)i * M1;
        size_t o1 = 24 * (size_t)M1 + (size_t)i * 4 * M1;
        size_t o2 = 48 * (size_t)M1 + (size_t)i * 4 * M1;

        tsplit_qkv_kernel<<<dim3(32, 32, 3), tb>>>(
            Wq + (size_t)i * NHEADS * DMODEL * DQKV,
            Wk + (size_t)i * NHEADS * DMODEL * DQKV,
            Wv + (size_t)i * NHEADS * DMODEL * DQKV,
            wt + oq);                                                   // 2 (layer 0)

        // fused QKV -> split fp16                                      // 3 (layer 0, profiled)
        gemm_mma<<<gQKV, 256, GSMEM>>>(hH, hL, wt + oq, nullptr, qvH, qvL,
                                       D3, DMODEL, nullptr, nullptr, 0);

        tsplit_kernel<<<dim3(32, 32), tb>>>(Wo_w + (size_t)i * DMODEL * DMODEL,
                                            wt + oo, DMODEL, DMODEL, 0);
        tsplit_kernel<<<dim3(128, 32), tb>>>(ff_w1 + (size_t)i * DMODEL * DFF,
                                             wt + o1, DMODEL, DFF, 0);
        tsplit_kernel<<<dim3(32, 128), tb>>>(ff_w2 + (size_t)i * DFF * DMODEL,
                                             wt + o2, DFF, DMODEL, 0);

        flash_kernel<<<dim3(SEQ / 64, NHEADS, BATCH), 256, FLASH_SMEM>>>(qvH, qvL, mb, cxH, cxL);

        gemm_mma<<<gD, 256, GSMEM>>>(cxH, cxL, wt + oo, tmp, nullptr, nullptr,
                                     DMODEL, DMODEL, Wo_b + (size_t)i * DMODEL, h, 0);
        layernorm_kernel<<<BL, 256>>>(tmp, ln1_s + (size_t)i * DMODEL, ln1_b + (size_t)i * DMODEL, h, hH, hL);

        gemm_mma<<<gF, 256, GSMEM>>>(hH, hL, wt + o1, nullptr, ffH, ffL,
                                     DFF, DMODEL, ff_b1 + (size_t)i * DFF, nullptr, 1);
        gemm_mma<<<gD, 256, GSMEM>>>(ffH, ffL, wt + o2, tmp, nullptr, nullptr,
                                     DMODEL, DFF, ff_b2 + (size_t)i * DMODEL, h, 0);
        layernorm_kernel<<<BL, 256>>>(tmp, ln2_s + (size_t)i * DMODEL, ln2_b + (size_t)i * DMODEL, h, hH, hL);
    }

    head_kernel<<<1, 128>>>(h, out_w, out_b, out);
}

// round 13
// speedup vs baseline: 2.4538x; 1.0276x over previous
#include <cuda_runtime.h>
#include <cuda_fp16.h>
#include <math.h>
#include <stdint.h>

// ---------------- dims ----------------
#define BATCH 8
#define SEQ   1024
#define DMODEL 1024
#define NHEADS 16
#define DQKV  64
#define DFF   4096
#define NLAYERS 6
#define BL    (BATCH*SEQ)          // 8192
#define D3    (3*DMODEL)           // 3072

typedef __half hf;

// ---------------- scratch ----------------
__device__ float g_h  [BL*DMODEL];
__device__ float g_tmp[BL*DMODEL];
__device__ float g_pe [SEQ*DMODEL];
__device__ unsigned long long g_mb[BL*(SEQ/64)];

// split activations (fp16 hi/lo)
__device__ hf g_hh  [BL*DMODEL];
__device__ hf g_hl  [BL*DMODEL];
__device__ hf g_qkvh[BL*D3];
__device__ hf g_qkvl[BL*D3];
__device__ hf g_cxh [BL*DMODEL];
__device__ hf g_cxl [BL*DMODEL];
__device__ hf g_ffh [BL*DFF];
__device__ hf g_ffl [BL*DFF];

// transposed weights (single fp16), layout [N][K] K-major
#define WT_TOTAL (72u*1048576u)
__device__ hf g_wt[WT_TOTAL];

// ================= PTX helpers =================
__device__ __forceinline__ uint32_t smem_u32(const void* p) {
    uint32_t a;
    asm("{ .reg .u64 t; cvta.to.shared.u64 t, %1; cvt.u32.u64 %0, t; }" : "=r"(a) : "l"(p));
    return a;
}
__device__ __forceinline__ void cp16(uint32_t s, const void* g) {
    asm volatile("cp.async.cg.shared.global [%0], [%1], 16;" :: "r"(s), "l"(g));
}
__device__ __forceinline__ void cp_commit() { asm volatile("cp.async.commit_group;"); }
template <int N> __device__ __forceinline__ void cp_wait() {
    asm volatile("cp.async.wait_group %0;" :: "n"(N));
}
__device__ __forceinline__ void ldm4(uint32_t& r0, uint32_t& r1, uint32_t& r2, uint32_t& r3, uint32_t a) {
    asm volatile("ldmatrix.sync.aligned.m8n8.x4.shared.b16 {%0,%1,%2,%3}, [%4];"
        : "=r"(r0), "=r"(r1), "=r"(r2), "=r"(r3) : "r"(a));
}
__device__ __forceinline__ void mma16816(float* c, uint32_t a0, uint32_t a1, uint32_t a2, uint32_t a3,
                                         uint32_t b0, uint32_t b1) {
    asm volatile("mma.sync.aligned.m16n8k16.row.col.f32.f16.f16.f32 "
        "{%0,%1,%2,%3}, {%4,%5,%6,%7}, {%8,%9}, {%0,%1,%2,%3};"
        : "+f"(c[0]), "+f"(c[1]), "+f"(c[2]), "+f"(c[3])
        : "r"(a0), "r"(a1), "r"(a2), "r"(a3), "r"(b0), "r"(b1));
}
__device__ __forceinline__ uint32_t pack_split2h(float v0, float v1, uint32_t& lo_out) {
    hf h0 = __float2half_rn(v0);
    hf h1 = __float2half_rn(v1);
    hf l0 = __float2half_rn(v0 - __half2float(h0));
    hf l1 = __float2half_rn(v1 - __half2float(h1));
    uint32_t hi = ((uint32_t)__half_as_ushort(h1) << 16) | __half_as_ushort(h0);
    lo_out = ((uint32_t)__half_as_ushort(l1) << 16) | __half_as_ushort(l0);
    return hi;
}

// ---------------- setup: positional encoding + mask bitwords ----------------
__global__ void setup_kernel(const int* __restrict__ mask, unsigned long long* __restrict__ mb,
                             float* __restrict__ pe) {
    int bid = blockIdx.x;
    if (bid < 4096) {
        int idx = bid * 256 + threadIdx.x;
        int l = idx >> 10;
        int c = idx & 1023;
        double p = (double)(c & ~1) / (double)DMODEL;
        double divisor = pow(10000.0, p);
        double ang = (double)(l + 1) / divisor;
        pe[idx] = (float)((c & 1) ? cos(ang) : sin(ang));
    } else {
        int warp = (((bid - 4096) * 256) + threadIdx.x) >> 5;
        int lane = threadIdx.x & 31;
        const int nwarps = 512 * 256 / 32;
        for (int w = warp; w < BL * (SEQ / 64); w += nwarps) {
            int row = w >> 4;
            int kt  = w & 15;
            size_t base = (size_t)row * SEQ + kt * 64;
            int m0 = mask[base + lane];
            int m1 = mask[base + 32 + lane];
            unsigned lo = __ballot_sync(0xffffffffu, m0 != 0);
            unsigned hi = __ballot_sync(0xffffffffu, m1 != 0);
            if (lane == 0) mb[w] = (unsigned long long)lo | ((unsigned long long)hi << 32);
        }
    }
}

// ---------------- embedding + PE (+ split) ----------------
__global__ void embed_kernel(const int* __restrict__ x, const float* __restrict__ embed,
                             const float* __restrict__ pe, float* __restrict__ h,
                             hf* __restrict__ Hh, hf* __restrict__ Hl) {
    int r = blockIdx.x;
    int t = threadIdx.x;
    int l = r & 1023;
    int tok = x[r];
    float4 e  = *(const float4*)(embed + (size_t)tok * DMODEL + t * 4);
    float4 pp = *(const float4*)(pe + (size_t)l * DMODEL + t * 4);
    float4 o;
    o.x = e.x * 32.0f + pp.x;
    o.y = e.y * 32.0f + pp.y;
    o.z = e.z * 32.0f + pp.z;
    o.w = e.w * 32.0f + pp.w;
    *(float4*)(h + (size_t)r * DMODEL + t * 4) = o;
    uint32_t hi0, hi1, lo0, lo1;
    hi0 = pack_split2h(o.x, o.y, lo0);
    hi1 = pack_split2h(o.z, o.w, lo1);
    uint2 hv = {hi0, hi1}, lv = {lo0, lo1};
    *(uint2*)(Hh + (size_t)r * DMODEL + t * 4) = hv;
    *(uint2*)(Hl + (size_t)r * DMODEL + t * 4) = lv;
}

// ---------------- weight transpose + fp16 round ----------------
__device__ __forceinline__ void tsplit_body(const float* W, hf* O, int K, int N, int mode) {
    __shared__ float tile[32][33];
    int n0 = blockIdx.x * 32, k0 = blockIdx.y * 32;
    int tx = threadIdx.x, ty = threadIdx.y;
#pragma unroll
    for (int i = 0; i < 32; i += 8) {
        int k = k0 + ty + i, n = n0 + tx;
        float v;
        if (mode == 0) v = W[(size_t)k * N + n];
        else v = W[(size_t)(n >> 6) * (K * 64) + (size_t)k * 64 + (n & 63)];
        tile[ty + i][tx] = v;
    }
    __syncthreads();
#pragma unroll
    for (int i = 0; i < 32; i += 8) {
        int n = n0 + ty + i, k = k0 + tx;
        O[(size_t)n * K + k] = __float2half_rn(tile[tx][ty + i]);
    }
}

__global__ void tsplit_kernel(const float* __restrict__ W, hf* __restrict__ O,
                              int K, int N, int mode) {
    tsplit_body(W, O, K, N, mode);
}

#define M1 1048576u
__global__ void tsplit_qkv_kernel(const float* __restrict__ Wq, const float* __restrict__ Wk,
                                  const float* __restrict__ Wv, hf* __restrict__ O) {
    int z = blockIdx.z;
    const float* W = (z == 0) ? Wq : (z == 1) ? Wk : Wv;
    tsplit_body(W, O + (size_t)z * M1, DMODEL, DMODEL, 1);
}

// ---------------- HMMA GEMM: fp16 2-term, 128x128 tile, BKC=64, 2 CTAs/SM ----------------
#define BMT 128
#define BNT 128
#define BKC 64
#define TSTRIDE 72
#define TILEB (128 * TSTRIDE * 2)           // 18432 B (A tile or B tile)
#define STAGEB (3 * TILEB)                  // Ah, Al, B = 55296 B
#define GSMEM (2 * STAGEB)                  // 110592 B -> 2 CTAs/SM

__global__ void __launch_bounds__(256, 2)
gemm_mma(const hf* __restrict__ Ah, const hf* __restrict__ Al,
         const hf* __restrict__ Bw,
         float* __restrict__ C, hf* __restrict__ Oh, hf* __restrict__ Ol,
         int N, int K,
         const float* __restrict__ bias, const float* __restrict__ res, int relu) {
    extern __shared__ char smem[];
    const uint32_t sbase = smem_u32(smem);
    const int t = threadIdx.x;
    const int wid = t >> 5, lane = t & 31;
    const int wm = wid >> 2, wn = wid & 3;       // 2 x 4 warps, warp tile 64x32
    const int row0 = blockIdx.y * BMT, col0 = blockIdx.x * BNT;

    const hf* srcA[2];
    srcA[0] = Ah + (size_t)row0 * K;
    srcA[1] = Al + (size_t)row0 * K;
    const hf* srcB = Bw + (size_t)col0 * K;

    const int nst = K / BKC;
    const int lrow8 = t >> 3, lchunk = t & 7;

    auto load_stage = [&](int kc, int buf) {
        uint32_t sb = sbase + buf * STAGEB;
#pragma unroll
        for (int m = 0; m < 2; ++m) {
            const hf* g = srcA[m] + (size_t)kc * BKC;
            uint32_t tb = sb + m * TILEB;
#pragma unroll
            for (int p = 0; p < 4; ++p) {
                int row = lrow8 + p * 32;
                cp16(tb + (row * TSTRIDE + lchunk * 8) * 2,
                     g + (size_t)row * K + lchunk * 8);
            }
        }
        {
            const hf* g = srcB + (size_t)kc * BKC;
            uint32_t tb = sb + 2 * TILEB;
#pragma unroll
            for (int p = 0; p < 4; ++p) {
                int row = lrow8 + p * 32;
                cp16(tb + (row * TSTRIDE + lchunk * 8) * 2,
                     g + (size_t)row * K + lchunk * 8);
            }
        }
        cp_commit();
    };

    float acc[4][4][4];
#pragma unroll
    for (int i = 0; i < 4; ++i)
#pragma unroll
        for (int j = 0; j < 4; ++j)
#pragma unroll
            for (int r = 0; r < 4; ++r) acc[i][j][r] = 0.f;

    const int lrow = lane & 15;
    const int lcol = (lane >> 4) << 3;

    load_stage(0, 0);

    for (int kc = 0; kc < nst; ++kc) {
        int buf = kc & 1;
        if (kc + 1 < nst) {
            load_stage(kc + 1, buf ^ 1);
            cp_wait<1>();
        } else {
            cp_wait<0>();
        }
        __syncthreads();

        uint32_t sb = sbase + buf * STAGEB;
        uint32_t sAh = sb;
        uint32_t sAl = sb + TILEB;
        uint32_t sB  = sb + 2 * TILEB;

#pragma unroll
        for (int ks = 0; ks < 4; ++ks) {
            int kof = ks * 16 + lcol;
            uint32_t ah[4][4], al[4][4];
#pragma unroll
            for (int mi = 0; mi < 4; ++mi) {
                int row = wm * 64 + mi * 16 + lrow;
                uint32_t off = (row * TSTRIDE + kof) * 2;
                ldm4(ah[mi][0], ah[mi][1], ah[mi][2], ah[mi][3], sAh + off);
                ldm4(al[mi][0], al[mi][1], al[mi][2], al[mi][3], sAl + off);
            }
            uint32_t bb[2][4];
#pragma unroll
            for (int nh = 0; nh < 2; ++nh) {
                int row = wn * 32 + nh * 16 + lrow;
                uint32_t off = (row * TSTRIDE + kof) * 2;
                ldm4(bb[nh][0], bb[nh][1], bb[nh][2], bb[nh][3], sB + off);
            }
#pragma unroll
            for (int mi = 0; mi < 4; ++mi) {
#pragma unroll
                for (int ni = 0; ni < 4; ++ni) {
                    int nh = ni >> 1, np = ni & 1;
                    uint32_t b0 = bb[nh][np], b1 = bb[nh][np + 2];
                    mma16816(acc[mi][ni], ah[mi][0], ah[mi][1], ah[mi][2], ah[mi][3], b0, b1);
                    mma16816(acc[mi][ni], al[mi][0], al[mi][1], al[mi][2], al[mi][3], b0, b1);
                }
            }
        }
        __syncthreads();
    }

    const int erow = lane >> 2, ecol = (lane & 3) * 2;
#pragma unroll
    for (int mi = 0; mi < 4; ++mi) {
#pragma unroll
        for (int p = 0; p < 2; ++p) {
            int r = row0 + wm * 64 + mi * 16 + p * 8 + erow;
            const float* rrow = res ? res + (size_t)r * N : (const float*)0;
#pragma unroll
            for (int ni = 0; ni < 4; ++ni) {
                int c = col0 + wn * 32 + ni * 8 + ecol;
                float v0 = acc[mi][ni][p * 2 + 0];
                float v1 = acc[mi][ni][p * 2 + 1];
                if (bias) { v0 += bias[c]; v1 += bias[c + 1]; }
                if (rrow) {
                    float2 rv = *(const float2*)(rrow + c);
                    v0 += rv.x; v1 += rv.y;
                }
                if (relu) { v0 = fmaxf(v0, 0.f); v1 = fmaxf(v1, 0.f); }
                if (C) {
                    float2 o = {v0, v1};
                    *(float2*)(C + (size_t)r * N + c) = o;
                }
                if (Oh) {
                    uint32_t lo, hi = pack_split2h(v0, v1, lo);
                    *(uint32_t*)(Oh + (size_t)r * N + c) = hi;
                    *(uint32_t*)(Ol + (size_t)r * N + c) = lo;
                }
            }
        }
    }
}

// ---------------- tensorized flash attention (fp16 2-term) ----------------
#define FTST 72
#define FT_TILE (64 * FTST * 2)            // 9216 B
#define F_QH 0
#define F_QL (F_QH + FT_TILE)
#define F_KH (F_QL + FT_TILE)
#define F_VTH (F_KH + FT_TILE)
#define F_VTL (F_VTH + FT_TILE)
#define F_P (F_VTL + FT_TILE)
#define F_SS (F_P + FT_TILE)               // 64*65 floats
#define F_ROWM (F_SS + 64*65*4)
#define F_ROWL (F_ROWM + 256)
#define F_ROWA (F_ROWL + 256)
#define FLASH_SMEM (F_ROWA + 256 + 64)

__global__ void __launch_bounds__(256, 2)
flash_kernel(const hf* __restrict__ qkvh, const hf* __restrict__ qkvl,
             const unsigned long long* __restrict__ mb,
             hf* __restrict__ cxh, hf* __restrict__ cxl) {
    extern __shared__ char smem[];
    const uint32_t sbase = smem_u32(smem);
    float* Ss   = (float*)(smem + F_SS);
    float* rowM = (float*)(smem + F_ROWM);
    float* rowL = (float*)(smem + F_ROWL);
    float* rowA = (float*)(smem + F_ROWA);
    hf* Pp = (hf*)(smem + F_P);

    const int b = blockIdx.z, hh = blockIdx.y, qt = blockIdx.x;
    const int t = threadIdx.x;
    const int wid = t >> 5, lane = t & 31;
    const int wm = wid >> 1, wn = wid & 1;
    const int rowbase = b * SEQ + qt * 64;
    const int lrow = lane & 15;
    const int lcol = (lane >> 4) << 3;
    const int erow = lane >> 2, ecol = (lane & 3) * 2;

    {
        const hf* qh = qkvh + (size_t)rowbase * D3 + hh * 64;
        const hf* ql = qkvl + (size_t)rowbase * D3 + hh * 64;
#pragma unroll
        for (int it = 0; it < 2; ++it) {
            int f = t + it * 256;
            int r = f >> 3, ch = (f & 7) * 8;
            *(uint4*)(smem + F_QH + (r * FTST + ch) * 2) = *(const uint4*)(qh + (size_t)r * D3 + ch);
            *(uint4*)(smem + F_QL + (r * FTST + ch) * 2) = *(const uint4*)(ql + (size_t)r * D3 + ch);
        }
    }
    if (t < 64) { rowM[t] = -INFINITY; rowL[t] = 0.f; }

    float oa[4][4];
#pragma unroll
    for (int i = 0; i < 4; ++i)
#pragma unroll
        for (int j = 0; j < 4; ++j) oa[i][j] = 0.f;

    const unsigned long long* mrow = mb + (size_t)rowbase * (SEQ / 64);

    for (int kt = 0; kt < SEQ / 64; ++kt) {
        __syncthreads();
        {
            const hf* kh = qkvh + (size_t)(b * SEQ + kt * 64) * D3 + DMODEL + hh * 64;
            const hf* vh = qkvh + (size_t)(b * SEQ + kt * 64) * D3 + 2 * DMODEL + hh * 64;
            const hf* vl = qkvl + (size_t)(b * SEQ + kt * 64) * D3 + 2 * DMODEL + hh * 64;
#pragma unroll
            for (int it = 0; it < 2; ++it) {
                int f = t + it * 256;
                int r = f >> 3, ch = (f & 7) * 8;
                *(uint4*)(smem + F_KH + (r * FTST + ch) * 2) = *(const uint4*)(kh + (size_t)r * D3 + ch);
                uint4 v4h = *(const uint4*)(vh + (size_t)r * D3 + ch);
                uint4 v4l = *(const uint4*)(vl + (size_t)r * D3 + ch);
                const uint16_t* eh = (const uint16_t*)&v4h;
                const uint16_t* el = (const uint16_t*)&v4l;
#pragma unroll
                for (int e = 0; e < 8; ++e) {
                    int d = ch + e;
                    *(uint16_t*)(smem + F_VTH + (d * FTST + r) * 2) = eh[e];
                    *(uint16_t*)(smem + F_VTL + (d * FTST + r) * 2) = el[e];
                }
            }
        }
        __syncthreads();

        float sc[4][4];
#pragma unroll
        for (int i = 0; i < 4; ++i)
#pragma unroll
            for (int j = 0; j < 4; ++j) sc[i][j] = 0.f;
#pragma unroll
        for (int ks = 0; ks < 4; ++ks) {
            int kof = ks * 16 + lcol;
            uint32_t ah[4], al[4];
            {
                int row = wm * 16 + lrow;
                uint32_t off = (row * FTST + kof) * 2;
                ldm4(ah[0], ah[1], ah[2], ah[3], sbase + F_QH + off);
                ldm4(al[0], al[1], al[2], al[3], sbase + F_QL + off);
            }
            uint32_t bb[2][4];
#pragma unroll
            for (int nh = 0; nh < 2; ++nh) {
                int row = wn * 32 + nh * 16 + lrow;
                uint32_t off = (row * FTST + kof) * 2;
                ldm4(bb[nh][0], bb[nh][1], bb[nh][2], bb[nh][3], sbase + F_KH + off);
            }
#pragma unroll
            for (int ni = 0; ni < 4; ++ni) {
                int nh = ni >> 1, np = ni & 1;
                uint32_t b0 = bb[nh][np], b1 = bb[nh][np + 2];
                mma16816(sc[ni], ah[0], ah[1], ah[2], ah[3], b0, b1);
                mma16816(sc[ni], al[0], al[1], al[2], al[3], b0, b1);
            }
        }
#pragma unroll
        for (int p = 0; p < 2; ++p) {
            int rl = wm * 16 + p * 8 + erow;
            unsigned long long wbits = mrow[rl * (SEQ / 64) + kt];
#pragma unroll
            for (int ni = 0; ni < 4; ++ni) {
                int c = wn * 32 + ni * 8 + ecol;
                float v0 = sc[ni][p * 2 + 0] * 0.125f;
                float v1 = sc[ni][p * 2 + 1] * 0.125f;
                if (!((wbits >> c) & 1ULL)) v0 = -1e9f;
                if (!((wbits >> (c + 1)) & 1ULL)) v1 = -1e9f;
                Ss[rl * 65 + c] = v0;
                Ss[rl * 65 + c + 1] = v1;
            }
        }
        __syncthreads();

        {
            int r = t >> 2, sub = t & 3;
            float* srow = Ss + r * 65 + sub * 16;
            hf* prow = Pp + r * FTST + sub * 16;
            float mold = rowM[r];
            float mx = mold;
#pragma unroll
            for (int j = 0; j < 16; ++j) mx = fmaxf(mx, srow[j]);
            mx = fmaxf(mx, __shfl_xor_sync(0xffffffffu, mx, 1));
            mx = fmaxf(mx, __shfl_xor_sync(0xffffffffu, mx, 2));
            float sum = 0.f;
#pragma unroll
            for (int j = 0; j < 16; ++j) {
                float p = __expf(srow[j] - mx);
                sum += p;
                prow[j] = __float2half_rn(p);
            }
            sum += __shfl_xor_sync(0xffffffffu, sum, 1);
            sum += __shfl_xor_sync(0xffffffffu, sum, 2);
            if (sub == 0) {
                float alpha = __expf(mold - mx);
                rowL[r] = rowL[r] * alpha + sum;
                rowM[r] = mx;
                rowA[r] = alpha;
            }
        }
        __syncthreads();

        {
            float a0 = rowA[wm * 16 + erow];
            float a1 = rowA[wm * 16 + 8 + erow];
#pragma unroll
            for (int ni = 0; ni < 4; ++ni) {
                oa[ni][0] *= a0; oa[ni][1] *= a0;
                oa[ni][2] *= a1; oa[ni][3] *= a1;
            }
        }
#pragma unroll
        for (int ks = 0; ks < 4; ++ks) {
            int kof = ks * 16 + lcol;
            uint32_t ap[4];
            {
                int row = wm * 16 + lrow;
                uint32_t off = (row * FTST + kof) * 2;
                ldm4(ap[0], ap[1], ap[2], ap[3], sbase + F_P + off);
            }
            uint32_t bh[2][4], bl[2][4];
#pragma unroll
            for (int nh = 0; nh < 2; ++nh) {
                int row = wn * 32 + nh * 16 + lrow;
                uint32_t off = (row * FTST + kof) * 2;
                ldm4(bh[nh][0], bh[nh][1], bh[nh][2], bh[nh][3], sbase + F_VTH + off);
                ldm4(bl[nh][0], bl[nh][1], bl[nh][2], bl[nh][3], sbase + F_VTL + off);
            }
#pragma unroll
            for (int ni = 0; ni < 4; ++ni) {
                int nh = ni >> 1, np = ni & 1;
                mma16816(oa[ni], ap[0], ap[1], ap[2], ap[3], bh[nh][np], bh[nh][np + 2]);
                mma16816(oa[ni], ap[0], ap[1], ap[2], ap[3], bl[nh][np], bl[nh][np + 2]);
            }
        }
    }

#pragma unroll
    for (int p = 0; p < 2; ++p) {
        int rl = wm * 16 + p * 8 + erow;
        float inv = 1.f / rowL[rl];
        int grow = rowbase + rl;
#pragma unroll
        for (int ni = 0; ni < 4; ++ni) {
            int c = wn * 32 + ni * 8 + ecol;
            float v0 = oa[ni][p * 2 + 0] * inv;
            float v1 = oa[ni][p * 2 + 1] * inv;
            uint32_t lo, hi = pack_split2h(v0, v1, lo);
            size_t off = (size_t)grow * DMODEL + hh * 64 + c;
            *(uint32_t*)(cxh + off) = hi;
            *(uint32_t*)(cxl + off) = lo;
        }
    }
}

// ---------------- layernorm (+ split out) ----------------
__global__ void layernorm_kernel(const float* __restrict__ X, const float* __restrict__ s,
                                 const float* __restrict__ bvec, float* __restrict__ Y,
                                 hf* __restrict__ Yh, hf* __restrict__ Yl) {
    __shared__ float red[256];
    int r = blockIdx.x;
    int t = threadIdx.x;
    float4 v = *(const float4*)(X + (size_t)r * DMODEL + t * 4);
    float ssum = v.x + v.y + v.z + v.w;
    red[t] = ssum;
    __syncthreads();
    for (int off = 128; off > 0; off >>= 1) {
        if (t < off) red[t] += red[t + off];
        __syncthreads();
    }
    float mu = red[0] * (1.f / DMODEL);
    __syncthreads();
    float d0 = v.x - mu, d1 = v.y - mu, d2 = v.z - mu, d3 = v.w - mu;
    red[t] = d0 * d0 + d1 * d1 + d2 * d2 + d3 * d3;
    __syncthreads();
    for (int off = 128; off > 0; off >>= 1) {
        if (t < off) red[t] += red[t + off];
        __syncthreads();
    }
    float var = red[0] * (1.f / DMODEL);
    float rs = rsqrtf(var + 1e-5f);
    float4 sc = *(const float4*)(s + t * 4);
    float4 be = *(const float4*)(bvec + t * 4);
    float4 out;
    out.x = d0 * rs * sc.x + be.x;
    out.y = d1 * rs * sc.y + be.y;
    out.z = d2 * rs * sc.z + be.z;
    out.w = d3 * rs * sc.w + be.w;
    *(float4*)(Y + (size_t)r * DMODEL + t * 4) = out;
    uint32_t lo0, lo1;
    uint32_t hi0 = pack_split2h(out.x, out.y, lo0);
    uint32_t hi1 = pack_split2h(out.z, out.w, lo1);
    uint2 hv = {hi0, hi1}, lv = {lo0, lo1};
    *(uint2*)(Yh + (size_t)r * DMODEL + t * 4) = hv;
    *(uint2*)(Yl + (size_t)r * DMODEL + t * 4) = lv;
}

// ---------------- output head ----------------
__global__ void head_kernel(const float* __restrict__ h, const float* __restrict__ ow,
                            const float* __restrict__ ob, float* __restrict__ out) {
    int t = threadIdx.x;
    int b = t >> 4, a = t & 15;
    const float* hrow = h + (size_t)(b * SEQ + (SEQ - 1)) * DMODEL;
    float acc = 0.f;
    for (int m = 0; m < DMODEL; ++m) acc = fmaf(hrow[m], ow[m * 16 + a], acc);
    acc += ob[a];
    float mx = acc;
    for (int off = 8; off > 0; off >>= 1)
        mx = fmaxf(mx, __shfl_xor_sync(0xffffffffu, mx, off));
    float e = expf(acc - mx);
    float sum = e;
    for (int off = 8; off > 0; off >>= 1)
        sum += __shfl_xor_sync(0xffffffffu, sum, off);
    out[b * 16 + a] = acc - mx - logf(sum);
}

// ---------------- launch ----------------
extern "C" void kernel_launch(void* const* d_in, const int* in_sizes, int n_in,
                              void* d_out, int out_size) {
    const int*   x     = (const int*)d_in[0];
    const int*   mask  = (const int*)d_in[1];
    const float* embed = (const float*)d_in[2];
    const float* Wq    = (const float*)d_in[3];
    const float* Wk    = (const float*)d_in[4];
    const float* Wv    = (const float*)d_in[5];
    const float* Wo_w  = (const float*)d_in[6];
    const float* Wo_b  = (const float*)d_in[7];
    const float* ln1_s = (const float*)d_in[8];
    const float* ln1_b = (const float*)d_in[9];
    const float* ff_w1 = (const float*)d_in[10];
    const float* ff_b1 = (const float*)d_in[11];
    const float* ff_w2 = (const float*)d_in[12];
    const float* ff_b2 = (const float*)d_in[13];
    const float* ln2_s = (const float*)d_in[14];
    const float* ln2_b = (const float*)d_in[15];
    const float* out_w = (const float*)d_in[16];
    const float* out_b = (const float*)d_in[17];
    float* out = (float*)d_out;

    float *h, *tmp, *pe;
    unsigned long long* mb;
    hf *wt, *hH, *hL, *qvH, *qvL, *cxH, *cxL, *ffH, *ffL;
    cudaGetSymbolAddress((void**)&h,   g_h);
    cudaGetSymbolAddress((void**)&tmp, g_tmp);
    cudaGetSymbolAddress((void**)&pe,  g_pe);
    cudaGetSymbolAddress((void**)&mb,  g_mb);
    cudaGetSymbolAddress((void**)&wt,  g_wt);
    cudaGetSymbolAddress((void**)&hH,  g_hh);
    cudaGetSymbolAddress((void**)&hL,  g_hl);
    cudaGetSymbolAddress((void**)&qvH, g_qkvh);
    cudaGetSymbolAddress((void**)&qvL, g_qkvl);
    cudaGetSymbolAddress((void**)&cxH, g_cxh);
    cudaGetSymbolAddress((void**)&cxL, g_cxl);
    cudaGetSymbolAddress((void**)&ffH, g_ffh);
    cudaGetSymbolAddress((void**)&ffL, g_ffl);

    cudaFuncSetAttribute(flash_kernel, cudaFuncAttributeMaxDynamicSharedMemorySize, FLASH_SMEM);
    cudaFuncSetAttribute(gemm_mma, cudaFuncAttributeMaxDynamicSharedMemorySize, GSMEM);

    dim3 tb(32, 8);
    dim3 gQKV(D3 / BNT, BL / BMT);   // (24, 64)
    dim3 gD(DMODEL / BNT, BL / BMT); // (8, 64)
    dim3 gF(DFF / BNT, BL / BMT);    // (32, 64)

    setup_kernel<<<4096 + 512, 256>>>(mask, mb, pe);                    // 0
    embed_kernel<<<BL, 256>>>(x, embed, pe, h, hH, hL);                 // 1

    for (int i = 0; i < NLAYERS; ++i) {
        size_t oq = (size_t)i * 3 * M1;
        size_t oo = 18 * (size_t)M1 + (size_t)i * M1;
        size_t o1 = 24 * (size_t)M1 + (size_t)i * 4 * M1;
        size_t o2 = 48 * (size_t)M1 + (size_t)i * 4 * M1;

        tsplit_qkv_kernel<<<dim3(32, 32, 3), tb>>>(
            Wq + (size_t)i * NHEADS * DMODEL * DQKV,
            Wk + (size_t)i * NHEADS * DMODEL * DQKV,
            Wv + (size_t)i * NHEADS * DMODEL * DQKV,
            wt + oq);                                                   // 2 (layer 0)

        // fused QKV -> split fp16                                      // 3 (layer 0, profiled)
        gemm_mma<<<gQKV, 256, GSMEM>>>(hH, hL, wt + oq, nullptr, qvH, qvL,
                                       D3, DMODEL, nullptr, nullptr, 0);

        tsplit_kernel<<<dim3(32, 32), tb>>>(Wo_w + (size_t)i * DMODEL * DMODEL,
                                            wt + oo, DMODEL, DMODEL, 0);
        tsplit_kernel<<<dim3(128, 32), tb>>>(ff_w1 + (size_t)i * DMODEL * DFF,
                                             wt + o1, DMODEL, DFF, 0);
        tsplit_kernel<<<dim3(32, 128), tb>>>(ff_w2 + (size_t)i * DFF * DMODEL,
                                             wt + o2, DFF, DMODEL, 0);

        flash_kernel<<<dim3(SEQ / 64, NHEADS, BATCH), 256, FLASH_SMEM>>>(qvH, qvL, mb, cxH, cxL);

        gemm_mma<<<gD, 256, GSMEM>>>(cxH, cxL, wt + oo, tmp, nullptr, nullptr,
                                     DMODEL, DMODEL, Wo_b + (size_t)i * DMODEL, h, 0);
        layernorm_kernel<<<BL, 256>>>(tmp, ln1_s + (size_t)i * DMODEL, ln1_b + (size_t)i * DMODEL, h, hH, hL);

        gemm_mma<<<gF, 256, GSMEM>>>(hH, hL, wt + o1, nullptr, ffH, ffL,
                                     DFF, DMODEL, ff_b1 + (size_t)i * DFF, nullptr, 1);
        gemm_mma<<<gD, 256, GSMEM>>>(ffH, ffL, wt + o2, tmp, nullptr, nullptr,
                                     DMODEL, DFF, ff_b2 + (size_t)i * DMODEL, h, 0);
        layernorm_kernel<<<BL, 256>>>(tmp, ln2_s + (size_t)i * DMODEL, ln2_b + (size_t)i * DMODEL, h, hH, hL);
    }

    head_kernel<<<1, 128>>>(h, out_w, out_b, out);
}

// round 14
// speedup vs baseline: 2.6627x; 1.0851x over previous
#include <cuda_runtime.h>
#include <cuda_fp16.h>
#include <math.h>
#include <stdint.h>

// ---------------- dims ----------------
#define BATCH 8
#define SEQ   1024
#define DMODEL 1024
#define NHEADS 16
#define DQKV  64
#define DFF   4096
#define NLAYERS 6
#define BL    (BATCH*SEQ)          // 8192
#define D3    (3*DMODEL)           // 3072

typedef __half hf;

// ---------------- scratch ----------------
__device__ float g_h  [BL*DMODEL];
__device__ float g_tmp[BL*DMODEL];
__device__ float g_pe [SEQ*DMODEL];
__device__ unsigned long long g_mb[BL*(SEQ/64)];

// split activations (fp16 hi/lo)
__device__ hf g_hh  [BL*DMODEL];
__device__ hf g_hl  [BL*DMODEL];
__device__ hf g_qkvh[BL*D3];
__device__ hf g_qkvl[BL*D3];
__device__ hf g_cxh [BL*DMODEL];
__device__ hf g_cxl [BL*DMODEL];
__device__ hf g_ffh [BL*DFF];

// transposed weights (single fp16), layout [N][K] K-major
#define WT_TOTAL (72u*1048576u)
__device__ hf g_wt[WT_TOTAL];

// ================= PTX helpers =================
__device__ __forceinline__ uint32_t smem_u32(const void* p) {
    uint32_t a;
    asm("{ .reg .u64 t; cvta.to.shared.u64 t, %1; cvt.u32.u64 %0, t; }" : "=r"(a) : "l"(p));
    return a;
}
__device__ __forceinline__ void cp16(uint32_t s, const void* g) {
    asm volatile("cp.async.cg.shared.global [%0], [%1], 16;" :: "r"(s), "l"(g));
}
__device__ __forceinline__ void cp_commit() { asm volatile("cp.async.commit_group;"); }
template <int N> __device__ __forceinline__ void cp_wait() {
    asm volatile("cp.async.wait_group %0;" :: "n"(N));
}
__device__ __forceinline__ void ldm4(uint32_t& r0, uint32_t& r1, uint32_t& r2, uint32_t& r3, uint32_t a) {
    asm volatile("ldmatrix.sync.aligned.m8n8.x4.shared.b16 {%0,%1,%2,%3}, [%4];"
        : "=r"(r0), "=r"(r1), "=r"(r2), "=r"(r3) : "r"(a));
}
__device__ __forceinline__ void mma16816(float* c, uint32_t a0, uint32_t a1, uint32_t a2, uint32_t a3,
                                         uint32_t b0, uint32_t b1) {
    asm volatile("mma.sync.aligned.m16n8k16.row.col.f32.f16.f16.f32 "
        "{%0,%1,%2,%3}, {%4,%5,%6,%7}, {%8,%9}, {%0,%1,%2,%3};"
        : "+f"(c[0]), "+f"(c[1]), "+f"(c[2]), "+f"(c[3])
        : "r"(a0), "r"(a1), "r"(a2), "r"(a3), "r"(b0), "r"(b1));
}
__device__ __forceinline__ uint32_t pack_split2h(float v0, float v1, uint32_t& lo_out) {
    hf h0 = __float2half_rn(v0);
    hf h1 = __float2half_rn(v1);
    hf l0 = __float2half_rn(v0 - __half2float(h0));
    hf l1 = __float2half_rn(v1 - __half2float(h1));
    uint32_t hi = ((uint32_t)__half_as_ushort(h1) << 16) | __half_as_ushort(h0);
    lo_out = ((uint32_t)__half_as_ushort(l1) << 16) | __half_as_ushort(l0);
    return hi;
}
__device__ __forceinline__ uint32_t pack2h(float v0, float v1) {
    hf h0 = __float2half_rn(v0);
    hf h1 = __float2half_rn(v1);
    return ((uint32_t)__half_as_ushort(h1) << 16) | __half_as_ushort(h0);
}

// ---------------- setup: positional encoding + mask bitwords ----------------
__global__ void setup_kernel(const int* __restrict__ mask, unsigned long long* __restrict__ mb,
                             float* __restrict__ pe) {
    int bid = blockIdx.x;
    if (bid < 4096) {
        int idx = bid * 256 + threadIdx.x;
        int l = idx >> 10;
        int c = idx & 1023;
        double p = (double)(c & ~1) / (double)DMODEL;
        double divisor = pow(10000.0, p);
        double ang = (double)(l + 1) / divisor;
        pe[idx] = (float)((c & 1) ? cos(ang) : sin(ang));
    } else {
        int warp = (((bid - 4096) * 256) + threadIdx.x) >> 5;
        int lane = threadIdx.x & 31;
        const int nwarps = 512 * 256 / 32;
        for (int w = warp; w < BL * (SEQ / 64); w += nwarps) {
            int row = w >> 4;
            int kt  = w & 15;
            size_t base = (size_t)row * SEQ + kt * 64;
            int m0 = mask[base + lane];
            int m1 = mask[base + 32 + lane];
            unsigned lo = __ballot_sync(0xffffffffu, m0 != 0);
            unsigned hi = __ballot_sync(0xffffffffu, m1 != 0);
            if (lane == 0) mb[w] = (unsigned long long)lo | ((unsigned long long)hi << 32);
        }
    }
}

// ---------------- embedding + PE (+ split) ----------------
__global__ void embed_kernel(const int* __restrict__ x, const float* __restrict__ embed,
                             const float* __restrict__ pe, float* __restrict__ h,
                             hf* __restrict__ Hh, hf* __restrict__ Hl) {
    int r = blockIdx.x;
    int t = threadIdx.x;
    int l = r & 1023;
    int tok = x[r];
    float4 e  = *(const float4*)(embed + (size_t)tok * DMODEL + t * 4);
    float4 pp = *(const float4*)(pe + (size_t)l * DMODEL + t * 4);
    float4 o;
    o.x = e.x * 32.0f + pp.x;
    o.y = e.y * 32.0f + pp.y;
    o.z = e.z * 32.0f + pp.z;
    o.w = e.w * 32.0f + pp.w;
    *(float4*)(h + (size_t)r * DMODEL + t * 4) = o;
    uint32_t hi0, hi1, lo0, lo1;
    hi0 = pack_split2h(o.x, o.y, lo0);
    hi1 = pack_split2h(o.z, o.w, lo1);
    uint2 hv = {hi0, hi1}, lv = {lo0, lo1};
    *(uint2*)(Hh + (size_t)r * DMODEL + t * 4) = hv;
    *(uint2*)(Hl + (size_t)r * DMODEL + t * 4) = lv;
}

// ---------------- weight transpose + fp16 round ----------------
__device__ __forceinline__ void tsplit_body(const float* W, hf* O, int K, int N, int mode) {
    __shared__ float tile[32][33];
    int n0 = blockIdx.x * 32, k0 = blockIdx.y * 32;
    int tx = threadIdx.x, ty = threadIdx.y;
#pragma unroll
    for (int i = 0; i < 32; i += 8) {
        int k = k0 + ty + i, n = n0 + tx;
        float v;
        if (mode == 0) v = W[(size_t)k * N + n];
        else v = W[(size_t)(n >> 6) * (K * 64) + (size_t)k * 64 + (n & 63)];
        tile[ty + i][tx] = v;
    }
    __syncthreads();
#pragma unroll
    for (int i = 0; i < 32; i += 8) {
        int n = n0 + ty + i, k = k0 + tx;
        O[(size_t)n * K + k] = __float2half_rn(tile[tx][ty + i]);
    }
}

__global__ void tsplit_kernel(const float* __restrict__ W, hf* __restrict__ O,
                              int K, int N, int mode) {
    tsplit_body(W, O, K, N, mode);
}

#define M1 1048576u
__global__ void tsplit_qkv_kernel(const float* __restrict__ Wq, const float* __restrict__ Wk,
                                  const float* __restrict__ Wv, hf* __restrict__ O) {
    int z = blockIdx.z;
    const float* W = (z == 0) ? Wq : (z == 1) ? Wk : Wv;
    tsplit_body(W, O + (size_t)z * M1, DMODEL, DMODEL, 1);
}

// ---------------- HMMA GEMM: fp16, 128x128 tile, BKC=64, 2 CTAs/SM ----------------
// at2 = 1: 2-term A split (Ah+Al). at2 = 0: single A (Ah only).
#define BMT 128
#define BNT 128
#define BKC 64
#define TSTRIDE 72
#define TILEB (128 * TSTRIDE * 2)           // 18432 B
#define STAGEB (3 * TILEB)                  // Ah, Al, B = 55296 B
#define GSMEM (2 * STAGEB)                  // 110592 B -> 2 CTAs/SM

__global__ void __launch_bounds__(256, 2)
gemm_mma(const hf* __restrict__ Ah, const hf* __restrict__ Al,
         const hf* __restrict__ Bw,
         float* __restrict__ C, hf* __restrict__ Oh, hf* __restrict__ Ol,
         int N, int K, int at2,
         const float* __restrict__ bias, const float* __restrict__ res, int relu) {
    extern __shared__ char smem[];
    const uint32_t sbase = smem_u32(smem);
    const int t = threadIdx.x;
    const int wid = t >> 5, lane = t & 31;
    const int wm = wid >> 2, wn = wid & 3;       // 2 x 4 warps, warp tile 64x32
    const int row0 = blockIdx.y * BMT, col0 = blockIdx.x * BNT;

    const hf* srcA0 = Ah + (size_t)row0 * K;
    const hf* srcA1 = at2 ? (Al + (size_t)row0 * K) : (const hf*)0;
    const hf* srcB = Bw + (size_t)col0 * K;

    const int nst = K / BKC;
    const int lrow8 = t >> 3, lchunk = t & 7;

    auto load_stage = [&](int kc, int buf) {
        uint32_t sb = sbase + buf * STAGEB;
        {
            const hf* g = srcA0 + (size_t)kc * BKC;
#pragma unroll
            for (int p = 0; p < 4; ++p) {
                int row = lrow8 + p * 32;
                cp16(sb + (row * TSTRIDE + lchunk * 8) * 2,
                     g + (size_t)row * K + lchunk * 8);
            }
        }
        if (srcA1) {
            const hf* g = srcA1 + (size_t)kc * BKC;
            uint32_t tb = sb + TILEB;
#pragma unroll
            for (int p = 0; p < 4; ++p) {
                int row = lrow8 + p * 32;
                cp16(tb + (row * TSTRIDE + lchunk * 8) * 2,
                     g + (size_t)row * K + lchunk * 8);
            }
        }
        {
            const hf* g = srcB + (size_t)kc * BKC;
            uint32_t tb = sb + 2 * TILEB;
#pragma unroll
            for (int p = 0; p < 4; ++p) {
                int row = lrow8 + p * 32;
                cp16(tb + (row * TSTRIDE + lchunk * 8) * 2,
                     g + (size_t)row * K + lchunk * 8);
            }
        }
        cp_commit();
    };

    float acc[4][4][4];
#pragma unroll
    for (int i = 0; i < 4; ++i)
#pragma unroll
        for (int j = 0; j < 4; ++j)
#pragma unroll
            for (int r = 0; r < 4; ++r) acc[i][j][r] = 0.f;

    const int lrow = lane & 15;
    const int lcol = (lane >> 4) << 3;

    load_stage(0, 0);

    for (int kc = 0; kc < nst; ++kc) {
        int buf = kc & 1;
        if (kc + 1 < nst) {
            load_stage(kc + 1, buf ^ 1);
            cp_wait<1>();
        } else {
            cp_wait<0>();
        }
        __syncthreads();

        uint32_t sb = sbase + buf * STAGEB;
        uint32_t sAh = sb;
        uint32_t sAl = sb + TILEB;
        uint32_t sB  = sb + 2 * TILEB;

#pragma unroll
        for (int ks = 0; ks < 4; ++ks) {
            int kof = ks * 16 + lcol;
            uint32_t ah[4][4], al[4][4];
#pragma unroll
            for (int mi = 0; mi < 4; ++mi) {
                int row = wm * 64 + mi * 16 + lrow;
                uint32_t off = (row * TSTRIDE + kof) * 2;
                ldm4(ah[mi][0], ah[mi][1], ah[mi][2], ah[mi][3], sAh + off);
                if (at2) ldm4(al[mi][0], al[mi][1], al[mi][2], al[mi][3], sAl + off);
            }
            uint32_t bb[2][4];
#pragma unroll
            for (int nh = 0; nh < 2; ++nh) {
                int row = wn * 32 + nh * 16 + lrow;
                uint32_t off = (row * TSTRIDE + kof) * 2;
                ldm4(bb[nh][0], bb[nh][1], bb[nh][2], bb[nh][3], sB + off);
            }
#pragma unroll
            for (int mi = 0; mi < 4; ++mi) {
#pragma unroll
                for (int ni = 0; ni < 4; ++ni) {
                    int nh = ni >> 1, np = ni & 1;
                    uint32_t b0 = bb[nh][np], b1 = bb[nh][np + 2];
                    mma16816(acc[mi][ni], ah[mi][0], ah[mi][1], ah[mi][2], ah[mi][3], b0, b1);
                    if (at2) mma16816(acc[mi][ni], al[mi][0], al[mi][1], al[mi][2], al[mi][3], b0, b1);
                }
            }
        }
        __syncthreads();
    }

    const int erow = lane >> 2, ecol = (lane & 3) * 2;
#pragma unroll
    for (int mi = 0; mi < 4; ++mi) {
#pragma unroll
        for (int p = 0; p < 2; ++p) {
            int r = row0 + wm * 64 + mi * 16 + p * 8 + erow;
            const float* rrow = res ? res + (size_t)r * N : (const float*)0;
#pragma unroll
            for (int ni = 0; ni < 4; ++ni) {
                int c = col0 + wn * 32 + ni * 8 + ecol;
                float v0 = acc[mi][ni][p * 2 + 0];
                float v1 = acc[mi][ni][p * 2 + 1];
                if (bias) { v0 += bias[c]; v1 += bias[c + 1]; }
                if (rrow) {
                    float2 rv = *(const float2*)(rrow + c);
                    v0 += rv.x; v1 += rv.y;
                }
                if (relu) { v0 = fmaxf(v0, 0.f); v1 = fmaxf(v1, 0.f); }
                if (C) {
                    float2 o = {v0, v1};
                    *(float2*)(C + (size_t)r * N + c) = o;
                }
                if (Oh) {
                    if (Ol) {
                        uint32_t lo, hi = pack_split2h(v0, v1, lo);
                        *(uint32_t*)(Oh + (size_t)r * N + c) = hi;
                        *(uint32_t*)(Ol + (size_t)r * N + c) = lo;
                    } else {
                        *(uint32_t*)(Oh + (size_t)r * N + c) = pack2h(v0, v1);
                    }
                }
            }
        }
    }
}

// ---------------- tensorized flash attention (fp16 2-term) ----------------
#define FTST 72
#define FT_TILE (64 * FTST * 2)            // 9216 B
#define F_QH 0
#define F_QL (F_QH + FT_TILE)
#define F_KH (F_QL + FT_TILE)
#define F_VTH (F_KH + FT_TILE)
#define F_VTL (F_VTH + FT_TILE)
#define F_P (F_VTL + FT_TILE)
#define F_SS (F_P + FT_TILE)               // 64*65 floats
#define F_ROWM (F_SS + 64*65*4)
#define F_ROWL (F_ROWM + 256)
#define F_ROWA (F_ROWL + 256)
#define FLASH_SMEM (F_ROWA + 256 + 64)

__global__ void __launch_bounds__(256, 2)
flash_kernel(const hf* __restrict__ qkvh, const hf* __restrict__ qkvl,
             const unsigned long long* __restrict__ mb,
             hf* __restrict__ cxh, hf* __restrict__ cxl) {
    extern __shared__ char smem[];
    const uint32_t sbase = smem_u32(smem);
    float* Ss   = (float*)(smem + F_SS);
    float* rowM = (float*)(smem + F_ROWM);
    float* rowL = (float*)(smem + F_ROWL);
    float* rowA = (float*)(smem + F_ROWA);
    hf* Pp = (hf*)(smem + F_P);

    const int b = blockIdx.z, hh = blockIdx.y, qt = blockIdx.x;
    const int t = threadIdx.x;
    const int wid = t >> 5, lane = t & 31;
    const int wm = wid >> 1, wn = wid & 1;
    const int rowbase = b * SEQ + qt * 64;
    const int lrow = lane & 15;
    const int lcol = (lane >> 4) << 3;
    const int erow = lane >> 2, ecol = (lane & 3) * 2;

    {
        const hf* qh = qkvh + (size_t)rowbase * D3 + hh * 64;
        const hf* ql = qkvl + (size_t)rowbase * D3 + hh * 64;
#pragma unroll
        for (int it = 0; it < 2; ++it) {
            int f = t + it * 256;
            int r = f >> 3, ch = (f & 7) * 8;
            *(uint4*)(smem + F_QH + (r * FTST + ch) * 2) = *(const uint4*)(qh + (size_t)r * D3 + ch);
            *(uint4*)(smem + F_QL + (r * FTST + ch) * 2) = *(const uint4*)(ql + (size_t)r * D3 + ch);
        }
    }
    if (t < 64) { rowM[t] = -INFINITY; rowL[t] = 0.f; }

    float oa[4][4];
#pragma unroll
    for (int i = 0; i < 4; ++i)
#pragma unroll
        for (int j = 0; j < 4; ++j) oa[i][j] = 0.f;

    const unsigned long long* mrow = mb + (size_t)rowbase * (SEQ / 64);

    for (int kt = 0; kt < SEQ / 64; ++kt) {
        __syncthreads();
        {
            const hf* kh = qkvh + (size_t)(b * SEQ + kt * 64) * D3 + DMODEL + hh * 64;
            const hf* vh = qkvh + (size_t)(b * SEQ + kt * 64) * D3 + 2 * DMODEL + hh * 64;
            const hf* vl = qkvl + (size_t)(b * SEQ + kt * 64) * D3 + 2 * DMODEL + hh * 64;
#pragma unroll
            for (int it = 0; it < 2; ++it) {
                int f = t + it * 256;
                int r = f >> 3, ch = (f & 7) * 8;
                *(uint4*)(smem + F_KH + (r * FTST + ch) * 2) = *(const uint4*)(kh + (size_t)r * D3 + ch);
                uint4 v4h = *(const uint4*)(vh + (size_t)r * D3 + ch);
                uint4 v4l = *(const uint4*)(vl + (size_t)r * D3 + ch);
                const uint16_t* eh = (const uint16_t*)&v4h;
                const uint16_t* el = (const uint16_t*)&v4l;
#pragma unroll
                for (int e = 0; e < 8; ++e) {
                    int d = ch + e;
                    *(uint16_t*)(smem + F_VTH + (d * FTST + r) * 2) = eh[e];
                    *(uint16_t*)(smem + F_VTL + (d * FTST + r) * 2) = el[e];
                }
            }
        }
        __syncthreads();

        float sc[4][4];
#pragma unroll
        for (int i = 0; i < 4; ++i)
#pragma unroll
            for (int j = 0; j < 4; ++j) sc[i][j] = 0.f;
#pragma unroll
        for (int ks = 0; ks < 4; ++ks) {
            int kof = ks * 16 + lcol;
            uint32_t ah[4], al[4];
            {
                int row = wm * 16 + lrow;
                uint32_t off = (row * FTST + kof) * 2;
                ldm4(ah[0], ah[1], ah[2], ah[3], sbase + F_QH + off);
                ldm4(al[0], al[1], al[2], al[3], sbase + F_QL + off);
            }
            uint32_t bb[2][4];
#pragma unroll
            for (int nh = 0; nh < 2; ++nh) {
                int row = wn * 32 + nh * 16 + lrow;
                uint32_t off = (row * FTST + kof) * 2;
                ldm4(bb[nh][0], bb[nh][1], bb[nh][2], bb[nh][3], sbase + F_KH + off);
            }
#pragma unroll
            for (int ni = 0; ni < 4; ++ni) {
                int nh = ni >> 1, np = ni & 1;
                uint32_t b0 = bb[nh][np], b1 = bb[nh][np + 2];
                mma16816(sc[ni], ah[0], ah[1], ah[2], ah[3], b0, b1);
                mma16816(sc[ni], al[0], al[1], al[2], al[3], b0, b1);
            }
        }
#pragma unroll
        for (int p = 0; p < 2; ++p) {
            int rl = wm * 16 + p * 8 + erow;
            unsigned long long wbits = mrow[rl * (SEQ / 64) + kt];
#pragma unroll
            for (int ni = 0; ni < 4; ++ni) {
                int c = wn * 32 + ni * 8 + ecol;
                float v0 = sc[ni][p * 2 + 0] * 0.125f;
                float v1 = sc[ni][p * 2 + 1] * 0.125f;
                if (!((wbits >> c) & 1ULL)) v0 = -1e9f;
                if (!((wbits >> (c + 1)) & 1ULL)) v1 = -1e9f;
                Ss[rl * 65 + c] = v0;
                Ss[rl * 65 + c + 1] = v1;
            }
        }
        __syncthreads();

        {
            int r = t >> 2, sub = t & 3;
            float* srow = Ss + r * 65 + sub * 16;
            hf* prow = Pp + r * FTST + sub * 16;
            float mold = rowM[r];
            float mx = mold;
#pragma unroll
            for (int j = 0; j < 16; ++j) mx = fmaxf(mx, srow[j]);
            mx = fmaxf(mx, __shfl_xor_sync(0xffffffffu, mx, 1));
            mx = fmaxf(mx, __shfl_xor_sync(0xffffffffu, mx, 2));
            float sum = 0.f;
#pragma unroll
            for (int j = 0; j < 16; ++j) {
                float p = __expf(srow[j] - mx);
                sum += p;
                prow[j] = __float2half_rn(p);
            }
            sum += __shfl_xor_sync(0xffffffffu, sum, 1);
            sum += __shfl_xor_sync(0xffffffffu, sum, 2);
            if (sub == 0) {
                float alpha = __expf(mold - mx);
                rowL[r] = rowL[r] * alpha + sum;
                rowM[r] = mx;
                rowA[r] = alpha;
            }
        }
        __syncthreads();

        {
            float a0 = rowA[wm * 16 + erow];
            float a1 = rowA[wm * 16 + 8 + erow];
#pragma unroll
            for (int ni = 0; ni < 4; ++ni) {
                oa[ni][0] *= a0; oa[ni][1] *= a0;
                oa[ni][2] *= a1; oa[ni][3] *= a1;
            }
        }
#pragma unroll
        for (int ks = 0; ks < 4; ++ks) {
            int kof = ks * 16 + lcol;
            uint32_t ap[4];
            {
                int row = wm * 16 + lrow;
                uint32_t off = (row * FTST + kof) * 2;
                ldm4(ap[0], ap[1], ap[2], ap[3], sbase + F_P + off);
            }
            uint32_t bh[2][4], bl[2][4];
#pragma unroll
            for (int nh = 0; nh < 2; ++nh) {
                int row = wn * 32 + nh * 16 + lrow;
                uint32_t off = (row * FTST + kof) * 2;
                ldm4(bh[nh][0], bh[nh][1], bh[nh][2], bh[nh][3], sbase + F_VTH + off);
                ldm4(bl[nh][0], bl[nh][1], bl[nh][2], bl[nh][3], sbase + F_VTL + off);
            }
#pragma unroll
            for (int ni = 0; ni < 4; ++ni) {
                int nh = ni >> 1, np = ni & 1;
                mma16816(oa[ni], ap[0], ap[1], ap[2], ap[3], bh[nh][np], bh[nh][np + 2]);
                mma16816(oa[ni], ap[0], ap[1], ap[2], ap[3], bl[nh][np], bl[nh][np + 2]);
            }
        }
    }

#pragma unroll
    for (int p = 0; p < 2; ++p) {
        int rl = wm * 16 + p * 8 + erow;
        float inv = 1.f / rowL[rl];
        int grow = rowbase + rl;
#pragma unroll
        for (int ni = 0; ni < 4; ++ni) {
            int c = wn * 32 + ni * 8 + ecol;
            float v0 = oa[ni][p * 2 + 0] * inv;
            float v1 = oa[ni][p * 2 + 1] * inv;
            uint32_t lo, hi = pack_split2h(v0, v1, lo);
            size_t off = (size_t)grow * DMODEL + hh * 64 + c;
            *(uint32_t*)(cxh + off) = hi;
            *(uint32_t*)(cxl + off) = lo;
        }
    }
}

// ---------------- layernorm (+ split out) ----------------
__global__ void layernorm_kernel(const float* __restrict__ X, const float* __restrict__ s,
                                 const float* __restrict__ bvec, float* __restrict__ Y,
                                 hf* __restrict__ Yh, hf* __restrict__ Yl) {
    __shared__ float red[256];
    int r = blockIdx.x;
    int t = threadIdx.x;
    float4 v = *(const float4*)(X + (size_t)r * DMODEL + t * 4);
    float ssum = v.x + v.y + v.z + v.w;
    red[t] = ssum;
    __syncthreads();
    for (int off = 128; off > 0; off >>= 1) {
        if (t < off) red[t] += red[t + off];
        __syncthreads();
    }
    float mu = red[0] * (1.f / DMODEL);
    __syncthreads();
    float d0 = v.x - mu, d1 = v.y - mu, d2 = v.z - mu, d3 = v.w - mu;
    red[t] = d0 * d0 + d1 * d1 + d2 * d2 + d3 * d3;
    __syncthreads();
    for (int off = 128; off > 0; off >>= 1) {
        if (t < off) red[t] += red[t + off];
        __syncthreads();
    }
    float var = red[0] * (1.f / DMODEL);
    float rs = rsqrtf(var + 1e-5f);
    float4 sc = *(const float4*)(s + t * 4);
    float4 be = *(const float4*)(bvec + t * 4);
    float4 out;
    out.x = d0 * rs * sc.x + be.x;
    out.y = d1 * rs * sc.y + be.y;
    out.z = d2 * rs * sc.z + be.z;
    out.w = d3 * rs * sc.w + be.w;
    *(float4*)(Y + (size_t)r * DMODEL + t * 4) = out;
    uint32_t lo0, lo1;
    uint32_t hi0 = pack_split2h(out.x, out.y, lo0);
    uint32_t hi1 = pack_split2h(out.z, out.w, lo1);
    uint2 hv = {hi0, hi1}, lv = {lo0, lo1};
    *(uint2*)(Yh + (size_t)r * DMODEL + t * 4) = hv;
    *(uint2*)(Yl + (size_t)r * DMODEL + t * 4) = lv;
}

// ---------------- output head ----------------
__global__ void head_kernel(const float* __restrict__ h, const float* __restrict__ ow,
                            const float* __restrict__ ob, float* __restrict__ out) {
    int t = threadIdx.x;
    int b = t >> 4, a = t & 15;
    const float* hrow = h + (size_t)(b * SEQ + (SEQ - 1)) * DMODEL;
    float acc = 0.f;
    for (int m = 0; m < DMODEL; ++m) acc = fmaf(hrow[m], ow[m * 16 + a], acc);
    acc += ob[a];
    float mx = acc;
    for (int off = 8; off > 0; off >>= 1)
        mx = fmaxf(mx, __shfl_xor_sync(0xffffffffu, mx, off));
    float e = expf(acc - mx);
    float sum = e;
    for (int off = 8; off > 0; off >>= 1)
        sum += __shfl_xor_sync(0xffffffffu, sum, off);
    out[b * 16 + a] = acc - mx - logf(sum);
}

// ---------------- launch ----------------
extern "C" void kernel_launch(void* const* d_in, const int* in_sizes, int n_in,
                              void* d_out, int out_size) {
    const int*   x     = (const int*)d_in[0];
    const int*   mask  = (const int*)d_in[1];
    const float* embed = (const float*)d_in[2];
    const float* Wq    = (const float*)d_in[3];
    const float* Wk    = (const float*)d_in[4];
    const float* Wv    = (const float*)d_in[5];
    const float* Wo_w  = (const float*)d_in[6];
    const float* Wo_b  = (const float*)d_in[7];
    const float* ln1_s = (const float*)d_in[8];
    const float* ln1_b = (const float*)d_in[9];
    const float* ff_w1 = (const float*)d_in[10];
    const float* ff_b1 = (const float*)d_in[11];
    const float* ff_w2 = (const float*)d_in[12];
    const float* ff_b2 = (const float*)d_in[13];
    const float* ln2_s = (const float*)d_in[14];
    const float* ln2_b = (const float*)d_in[15];
    const float* out_w = (const float*)d_in[16];
    const float* out_b = (const float*)d_in[17];
    float* out = (float*)d_out;

    float *h, *tmp, *pe;
    unsigned long long* mb;
    hf *wt, *hH, *hL, *qvH, *qvL, *cxH, *cxL, *ffH;
    cudaGetSymbolAddress((void**)&h,   g_h);
    cudaGetSymbolAddress((void**)&tmp, g_tmp);
    cudaGetSymbolAddress((void**)&pe,  g_pe);
    cudaGetSymbolAddress((void**)&mb,  g_mb);
    cudaGetSymbolAddress((void**)&wt,  g_wt);
    cudaGetSymbolAddress((void**)&hH,  g_hh);
    cudaGetSymbolAddress((void**)&hL,  g_hl);
    cudaGetSymbolAddress((void**)&qvH, g_qkvh);
    cudaGetSymbolAddress((void**)&qvL, g_qkvl);
    cudaGetSymbolAddress((void**)&cxH, g_cxh);
    cudaGetSymbolAddress((void**)&cxL, g_cxl);
    cudaGetSymbolAddress((void**)&ffH, g_ffh);

    cudaFuncSetAttribute(flash_kernel, cudaFuncAttributeMaxDynamicSharedMemorySize, FLASH_SMEM);
    cudaFuncSetAttribute(gemm_mma, cudaFuncAttributeMaxDynamicSharedMemorySize, GSMEM);

    dim3 tb(32, 8);
    dim3 gQKV(D3 / BNT, BL / BMT);   // (24, 64)
    dim3 gD(DMODEL / BNT, BL / BMT); // (8, 64)
    dim3 gF(DFF / BNT, BL / BMT);    // (32, 64)

    setup_kernel<<<4096 + 512, 256>>>(mask, mb, pe);                    // 0
    embed_kernel<<<BL, 256>>>(x, embed, pe, h, hH, hL);                 // 1

    for (int i = 0; i < NLAYERS; ++i) {
        size_t oq = (size_t)i * 3 * M1;
        size_t oo = 18 * (size_t)M1 + (size_t)i * M1;
        size_t o1 = 24 * (size_t)M1 + (size_t)i * 4 * M1;
        size_t o2 = 48 * (size_t)M1 + (size_t)i * 4 * M1;

        tsplit_qkv_kernel<<<dim3(32, 32, 3), tb>>>(
            Wq + (size_t)i * NHEADS * DMODEL * DQKV,
            Wk + (size_t)i * NHEADS * DMODEL * DQKV,
            Wv + (size_t)i * NHEADS * DMODEL * DQKV,
            wt + oq);                                                   // 2 (layer 0)

        // fused QKV -> split fp16 (2-term A)                           // 3 (layer 0, profiled)
        gemm_mma<<<gQKV, 256, GSMEM>>>(hH, hL, wt + oq, nullptr, qvH, qvL,
                                       D3, DMODEL, 1, nullptr, nullptr, 0);

        tsplit_kernel<<<dim3(32, 32), tb>>>(Wo_w + (size_t)i * DMODEL * DMODEL,
                                            wt + oo, DMODEL, DMODEL, 0);
        tsplit_kernel<<<dim3(128, 32), tb>>>(ff_w1 + (size_t)i * DMODEL * DFF,
                                             wt + o1, DMODEL, DFF, 0);
        tsplit_kernel<<<dim3(32, 128), tb>>>(ff_w2 + (size_t)i * DFF * DMODEL,
                                             wt + o2, DFF, DMODEL, 0);

        flash_kernel<<<dim3(SEQ / 64, NHEADS, BATCH), 256, FLASH_SMEM>>>(qvH, qvL, mb, cxH, cxL);

        // Wo (2-term A)
        gemm_mma<<<gD, 256, GSMEM>>>(cxH, cxL, wt + oo, tmp, nullptr, nullptr,
                                     DMODEL, DMODEL, 1, Wo_b + (size_t)i * DMODEL, h, 0);
        layernorm_kernel<<<BL, 256>>>(tmp, ln1_s + (size_t)i * DMODEL, ln1_b + (size_t)i * DMODEL, h, hH, hL);

        // FF1 (single-A: hH only) -> ffH only
        gemm_mma<<<gF, 256, GSMEM>>>(hH, hH, wt + o1, nullptr, ffH, nullptr,
                                     DFF, DMODEL, 0, ff_b1 + (size_t)i * DFF, nullptr, 1);
        // FF2 (single-A: ffH only)
        gemm_mma<<<gD, 256, GSMEM>>>(ffH, ffH, wt + o2, tmp, nullptr, nullptr,
                                     DMODEL, DFF, 0, ff_b2 + (size_t)i * DMODEL, h, 0);
        layernorm_kernel<<<BL, 256>>>(tmp, ln2_s + (size_t)i * DMODEL, ln2_b + (size_t)i * DMODEL, h, hH, hL);
    }

    head_kernel<<<1, 128>>>(h, out_w, out_b, out);
}

// round 15
// speedup vs baseline: 2.7125x; 1.0187x over previous
#include <cuda_runtime.h>
#include <cuda_fp16.h>
#include <math.h>
#include <stdint.h>

// ---------------- dims ----------------
#define BATCH 8
#define SEQ   1024
#define DMODEL 1024
#define NHEADS 16
#define DQKV  64
#define DFF   4096
#define NLAYERS 6
#define BL    (BATCH*SEQ)          // 8192
#define D3    (3*DMODEL)           // 3072

typedef __half hf;

// ---------------- scratch ----------------
__device__ float g_h  [BL*DMODEL];
__device__ float g_tmp[BL*DMODEL];
__device__ float g_pe [SEQ*DMODEL];
__device__ unsigned long long g_mb[BL*(SEQ/64)];

// split activations (fp16 hi/lo)
__device__ hf g_hh  [BL*DMODEL];
__device__ hf g_hl  [BL*DMODEL];
__device__ hf g_qkvh[BL*D3];
__device__ hf g_qkvl[BL*D3];
__device__ hf g_cxh [BL*DMODEL];
__device__ hf g_cxl [BL*DMODEL];
__device__ hf g_ffh [BL*DFF];

// transposed weights (single fp16), layout [N][K] K-major
#define WT_TOTAL (72u*1048576u)
__device__ hf g_wt[WT_TOTAL];

// ================= PTX helpers =================
__device__ __forceinline__ uint32_t smem_u32(const void* p) {
    uint32_t a;
    asm("{ .reg .u64 t; cvta.to.shared.u64 t, %1; cvt.u32.u64 %0, t; }" : "=r"(a) : "l"(p));
    return a;
}
__device__ __forceinline__ void cp16(uint32_t s, const void* g) {
    asm volatile("cp.async.cg.shared.global [%0], [%1], 16;" :: "r"(s), "l"(g));
}
__device__ __forceinline__ void cp_commit() { asm volatile("cp.async.commit_group;"); }
template <int N> __device__ __forceinline__ void cp_wait() {
    asm volatile("cp.async.wait_group %0;" :: "n"(N));
}
__device__ __forceinline__ void ldm4(uint32_t& r0, uint32_t& r1, uint32_t& r2, uint32_t& r3, uint32_t a) {
    asm volatile("ldmatrix.sync.aligned.m8n8.x4.shared.b16 {%0,%1,%2,%3}, [%4];"
        : "=r"(r0), "=r"(r1), "=r"(r2), "=r"(r3) : "r"(a));
}
__device__ __forceinline__ void mma16816(float* c, uint32_t a0, uint32_t a1, uint32_t a2, uint32_t a3,
                                         uint32_t b0, uint32_t b1) {
    asm volatile("mma.sync.aligned.m16n8k16.row.col.f32.f16.f16.f32 "
        "{%0,%1,%2,%3}, {%4,%5,%6,%7}, {%8,%9}, {%0,%1,%2,%3};"
        : "+f"(c[0]), "+f"(c[1]), "+f"(c[2]), "+f"(c[3])
        : "r"(a0), "r"(a1), "r"(a2), "r"(a3), "r"(b0), "r"(b1));
}
__device__ __forceinline__ uint32_t pack_split2h(float v0, float v1, uint32_t& lo_out) {
    hf h0 = __float2half_rn(v0);
    hf h1 = __float2half_rn(v1);
    hf l0 = __float2half_rn(v0 - __half2float(h0));
    hf l1 = __float2half_rn(v1 - __half2float(h1));
    uint32_t hi = ((uint32_t)__half_as_ushort(h1) << 16) | __half_as_ushort(h0);
    lo_out = ((uint32_t)__half_as_ushort(l1) << 16) | __half_as_ushort(l0);
    return hi;
}
__device__ __forceinline__ uint32_t pack2h(float v0, float v1) {
    hf h0 = __float2half_rn(v0);
    hf h1 = __float2half_rn(v1);
    return ((uint32_t)__half_as_ushort(h1) << 16) | __half_as_ushort(h0);
}
// half2 exponential: one MUFU op for two exps
__device__ __forceinline__ uint32_t ex2_h2(float e0, float e1) {
    __half2 x = __floats2half2_rn(e0, e1);
    uint32_t xu = *(uint32_t*)&x;
    uint32_t r;
    asm("ex2.approx.f16x2 %0, %1;" : "=r"(r) : "r"(xu));
    return r;
}

// ---------------- setup: positional encoding + mask bitwords ----------------
__global__ void setup_kernel(const int* __restrict__ mask, unsigned long long* __restrict__ mb,
                             float* __restrict__ pe) {
    int bid = blockIdx.x;
    if (bid < 4096) {
        int idx = bid * 256 + threadIdx.x;
        int l = idx >> 10;
        int c = idx & 1023;
        double p = (double)(c & ~1) / (double)DMODEL;
        double divisor = pow(10000.0, p);
        double ang = (double)(l + 1) / divisor;
        pe[idx] = (float)((c & 1) ? cos(ang) : sin(ang));
    } else {
        int warp = (((bid - 4096) * 256) + threadIdx.x) >> 5;
        int lane = threadIdx.x & 31;
        const int nwarps = 512 * 256 / 32;
        for (int w = warp; w < BL * (SEQ / 64); w += nwarps) {
            int row = w >> 4;
            int kt  = w & 15;
            size_t base = (size_t)row * SEQ + kt * 64;
            int m0 = mask[base + lane];
            int m1 = mask[base + 32 + lane];
            unsigned lo = __ballot_sync(0xffffffffu, m0 != 0);
            unsigned hi = __ballot_sync(0xffffffffu, m1 != 0);
            if (lane == 0) mb[w] = (unsigned long long)lo | ((unsigned long long)hi << 32);
        }
    }
}

// ---------------- embedding + PE (+ split) ----------------
__global__ void embed_kernel(const int* __restrict__ x, const float* __restrict__ embed,
                             const float* __restrict__ pe, float* __restrict__ h,
                             hf* __restrict__ Hh, hf* __restrict__ Hl) {
    int r = blockIdx.x;
    int t = threadIdx.x;
    int l = r & 1023;
    int tok = x[r];
    float4 e  = *(const float4*)(embed + (size_t)tok * DMODEL + t * 4);
    float4 pp = *(const float4*)(pe + (size_t)l * DMODEL + t * 4);
    float4 o;
    o.x = e.x * 32.0f + pp.x;
    o.y = e.y * 32.0f + pp.y;
    o.z = e.z * 32.0f + pp.z;
    o.w = e.w * 32.0f + pp.w;
    *(float4*)(h + (size_t)r * DMODEL + t * 4) = o;
    uint32_t hi0, hi1, lo0, lo1;
    hi0 = pack_split2h(o.x, o.y, lo0);
    hi1 = pack_split2h(o.z, o.w, lo1);
    uint2 hv = {hi0, hi1}, lv = {lo0, lo1};
    *(uint2*)(Hh + (size_t)r * DMODEL + t * 4) = hv;
    *(uint2*)(Hl + (size_t)r * DMODEL + t * 4) = lv;
}

// ---------------- weight transpose + fp16 round ----------------
__device__ __forceinline__ void tsplit_body(const float* W, hf* O, int K, int N, int mode) {
    __shared__ float tile[32][33];
    int n0 = blockIdx.x * 32, k0 = blockIdx.y * 32;
    int tx = threadIdx.x, ty = threadIdx.y;
#pragma unroll
    for (int i = 0; i < 32; i += 8) {
        int k = k0 + ty + i, n = n0 + tx;
        float v;
        if (mode == 0) v = W[(size_t)k * N + n];
        else v = W[(size_t)(n >> 6) * (K * 64) + (size_t)k * 64 + (n & 63)];
        tile[ty + i][tx] = v;
    }
    __syncthreads();
#pragma unroll
    for (int i = 0; i < 32; i += 8) {
        int n = n0 + ty + i, k = k0 + tx;
        O[(size_t)n * K + k] = __float2half_rn(tile[tx][ty + i]);
    }
}

__global__ void tsplit_kernel(const float* __restrict__ W, hf* __restrict__ O,
                              int K, int N, int mode) {
    tsplit_body(W, O, K, N, mode);
}

#define M1 1048576u
__global__ void tsplit_qkv_kernel(const float* __restrict__ Wq, const float* __restrict__ Wk,
                                  const float* __restrict__ Wv, hf* __restrict__ O) {
    int z = blockIdx.z;
    const float* W = (z == 0) ? Wq : (z == 1) ? Wk : Wv;
    tsplit_body(W, O + (size_t)z * M1, DMODEL, DMODEL, 1);
}

// ---------------- HMMA GEMM: fp16, 128x128 tile, BKC=64, 2 CTAs/SM ----------------
#define BMT 128
#define BNT 128
#define BKC 64
#define TSTRIDE 72
#define TILEB (128 * TSTRIDE * 2)           // 18432 B
#define STAGEB (3 * TILEB)                  // 55296 B
#define GSMEM (2 * STAGEB)                  // 110592 B -> 2 CTAs/SM

__global__ void __launch_bounds__(256, 2)
gemm_mma(const hf* __restrict__ Ah, const hf* __restrict__ Al,
         const hf* __restrict__ Bw,
         float* __restrict__ C, hf* __restrict__ Oh, hf* __restrict__ Ol,
         int N, int K, int at2,
         const float* __restrict__ bias, const float* __restrict__ res, int relu) {
    extern __shared__ char smem[];
    const uint32_t sbase = smem_u32(smem);
    const int t = threadIdx.x;
    const int wid = t >> 5, lane = t & 31;
    const int wm = wid >> 2, wn = wid & 3;
    const int row0 = blockIdx.y * BMT, col0 = blockIdx.x * BNT;

    const hf* srcA0 = Ah + (size_t)row0 * K;
    const hf* srcA1 = at2 ? (Al + (size_t)row0 * K) : (const hf*)0;
    const hf* srcB = Bw + (size_t)col0 * K;

    const int nst = K / BKC;
    const int lrow8 = t >> 3, lchunk = t & 7;

    auto load_stage = [&](int kc, int buf) {
        uint32_t sb = sbase + buf * STAGEB;
        {
            const hf* g = srcA0 + (size_t)kc * BKC;
#pragma unroll
            for (int p = 0; p < 4; ++p) {
                int row = lrow8 + p * 32;
                cp16(sb + (row * TSTRIDE + lchunk * 8) * 2,
                     g + (size_t)row * K + lchunk * 8);
            }
        }
        if (srcA1) {
            const hf* g = srcA1 + (size_t)kc * BKC;
            uint32_t tb = sb + TILEB;
#pragma unroll
            for (int p = 0; p < 4; ++p) {
                int row = lrow8 + p * 32;
                cp16(tb + (row * TSTRIDE + lchunk * 8) * 2,
                     g + (size_t)row * K + lchunk * 8);
            }
        }
        {
            const hf* g = srcB + (size_t)kc * BKC;
            uint32_t tb = sb + 2 * TILEB;
#pragma unroll
            for (int p = 0; p < 4; ++p) {
                int row = lrow8 + p * 32;
                cp16(tb + (row * TSTRIDE + lchunk * 8) * 2,
                     g + (size_t)row * K + lchunk * 8);
            }
        }
        cp_commit();
    };

    float acc[4][4][4];
#pragma unroll
    for (int i = 0; i < 4; ++i)
#pragma unroll
        for (int j = 0; j < 4; ++j)
#pragma unroll
            for (int r = 0; r < 4; ++r) acc[i][j][r] = 0.f;

    const int lrow = lane & 15;
    const int lcol = (lane >> 4) << 3;

    load_stage(0, 0);

    for (int kc = 0; kc < nst; ++kc) {
        int buf = kc & 1;
        if (kc + 1 < nst) {
            load_stage(kc + 1, buf ^ 1);
            cp_wait<1>();
        } else {
            cp_wait<0>();
        }
        __syncthreads();

        uint32_t sb = sbase + buf * STAGEB;
        uint32_t sAh = sb;
        uint32_t sAl = sb + TILEB;
        uint32_t sB  = sb + 2 * TILEB;

#pragma unroll
        for (int ks = 0; ks < 4; ++ks) {
            int kof = ks * 16 + lcol;
            uint32_t ah[4][4], al[4][4];
#pragma unroll
            for (int mi = 0; mi < 4; ++mi) {
                int row = wm * 64 + mi * 16 + lrow;
                uint32_t off = (row * TSTRIDE + kof) * 2;
                ldm4(ah[mi][0], ah[mi][1], ah[mi][2], ah[mi][3], sAh + off);
                if (at2) ldm4(al[mi][0], al[mi][1], al[mi][2], al[mi][3], sAl + off);
            }
            uint32_t bb[2][4];
#pragma unroll
            for (int nh = 0; nh < 2; ++nh) {
                int row = wn * 32 + nh * 16 + lrow;
                uint32_t off = (row * TSTRIDE + kof) * 2;
                ldm4(bb[nh][0], bb[nh][1], bb[nh][2], bb[nh][3], sB + off);
            }
#pragma unroll
            for (int mi = 0; mi < 4; ++mi) {
#pragma unroll
                for (int ni = 0; ni < 4; ++ni) {
                    int nh = ni >> 1, np = ni & 1;
                    uint32_t b0 = bb[nh][np], b1 = bb[nh][np + 2];
                    mma16816(acc[mi][ni], ah[mi][0], ah[mi][1], ah[mi][2], ah[mi][3], b0, b1);
                    if (at2) mma16816(acc[mi][ni], al[mi][0], al[mi][1], al[mi][2], al[mi][3], b0, b1);
                }
            }
        }
        __syncthreads();
    }

    const int erow = lane >> 2, ecol = (lane & 3) * 2;
#pragma unroll
    for (int mi = 0; mi < 4; ++mi) {
#pragma unroll
        for (int p = 0; p < 2; ++p) {
            int r = row0 + wm * 64 + mi * 16 + p * 8 + erow;
            const float* rrow = res ? res + (size_t)r * N : (const float*)0;
#pragma unroll
            for (int ni = 0; ni < 4; ++ni) {
                int c = col0 + wn * 32 + ni * 8 + ecol;
                float v0 = acc[mi][ni][p * 2 + 0];
                float v1 = acc[mi][ni][p * 2 + 1];
                if (bias) { v0 += bias[c]; v1 += bias[c + 1]; }
                if (rrow) {
                    float2 rv = *(const float2*)(rrow + c);
                    v0 += rv.x; v1 += rv.y;
                }
                if (relu) { v0 = fmaxf(v0, 0.f); v1 = fmaxf(v1, 0.f); }
                if (C) {
                    float2 o = {v0, v1};
                    *(float2*)(C + (size_t)r * N + c) = o;
                }
                if (Oh) {
                    if (Ol) {
                        uint32_t lo, hi = pack_split2h(v0, v1, lo);
                        *(uint32_t*)(Oh + (size_t)r * N + c) = hi;
                        *(uint32_t*)(Ol + (size_t)r * N + c) = lo;
                    } else {
                        *(uint32_t*)(Oh + (size_t)r * N + c) = pack2h(v0, v1);
                    }
                }
            }
        }
    }
}

// ---------------- tensorized flash attention (fp16 2-term, half2 exp) ----------------
#define FTST 72
#define FT_TILE (64 * FTST * 2)
#define F_QH 0
#define F_QL (F_QH + FT_TILE)
#define F_KH (F_QL + FT_TILE)
#define F_VTH (F_KH + FT_TILE)
#define F_VTL (F_VTH + FT_TILE)
#define F_P (F_VTL + FT_TILE)
#define F_SS (F_P + FT_TILE)
#define F_ROWM (F_SS + 64*65*4)
#define F_ROWL (F_ROWM + 256)
#define F_ROWA (F_ROWL + 256)
#define FLASH_SMEM (F_ROWA + 256 + 64)

__global__ void __launch_bounds__(256, 2)
flash_kernel(const hf* __restrict__ qkvh, const hf* __restrict__ qkvl,
             const unsigned long long* __restrict__ mb,
             hf* __restrict__ cxh, hf* __restrict__ cxl) {
    extern __shared__ char smem[];
    const uint32_t sbase = smem_u32(smem);
    float* Ss   = (float*)(smem + F_SS);
    float* rowM = (float*)(smem + F_ROWM);
    float* rowL = (float*)(smem + F_ROWL);
    float* rowA = (float*)(smem + F_ROWA);
    hf* Pp = (hf*)(smem + F_P);

    const int b = blockIdx.z, hh = blockIdx.y, qt = blockIdx.x;
    const int t = threadIdx.x;
    const int wid = t >> 5, lane = t & 31;
    const int wm = wid >> 1, wn = wid & 1;
    const int rowbase = b * SEQ + qt * 64;
    const int lrow = lane & 15;
    const int lcol = (lane >> 4) << 3;
    const int erow = lane >> 2, ecol = (lane & 3) * 2;
    const float LOG2E = 1.44269504f;

    {
        const hf* qh = qkvh + (size_t)rowbase * D3 + hh * 64;
        const hf* ql = qkvl + (size_t)rowbase * D3 + hh * 64;
#pragma unroll
        for (int it = 0; it < 2; ++it) {
            int f = t + it * 256;
            int r = f >> 3, ch = (f & 7) * 8;
            *(uint4*)(smem + F_QH + (r * FTST + ch) * 2) = *(const uint4*)(qh + (size_t)r * D3 + ch);
            *(uint4*)(smem + F_QL + (r * FTST + ch) * 2) = *(const uint4*)(ql + (size_t)r * D3 + ch);
        }
    }
    if (t < 64) { rowM[t] = -INFINITY; rowL[t] = 0.f; }

    float oa[4][4];
#pragma unroll
    for (int i = 0; i < 4; ++i)
#pragma unroll
        for (int j = 0; j < 4; ++j) oa[i][j] = 0.f;

    const unsigned long long* mrow = mb + (size_t)rowbase * (SEQ / 64);

    for (int kt = 0; kt < SEQ / 64; ++kt) {
        __syncthreads();
        {
            const hf* kh = qkvh + (size_t)(b * SEQ + kt * 64) * D3 + DMODEL + hh * 64;
            const hf* vh = qkvh + (size_t)(b * SEQ + kt * 64) * D3 + 2 * DMODEL + hh * 64;
            const hf* vl = qkvl + (size_t)(b * SEQ + kt * 64) * D3 + 2 * DMODEL + hh * 64;
#pragma unroll
            for (int it = 0; it < 2; ++it) {
                int f = t + it * 256;
                int r = f >> 3, ch = (f & 7) * 8;
                *(uint4*)(smem + F_KH + (r * FTST + ch) * 2) = *(const uint4*)(kh + (size_t)r * D3 + ch);
                uint4 v4h = *(const uint4*)(vh + (size_t)r * D3 + ch);
                uint4 v4l = *(const uint4*)(vl + (size_t)r * D3 + ch);
                const uint16_t* eh = (const uint16_t*)&v4h;
                const uint16_t* el = (const uint16_t*)&v4l;
#pragma unroll
                for (int e = 0; e < 8; ++e) {
                    int d = ch + e;
                    *(uint16_t*)(smem + F_VTH + (d * FTST + r) * 2) = eh[e];
                    *(uint16_t*)(smem + F_VTL + (d * FTST + r) * 2) = el[e];
                }
            }
        }
        __syncthreads();

        float sc[4][4];
#pragma unroll
        for (int i = 0; i < 4; ++i)
#pragma unroll
            for (int j = 0; j < 4; ++j) sc[i][j] = 0.f;
#pragma unroll
        for (int ks = 0; ks < 4; ++ks) {
            int kof = ks * 16 + lcol;
            uint32_t ah[4], al[4];
            {
                int row = wm * 16 + lrow;
                uint32_t off = (row * FTST + kof) * 2;
                ldm4(ah[0], ah[1], ah[2], ah[3], sbase + F_QH + off);
                ldm4(al[0], al[1], al[2], al[3], sbase + F_QL + off);
            }
            uint32_t bb[2][4];
#pragma unroll
            for (int nh = 0; nh < 2; ++nh) {
                int row = wn * 32 + nh * 16 + lrow;
                uint32_t off = (row * FTST + kof) * 2;
                ldm4(bb[nh][0], bb[nh][1], bb[nh][2], bb[nh][3], sbase + F_KH + off);
            }
#pragma unroll
            for (int ni = 0; ni < 4; ++ni) {
                int nh = ni >> 1, np = ni & 1;
                uint32_t b0 = bb[nh][np], b1 = bb[nh][np + 2];
                mma16816(sc[ni], ah[0], ah[1], ah[2], ah[3], b0, b1);
                mma16816(sc[ni], al[0], al[1], al[2], al[3], b0, b1);
            }
        }
#pragma unroll
        for (int p = 0; p < 2; ++p) {
            int rl = wm * 16 + p * 8 + erow;
            unsigned long long wbits = mrow[rl * (SEQ / 64) + kt];
#pragma unroll
            for (int ni = 0; ni < 4; ++ni) {
                int c = wn * 32 + ni * 8 + ecol;
                float v0 = sc[ni][p * 2 + 0] * 0.125f;
                float v1 = sc[ni][p * 2 + 1] * 0.125f;
                if (!((wbits >> c) & 1ULL)) v0 = -1e9f;
                if (!((wbits >> (c + 1)) & 1ULL)) v1 = -1e9f;
                Ss[rl * 65 + c] = v0;
                Ss[rl * 65 + c + 1] = v1;
            }
        }
        __syncthreads();

        // online softmax: 4 threads/row; half2 exp (1 MUFU per 2 values)
        {
            int r = t >> 2, sub = t & 3;
            float* srow = Ss + r * 65 + sub * 16;
            hf* prow = Pp + r * FTST + sub * 16;
            float mold = rowM[r];
            float mx = mold;
#pragma unroll
            for (int j = 0; j < 16; ++j) mx = fmaxf(mx, srow[j]);
            mx = fmaxf(mx, __shfl_xor_sync(0xffffffffu, mx, 1));
            mx = fmaxf(mx, __shfl_xor_sync(0xffffffffu, mx, 2));
            float sum = 0.f;
#pragma unroll
            for (int j = 0; j < 16; j += 2) {
                float e0 = (srow[j]     - mx) * LOG2E;
                float e1 = (srow[j + 1] - mx) * LOG2E;
                uint32_t pu = ex2_h2(e0, e1);
                *(uint32_t*)(prow + j) = pu;
                __half2 ph = *(__half2*)&pu;
                float2 pf = __half22float2(ph);
                sum += pf.x + pf.y;
            }
            sum += __shfl_xor_sync(0xffffffffu, sum, 1);
            sum += __shfl_xor_sync(0xffffffffu, sum, 2);
            if (sub == 0) {
                float alpha = __expf(mold - mx);
                rowL[r] = rowL[r] * alpha + sum;
                rowM[r] = mx;
                rowA[r] = alpha;
            }
        }
        __syncthreads();

        {
            float a0 = rowA[wm * 16 + erow];
            float a1 = rowA[wm * 16 + 8 + erow];
#pragma unroll
            for (int ni = 0; ni < 4; ++ni) {
                oa[ni][0] *= a0; oa[ni][1] *= a0;
                oa[ni][2] *= a1; oa[ni][3] *= a1;
            }
        }
#pragma unroll
        for (int ks = 0; ks < 4; ++ks) {
            int kof = ks * 16 + lcol;
            uint32_t ap[4];
            {
                int row = wm * 16 + lrow;
                uint32_t off = (row * FTST + kof) * 2;
                ldm4(ap[0], ap[1], ap[2], ap[3], sbase + F_P + off);
            }
            uint32_t bh[2][4], bl[2][4];
#pragma unroll
            for (int nh = 0; nh < 2; ++nh) {
                int row = wn * 32 + nh * 16 + lrow;
                uint32_t off = (row * FTST + kof) * 2;
                ldm4(bh[nh][0], bh[nh][1], bh[nh][2], bh[nh][3], sbase + F_VTH + off);
                ldm4(bl[nh][0], bl[nh][1], bl[nh][2], bl[nh][3], sbase + F_VTL + off);
            }
#pragma unroll
            for (int ni = 0; ni < 4; ++ni) {
                int nh = ni >> 1, np = ni & 1;
                mma16816(oa[ni], ap[0], ap[1], ap[2], ap[3], bh[nh][np], bh[nh][np + 2]);
                mma16816(oa[ni], ap[0], ap[1], ap[2], ap[3], bl[nh][np], bl[nh][np + 2]);
            }
        }
    }

#pragma unroll
    for (int p = 0; p < 2; ++p) {
        int rl = wm * 16 + p * 8 + erow;
        float inv = 1.f / rowL[rl];
        int grow = rowbase + rl;
#pragma unroll
        for (int ni = 0; ni < 4; ++ni) {
            int c = wn * 32 + ni * 8 + ecol;
            float v0 = oa[ni][p * 2 + 0] * inv;
            float v1 = oa[ni][p * 2 + 1] * inv;
            uint32_t lo, hi = pack_split2h(v0, v1, lo);
            size_t off = (size_t)grow * DMODEL + hh * 64 + c;
            *(uint32_t*)(cxh + off) = hi;
            *(uint32_t*)(cxl + off) = lo;
        }
    }
}

// ---------------- layernorm (+ split out) ----------------
__global__ void layernorm_kernel(const float* __restrict__ X, const float* __restrict__ s,
                                 const float* __restrict__ bvec, float* __restrict__ Y,
                                 hf* __restrict__ Yh, hf* __restrict__ Yl) {
    __shared__ float red[256];
    int r = blockIdx.x;
    int t = threadIdx.x;
    float4 v = *(const float4*)(X + (size_t)r * DMODEL + t * 4);
    float ssum = v.x + v.y + v.z + v.w;
    red[t] = ssum;
    __syncthreads();
    for (int off = 128; off > 0; off >>= 1) {
        if (t < off) red[t] += red[t + off];
        __syncthreads();
    }
    float mu = red[0] * (1.f / DMODEL);
    __syncthreads();
    float d0 = v.x - mu, d1 = v.y - mu, d2 = v.z - mu, d3 = v.w - mu;
    red[t] = d0 * d0 + d1 * d1 + d2 * d2 + d3 * d3;
    __syncthreads();
    for (int off = 128; off > 0; off >>= 1) {
        if (t < off) red[t] += red[t + off];
        __syncthreads();
    }
    float var = red[0] * (1.f / DMODEL);
    float rs = rsqrtf(var + 1e-5f);
    float4 sc = *(const float4*)(s + t * 4);
    float4 be = *(const float4*)(bvec + t * 4);
    float4 out;
    out.x = d0 * rs * sc.x + be.x;
    out.y = d1 * rs * sc.y + be.y;
    out.z = d2 * rs * sc.z + be.z;
    out.w = d3 * rs * sc.w + be.w;
    *(float4*)(Y + (size_t)r * DMODEL + t * 4) = out;
    uint32_t lo0, lo1;
    uint32_t hi0 = pack_split2h(out.x, out.y, lo0);
    uint32_t hi1 = pack_split2h(out.z, out.w, lo1);
    uint2 hv = {hi0, hi1}, lv = {lo0, lo1};
    *(uint2*)(Yh + (size_t)r * DMODEL + t * 4) = hv;
    *(uint2*)(Yl + (size_t)r * DMODEL + t * 4) = lv;
}

// ---------------- output head ----------------
__global__ void head_kernel(const float* __restrict__ h, const float* __restrict__ ow,
                            const float* __restrict__ ob, float* __restrict__ out) {
    int t = threadIdx.x;
    int b = t >> 4, a = t & 15;
    const float* hrow = h + (size_t)(b * SEQ + (SEQ - 1)) * DMODEL;
    float acc = 0.f;
    for (int m = 0; m < DMODEL; ++m) acc = fmaf(hrow[m], ow[m * 16 + a], acc);
    acc += ob[a];
    float mx = acc;
    for (int off = 8; off > 0; off >>= 1)
        mx = fmaxf(mx, __shfl_xor_sync(0xffffffffu, mx, off));
    float e = expf(acc - mx);
    float sum = e;
    for (int off = 8; off > 0; off >>= 1)
        sum += __shfl_xor_sync(0xffffffffu, sum, off);
    out[b * 16 + a] = acc - mx - logf(sum);
}

// ---------------- launch ----------------
extern "C" void kernel_launch(void* const* d_in, const int* in_sizes, int n_in,
                              void* d_out, int out_size) {
    const int*   x     = (const int*)d_in[0];
    const int*   mask  = (const int*)d_in[1];
    const float* embed = (const float*)d_in[2];
    const float* Wq    = (const float*)d_in[3];
    const float* Wk    = (const float*)d_in[4];
    const float* Wv    = (const float*)d_in[5];
    const float* Wo_w  = (const float*)d_in[6];
    const float* Wo_b  = (const float*)d_in[7];
    const float* ln1_s = (const float*)d_in[8];
    const float* ln1_b = (const float*)d_in[9];
    const float* ff_w1 = (const float*)d_in[10];
    const float* ff_b1 = (const float*)d_in[11];
    const float* ff_w2 = (const float*)d_in[12];
    const float* ff_b2 = (const float*)d_in[13];
    const float* ln2_s = (const float*)d_in[14];
    const float* ln2_b = (const float*)d_in[15];
    const float* out_w = (const float*)d_in[16];
    const float* out_b = (const float*)d_in[17];
    float* out = (float*)d_out;

    float *h, *tmp, *pe;
    unsigned long long* mb;
    hf *wt, *hH, *hL, *qvH, *qvL, *cxH, *cxL, *ffH;
    cudaGetSymbolAddress((void**)&h,   g_h);
    cudaGetSymbolAddress((void**)&tmp, g_tmp);
    cudaGetSymbolAddress((void**)&pe,  g_pe);
    cudaGetSymbolAddress((void**)&mb,  g_mb);
    cudaGetSymbolAddress((void**)&wt,  g_wt);
    cudaGetSymbolAddress((void**)&hH,  g_hh);
    cudaGetSymbolAddress((void**)&hL,  g_hl);
    cudaGetSymbolAddress((void**)&qvH, g_qkvh);
    cudaGetSymbolAddress((void**)&qvL, g_qkvl);
    cudaGetSymbolAddress((void**)&cxH, g_cxh);
    cudaGetSymbolAddress((void**)&cxL, g_cxl);
    cudaGetSymbolAddress((void**)&ffH, g_ffh);

    cudaFuncSetAttribute(flash_kernel, cudaFuncAttributeMaxDynamicSharedMemorySize, FLASH_SMEM);
    cudaFuncSetAttribute(gemm_mma, cudaFuncAttributeMaxDynamicSharedMemorySize, GSMEM);

    dim3 tb(32, 8);
    dim3 gQKV(D3 / BNT, BL / BMT);   // (24, 64)
    dim3 gD(DMODEL / BNT, BL / BMT); // (8, 64)
    dim3 gF(DFF / BNT, BL / BMT);    // (32, 64)

    setup_kernel<<<4096 + 512, 256>>>(mask, mb, pe);                    // 0
    embed_kernel<<<BL, 256>>>(x, embed, pe, h, hH, hL);                 // 1

    for (int i = 0; i < NLAYERS; ++i) {
        size_t oq = (size_t)i * 3 * M1;
        size_t oo = 18 * (size_t)M1 + (size_t)i * M1;
        size_t o1 = 24 * (size_t)M1 + (size_t)i * 4 * M1;
        size_t o2 = 48 * (size_t)M1 + (size_t)i * 4 * M1;

        tsplit_qkv_kernel<<<dim3(32, 32, 3), tb>>>(
            Wq + (size_t)i * NHEADS * DMODEL * DQKV,
            Wk + (size_t)i * NHEADS * DMODEL * DQKV,
            Wv + (size_t)i * NHEADS * DMODEL * DQKV,
            wt + oq);                                                   // 2 (layer 0)

        // fused QKV -> split fp16 (2-term A)                           // 3 (layer 0, profiled)
        gemm_mma<<<gQKV, 256, GSMEM>>>(hH, hL, wt + oq, nullptr, qvH, qvL,
                                       D3, DMODEL, 1, nullptr, nullptr, 0);

        tsplit_kernel<<<dim3(32, 32), tb>>>(Wo_w + (size_t)i * DMODEL * DMODEL,
                                            wt + oo, DMODEL, DMODEL, 0);
        tsplit_kernel<<<dim3(128, 32), tb>>>(ff_w1 + (size_t)i * DMODEL * DFF,
                                             wt + o1, DMODEL, DFF, 0);
        tsplit_kernel<<<dim3(32, 128), tb>>>(ff_w2 + (size_t)i * DFF * DMODEL,
                                             wt + o2, DFF, DMODEL, 0);

        flash_kernel<<<dim3(SEQ / 64, NHEADS, BATCH), 256, FLASH_SMEM>>>(qvH, qvL, mb, cxH, cxL);

        gemm_mma<<<gD, 256, GSMEM>>>(cxH, cxL, wt + oo, tmp, nullptr, nullptr,
                                     DMODEL, DMODEL, 1, Wo_b + (size_t)i * DMODEL, h, 0);
        layernorm_kernel<<<BL, 256>>>(tmp, ln1_s + (size_t)i * DMODEL, ln1_b + (size_t)i * DMODEL, h, hH, hL);

        gemm_mma<<<gF, 256, GSMEM>>>(hH, hH, wt + o1, nullptr, ffH, nullptr,
                                     DFF, DMODEL, 0, ff_b1 + (size_t)i * DFF, nullptr, 1);
        gemm_mma<<<gD, 256, GSMEM>>>(ffH, ffH, wt + o2, tmp, nullptr, nullptr,
                                     DMODEL, DFF, 0, ff_b2 + (size_t)i * DMODEL, h, 0);
        layernorm_kernel<<<BL, 256>>>(tmp, ln2_s + (size_t)i * DMODEL, ln2_b + (size_t)i * DMODEL, h, hH, hL);
    }

    head_kernel<<<1, 128>>>(h, out_w, out_b, out);
}